// round 6
// baseline (speedup 1.0000x reference)
#include <cuda_runtime.h>

#define BB 4
#define SS 2048
#define DM 1024
#define HH 16
#define FF 16
#define HD 64
#define EXPD 273
#define NC 16
#define CHK 128
#define QKDIM (HH*FF)
#define VDIM  (HH*HD)
#define C2 0.17677669529663687f

#define Y_ELEMS   (BB*SS*DM)
#define KV_ELEMS  (BB*HH*EXPD*HD)
#define KST_ELEMS (BB*HH*EXPD)

__device__ float g_q[BB*SS*QKDIM];
__device__ float g_k[BB*SS*QKDIM];
__device__ float g_v[BB*SS*VDIM];
__device__ float g_att[BB*SS*VDIM];
__device__ float g_S[BB*HH*NC*EXPD*HD];
__device__ float g_z[BB*HH*NC*EXPD];
__device__ float g_den[BB*HH*SS];

// ---- fp32 GEMM: C[M,N] = A[M,K] @ W[K,N] + bias, 128x64 tile ----
__global__ __launch_bounds__(256, 2) void gemm_bias(
    const float* __restrict__ A, const float* __restrict__ W,
    const float* __restrict__ bias, float* __restrict__ C,
    int M, int N, int K)
{
    __shared__ __align__(16) float As[16][132];
    __shared__ __align__(16) float Bs[16][64];
    const int bm = blockIdx.y * 128, bn = blockIdx.x * 64;
    const int tid = threadIdx.x;
    const int tx = tid & 15, ty = tid >> 4;
    const int arow = tid >> 1, acol = (tid & 1) * 8;
    const int brow = tid >> 4, bcol = (tid & 15) * 4;

    float acc[8][4];
#pragma unroll
    for (int i = 0; i < 8; i++)
#pragma unroll
        for (int j = 0; j < 4; j++) acc[i][j] = 0.f;

    const float* Ap = A + (size_t)(bm + arow) * K + acol;
    const float* Wp = W + (size_t)brow * N + bn + bcol;

    for (int k0 = 0; k0 < K; k0 += 16) {
        float4 a0 = *(const float4*)(Ap + k0);
        float4 a1 = *(const float4*)(Ap + k0 + 4);
        float4 bw = *(const float4*)(Wp + (size_t)k0 * N);
        As[acol+0][arow]=a0.x; As[acol+1][arow]=a0.y; As[acol+2][arow]=a0.z; As[acol+3][arow]=a0.w;
        As[acol+4][arow]=a1.x; As[acol+5][arow]=a1.y; As[acol+6][arow]=a1.z; As[acol+7][arow]=a1.w;
        *(float4*)&Bs[brow][bcol] = bw;
        __syncthreads();
#pragma unroll
        for (int kk = 0; kk < 16; kk++) {
            float4 ra0 = *(const float4*)&As[kk][ty*8];
            float4 ra1 = *(const float4*)&As[kk][ty*8+4];
            float4 rb  = *(const float4*)&Bs[kk][tx*4];
            float av[8] = {ra0.x,ra0.y,ra0.z,ra0.w,ra1.x,ra1.y,ra1.z,ra1.w};
            float bv4[4] = {rb.x,rb.y,rb.z,rb.w};
#pragma unroll
            for (int i = 0; i < 8; i++)
#pragma unroll
                for (int j = 0; j < 4; j++)
                    acc[i][j] = fmaf(av[i], bv4[j], acc[i][j]);
        }
        __syncthreads();
    }
    float4 bb = *(const float4*)(bias + bn + tx*4);
#pragma unroll
    for (int i = 0; i < 8; i++) {
        float4 o = make_float4(acc[i][0]+bb.x, acc[i][1]+bb.y, acc[i][2]+bb.z, acc[i][3]+bb.w);
        *(float4*)(C + (size_t)(bm + ty*8 + i) * N + bn + tx*4) = o;
    }
}

// ---- pass1: per-chunk S = Phi_k^T V (273x64), z = sum phi_k ----
#define P1ACC(s_) do { \
    float phi = ks[t][ii[s_]] * ks[t][jj[s_]]; \
    zacc[s_] += phi; \
    acc[s_][0].x=fmaf(phi,v0.x,acc[s_][0].x); acc[s_][0].y=fmaf(phi,v0.y,acc[s_][0].y); \
    acc[s_][0].z=fmaf(phi,v0.z,acc[s_][0].z); acc[s_][0].w=fmaf(phi,v0.w,acc[s_][0].w); \
    acc[s_][1].x=fmaf(phi,v1.x,acc[s_][1].x); acc[s_][1].y=fmaf(phi,v1.y,acc[s_][1].y); \
    acc[s_][1].z=fmaf(phi,v1.z,acc[s_][1].z); acc[s_][1].w=fmaf(phi,v1.w,acc[s_][1].w); \
    acc[s_][2].x=fmaf(phi,v2.x,acc[s_][2].x); acc[s_][2].y=fmaf(phi,v2.y,acc[s_][2].y); \
    acc[s_][2].z=fmaf(phi,v2.z,acc[s_][2].z); acc[s_][2].w=fmaf(phi,v2.w,acc[s_][2].w); \
    acc[s_][3].x=fmaf(phi,v3.x,acc[s_][3].x); acc[s_][3].y=fmaf(phi,v3.y,acc[s_][3].y); \
    acc[s_][3].z=fmaf(phi,v3.z,acc[s_][3].z); acc[s_][3].w=fmaf(phi,v3.w,acc[s_][3].w); \
} while (0)

__global__ __launch_bounds__(256) void pass1_kernel()
{
    __shared__ __align__(16) float ks[CHK][18];
    __shared__ __align__(16) float vs[CHK][64];
    const int c = blockIdx.x, h = blockIdx.y, b = blockIdx.z;
    const int tid = threadIdx.x;
    {
        int t = tid >> 1, f0 = (tid & 1) * 8;
        const float* kp = g_k + (size_t)(b*SS + c*CHK + t)*QKDIM + h*FF + f0;
        float4 k0 = *(const float4*)kp;
        float4 k1 = *(const float4*)(kp + 4);
        ks[t][f0+0]=k0.x; ks[t][f0+1]=k0.y; ks[t][f0+2]=k0.z; ks[t][f0+3]=k0.w;
        ks[t][f0+4]=k1.x; ks[t][f0+5]=k1.y; ks[t][f0+6]=k1.z; ks[t][f0+7]=k1.w;
        if (f0 == 0) ks[t][16] = 1.0f;
    }
    for (int idx = tid; idx < CHK*16; idx += 256) {
        int t = idx >> 4, d4 = (idx & 15) * 4;
        *(float4*)&vs[t][d4] = *(const float4*)(g_v + (size_t)(b*SS + c*CHK + t)*VDIM + h*HD + d4);
    }
    __syncthreads();

    const int eg = tid >> 2, dsub = tid & 3;
    int ii[5], jj[5]; float cf[5];
#pragma unroll
    for (int s = 0; s < 5; s++) {
        int e = eg + 64 * s;
        if (e >= EXPD)   { ii[s]=16; jj[s]=16; cf[s]=0.f; }
        else if (e == 0) { ii[s]=16; jj[s]=16; cf[s]=1.f; }
        else if (e < 17) { ii[s]=e-1; jj[s]=16; cf[s]=0.5f; }
        else { int p = e-17; ii[s]=p>>4; jj[s]=p&15; cf[s]=C2; }
    }
    const bool has5 = (eg < 17);

    float4 acc[5][4];
#pragma unroll
    for (int s = 0; s < 5; s++)
#pragma unroll
        for (int g = 0; g < 4; g++) acc[s][g] = make_float4(0.f,0.f,0.f,0.f);
    float zacc[5] = {0.f,0.f,0.f,0.f,0.f};

    for (int t = 0; t < CHK; t++) {
        float4 v0 = *(const float4*)&vs[t][dsub*16];
        float4 v1 = *(const float4*)&vs[t][dsub*16+4];
        float4 v2 = *(const float4*)&vs[t][dsub*16+8];
        float4 v3 = *(const float4*)&vs[t][dsub*16+12];
        P1ACC(0); P1ACC(1); P1ACC(2); P1ACC(3);
        if (has5) { P1ACC(4); }
    }

    const size_t Sbase = ((size_t)((b*HH + h)*NC + c)) * EXPD * HD;
    const size_t zbase = ((size_t)((b*HH + h)*NC + c)) * EXPD;
#pragma unroll
    for (int s = 0; s < 5; s++) {
        int e = eg + 64*s;
        if (e >= EXPD) continue;
        float cfv = cf[s];
        float* op = g_S + Sbase + (size_t)e*HD + dsub*16;
#pragma unroll
        for (int g = 0; g < 4; g++) {
            float4 o = acc[s][g];
            o.x*=cfv; o.y*=cfv; o.z*=cfv; o.w*=cfv;
            *(float4*)(op + g*4) = o;
        }
        if (dsub == 0) g_z[zbase + e] = zacc[s] * cfv;
    }
}

// ---- exclusive prefix over chunks; emits kv_f / kst_f ----
__global__ __launch_bounds__(256) void prefix_kernel(
    const float* __restrict__ kv0, const float* __restrict__ kst0,
    float* __restrict__ out_kv, float* __restrict__ out_kst)
{
    const int h = blockIdx.x, b = blockIdx.y;
    const int pair = b*HH + h;
    const int tid = threadIdx.x;
    for (int idx = tid; idx < EXPD*HD; idx += 256) {
        float run = kv0[(size_t)pair*EXPD*HD + idx];
        float* p = g_S + ((size_t)pair*NC)*EXPD*HD + idx;
#pragma unroll
        for (int cc = 0; cc < NC; cc++) {
            float sv = p[(size_t)cc*EXPD*HD];
            p[(size_t)cc*EXPD*HD] = run;
            run += sv;
        }
        if (out_kv) out_kv[(size_t)pair*EXPD*HD + idx] = run;
    }
    for (int idx = tid; idx < EXPD; idx += 256) {
        float run = kst0[(size_t)pair*EXPD + idx];
        float* p = g_z + ((size_t)pair*NC)*EXPD + idx;
#pragma unroll
        for (int cc = 0; cc < NC; cc++) {
            float sv = p[(size_t)cc*EXPD];
            p[(size_t)cc*EXPD] = run;
            run += sv;
        }
        if (out_kst) out_kst[(size_t)pair*EXPD + idx] = run;
    }
}

// ---- pass2a: inter-chunk  att = Phi_q @ KV_prev,  den = Phi_q . z_prev ----
#define P2A_SMEM ((128*18 + 128*274 + 280 + 16*64) * 4)
__global__ __launch_bounds__(256) void pass2a_kernel()
{
    extern __shared__ float sm[];
    float* qs  = sm;              // [128][18]
    float* Phi = sm + 128*18;     // [128][274]
    float* zs  = Phi + 128*274;   // [280]
    float* kvt = zs + 280;        // [16][64]
    const int c = blockIdx.x, h = blockIdx.y, b = blockIdx.z;
    const int tid = threadIdx.x;
    {
        int t = tid >> 1, f0 = (tid & 1) * 8;
        const float* qp = g_q + (size_t)(b*SS + c*CHK + t)*QKDIM + h*FF + f0;
        float4 a = *(const float4*)qp;
        float4 b4 = *(const float4*)(qp + 4);
        qs[t*18+f0+0]=a.x;  qs[t*18+f0+1]=a.y;  qs[t*18+f0+2]=a.z;  qs[t*18+f0+3]=a.w;
        qs[t*18+f0+4]=b4.x; qs[t*18+f0+5]=b4.y; qs[t*18+f0+6]=b4.z; qs[t*18+f0+7]=b4.w;
        if (f0 == 0) qs[t*18+16] = 1.0f;
    }
    __syncthreads();
    {
        int w = tid >> 5, lane = tid & 31;
        for (int tt = w*16; tt < w*16 + 16; tt++) {
            for (int e = lane; e < EXPD; e += 32) {
                int i, j; float cfv;
                if (e == 0)      { i=16; j=16; cfv=1.f; }
                else if (e < 17) { i=e-1; j=16; cfv=0.5f; }
                else { int p = e-17; i=p>>4; j=p&15; cfv=C2; }
                Phi[tt*274 + e] = qs[tt*18+i] * qs[tt*18+j] * cfv;
            }
        }
        for (int e = tid; e < EXPD; e += 256)
            zs[e] = g_z[((size_t)((b*HH + h)*NC + c))*EXPD + e];
    }
    __syncthreads();

    const int t = tid >> 1, d0 = (tid & 1) * 32;
    const int t274 = t * 274;
    float4 acc[8];
#pragma unroll
    for (int g = 0; g < 8; g++) acc[g] = make_float4(0.f,0.f,0.f,0.f);
    float den = 0.f;
    const size_t Sbase = ((size_t)((b*HH + h)*NC + c)) * EXPD * HD;

    for (int e0 = 0; e0 < EXPD; e0 += 16) {
        int ne = EXPD - e0; if (ne > 16) ne = 16;
        __syncthreads();
        for (int idx = tid; idx < ne*64; idx += 256)
            kvt[idx] = g_S[Sbase + (size_t)e0*64 + idx];
        __syncthreads();
        for (int ee = 0; ee < ne; ee++) {
            float ph = Phi[t274 + e0 + ee];
            den = fmaf(ph, zs[e0 + ee], den);
            const float4* kr = (const float4*)(kvt + ee*64 + d0);
#pragma unroll
            for (int g = 0; g < 8; g++) {
                float4 kv4 = kr[g];
                acc[g].x = fmaf(ph, kv4.x, acc[g].x);
                acc[g].y = fmaf(ph, kv4.y, acc[g].y);
                acc[g].z = fmaf(ph, kv4.z, acc[g].z);
                acc[g].w = fmaf(ph, kv4.w, acc[g].w);
            }
        }
    }
    float* op = g_att + (size_t)(b*SS + c*CHK + t)*VDIM + h*HD + d0;
#pragma unroll
    for (int g = 0; g < 8; g++) *(float4*)(op + g*4) = acc[g];
    if ((tid & 1) == 0)
        g_den[(size_t)(b*HH + h)*SS + c*CHK + t] = den;
}

// ---- pass2b: intra-chunk causal term + normalize ----
#define P2B_SMEM ((128*17*2 + 128*64 + 128*129 + 128) * 4)
__global__ __launch_bounds__(256) void pass2b_kernel()
{
    extern __shared__ float sm[];
    float* qs  = sm;              // [128][17]
    float* ksm = qs + 128*17;     // [128][17]
    float* vsm = ksm + 128*17;    // [128][64]
    float* Am  = vsm + 128*64;    // [128][129]
    float* rs  = Am + 128*129;    // [128]
    const int c = blockIdx.x, h = blockIdx.y, b = blockIdx.z;
    const int tid = threadIdx.x;
    {
        int t = tid >> 1, f0 = (tid & 1) * 8;
        const float* qp = g_q + (size_t)(b*SS + c*CHK + t)*QKDIM + h*FF + f0;
        const float* kp = g_k + (size_t)(b*SS + c*CHK + t)*QKDIM + h*FF + f0;
        float4 a = *(const float4*)qp;  float4 a2 = *(const float4*)(qp + 4);
        float4 kk = *(const float4*)kp; float4 k2 = *(const float4*)(kp + 4);
        qs[t*17+f0+0]=a.x;  qs[t*17+f0+1]=a.y;  qs[t*17+f0+2]=a.z;  qs[t*17+f0+3]=a.w;
        qs[t*17+f0+4]=a2.x; qs[t*17+f0+5]=a2.y; qs[t*17+f0+6]=a2.z; qs[t*17+f0+7]=a2.w;
        ksm[t*17+f0+0]=kk.x; ksm[t*17+f0+1]=kk.y; ksm[t*17+f0+2]=kk.z; ksm[t*17+f0+3]=kk.w;
        ksm[t*17+f0+4]=k2.x; ksm[t*17+f0+5]=k2.y; ksm[t*17+f0+6]=k2.z; ksm[t*17+f0+7]=k2.w;
    }
    for (int idx = tid; idx < CHK*16; idx += 256) {
        int t = idx >> 4, d4 = (idx & 15) * 4;
        *(float4*)&vsm[t*64 + d4] = *(const float4*)(g_v + (size_t)(b*SS + c*CHK + t)*VDIM + h*HD + d4);
    }
    __syncthreads();

    {
        const int t = tid >> 1, u0 = (tid & 1) * 64;
        float qreg[16];
#pragma unroll
        for (int f = 0; f < 16; f++) qreg[f] = qs[t*17+f];
        float rsum = 0.f;
        for (int uu = 0; uu < 64; uu++) {
            int u = u0 + uu;
            float s = 0.f;
#pragma unroll
            for (int f = 0; f < 16; f++)
                s = fmaf(qreg[f], ksm[u*17+f], s);
            float a = (u <= t) ? fmaf(s, fmaf(s, 0.03125f, 0.25f), 1.0f) : 0.f;
            Am[t*129 + u] = a;
            rsum += a;
        }
        rsum += __shfl_xor_sync(0xffffffffu, rsum, 1);
        if ((tid & 1) == 0) rs[t] = rsum;
    }
    __syncthreads();

    {
        const int t = tid >> 1, d0 = (tid & 1) * 32;
        float4 acc[8];
#pragma unroll
        for (int g = 0; g < 8; g++) acc[g] = make_float4(0.f,0.f,0.f,0.f);
        const int tmax = (tid >> 5) * 16 + 15;
        for (int u = 0; u <= tmax; u++) {
            float a = Am[t*129 + u];
            const float4* vr = (const float4*)&vsm[u*64 + d0];
#pragma unroll
            for (int g = 0; g < 8; g++) {
                float4 vv = vr[g];
                acc[g].x = fmaf(a, vv.x, acc[g].x);
                acc[g].y = fmaf(a, vv.y, acc[g].y);
                acc[g].z = fmaf(a, vv.z, acc[g].z);
                acc[g].w = fmaf(a, vv.w, acc[g].w);
            }
        }
        float den = rs[t] + g_den[(size_t)(b*HH + h)*SS + c*CHK + t] + 1e-6f;
        float inv = 1.0f / den;
        float* op = g_att + (size_t)(b*SS + c*CHK + t)*VDIM + h*HD + d0;
#pragma unroll
        for (int g = 0; g < 8; g++) {
            float4 cur = *(float4*)(op + g*4);
            cur.x = (cur.x + acc[g].x) * inv;
            cur.y = (cur.y + acc[g].y) * inv;
            cur.z = (cur.z + acc[g].z) * inv;
            cur.w = (cur.w + acc[g].w) * inv;
            *(float4*)(op + g*4) = cur;
        }
    }
}

extern "C" void kernel_launch(void* const* d_in, const int* in_sizes, int n_in,
                              void* d_out, int out_size)
{
    (void)in_sizes; (void)n_in;
    const float* x    = (const float*)d_in[0];
    const float* kv0  = (const float*)d_in[1];
    const float* kst0 = (const float*)d_in[2];
    const float* Wq   = (const float*)d_in[3];
    const float* bq   = (const float*)d_in[4];
    const float* Wk   = (const float*)d_in[5];
    const float* bk   = (const float*)d_in[6];
    const float* Wv   = (const float*)d_in[7];
    const float* bv   = (const float*)d_in[8];
    const float* Wo   = (const float*)d_in[9];
    const float* bo   = (const float*)d_in[10];

    float* y = (float*)d_out;
    float* kvf = nullptr;
    float* kstf = nullptr;
    if (out_size >= Y_ELEMS + KV_ELEMS + KST_ELEMS) {
        kvf  = y + Y_ELEMS;
        kstf = kvf + KV_ELEMS;
    }

    float *pq, *pk, *pv, *patt;
    cudaGetSymbolAddress((void**)&pq,   g_q);
    cudaGetSymbolAddress((void**)&pk,   g_k);
    cudaGetSymbolAddress((void**)&pv,   g_v);
    cudaGetSymbolAddress((void**)&patt, g_att);

    cudaFuncSetAttribute(pass2a_kernel, cudaFuncAttributeMaxDynamicSharedMemorySize, P2A_SMEM);
    cudaFuncSetAttribute(pass2b_kernel, cudaFuncAttributeMaxDynamicSharedMemorySize, P2B_SMEM);

    const int M = BB * SS;
    gemm_bias<<<dim3(QKDIM/64, M/128), 256>>>(x, Wq, bq, pq, M, QKDIM, DM);
    gemm_bias<<<dim3(QKDIM/64, M/128), 256>>>(x, Wk, bk, pk, M, QKDIM, DM);
    gemm_bias<<<dim3(VDIM/64,  M/128), 256>>>(x, Wv, bv, pv, M, VDIM,  DM);

    pass1_kernel<<<dim3(NC, HH, BB), 256>>>();
    prefix_kernel<<<dim3(HH, BB), 256>>>(kv0, kst0, kvf, kstf);
    pass2a_kernel<<<dim3(NC, HH, BB), 256, P2A_SMEM>>>();
    pass2b_kernel<<<dim3(NC, HH, BB), 256, P2B_SMEM>>>();

    gemm_bias<<<dim3(DM/64, M/128), 256>>>(patt, Wo, bo, y, M, DM, VDIM);
}

// round 9
// speedup vs baseline: 1.4206x; 1.4206x over previous
#include <cuda_runtime.h>
#include <cuda_bf16.h>
#include <cstdint>

#define BB 4
#define SS 2048
#define DM 1024
#define HH 16
#define FF 16
#define HD 64
#define EXPD 273
#define NC 16
#define CHK 128
#define QKDIM (HH*FF)
#define VDIM  (HH*HD)
#define C2 0.17677669529663687f

#define Y_ELEMS   (BB*SS*DM)
#define KV_ELEMS  (BB*HH*EXPD*HD)
#define KST_ELEMS (BB*HH*EXPD)

__device__ float g_q[BB*SS*QKDIM];
__device__ float g_k[BB*SS*QKDIM];
__device__ float g_v[BB*SS*VDIM];
__device__ float g_S[BB*HH*NC*EXPD*HD];
__device__ float g_z[BB*HH*NC*EXPD];
__device__ float g_den[BB*HH*SS];
__device__ float g_att[BB*SS*VDIM];           // inter-chunk partial (pass2a -> pass2b)
__device__ __nv_bfloat16 g_xhi[BB*SS*DM];     // x hi/lo, later reused for att hi/lo
__device__ __nv_bfloat16 g_xlo[BB*SS*DM];
__device__ __nv_bfloat16 g_wth[DM*DM];        // W^T hi/lo (reused per GEMM, serialized)
__device__ __nv_bfloat16 g_wtl[DM*DM];

// ---------------- helpers ----------------
__device__ __forceinline__ uint32_t su32(const void* p) {
    uint32_t a;
    asm("{ .reg .u64 t; cvta.to.shared.u64 t, %1; cvt.u32.u64 %0, t; }" : "=r"(a) : "l"(p));
    return a;
}
__device__ __forceinline__ uint32_t swz(uint32_t o) { return o ^ ((o >> 3) & 0x70); }

#define LDSM4(r0,r1,r2,r3, addr) \
    asm volatile("ldmatrix.sync.aligned.m8n8.x4.shared.b16 {%0,%1,%2,%3}, [%4];" \
                 : "=r"(r0),"=r"(r1),"=r"(r2),"=r"(r3) : "r"(addr))
#define LDSM2(r0,r1, addr) \
    asm volatile("ldmatrix.sync.aligned.m8n8.x2.shared.b16 {%0,%1}, [%2];" \
                 : "=r"(r0),"=r"(r1) : "r"(addr))
#define MMA16816(d, a, b) \
    asm volatile("mma.sync.aligned.m16n8k16.row.col.f32.bf16.bf16.f32 " \
                 "{%0,%1,%2,%3},{%4,%5,%6,%7},{%8,%9},{%0,%1,%2,%3};" \
                 : "+f"((d)[0]),"+f"((d)[1]),"+f"((d)[2]),"+f"((d)[3]) \
                 : "r"((a)[0]),"r"((a)[1]),"r"((a)[2]),"r"((a)[3]),"r"((b)[0]),"r"((b)[1]))

// ---------------- conversion kernels ----------------
__global__ void cvt_split(const float* __restrict__ in,
                          __nv_bfloat16* __restrict__ hi,
                          __nv_bfloat16* __restrict__ lo, int n)
{
    int i = (blockIdx.x * blockDim.x + threadIdx.x) * 4;
    if (i >= n) return;
    float4 v = *(const float4*)(in + i);
    __nv_bfloat16 h0 = __float2bfloat16(v.x), h1 = __float2bfloat16(v.y);
    __nv_bfloat16 h2 = __float2bfloat16(v.z), h3 = __float2bfloat16(v.w);
    __nv_bfloat162 ph0 = __halves2bfloat162(h0, h1);
    __nv_bfloat162 ph1 = __halves2bfloat162(h2, h3);
    __nv_bfloat162 pl0 = __halves2bfloat162(__float2bfloat16(v.x - __bfloat162float(h0)),
                                            __float2bfloat16(v.y - __bfloat162float(h1)));
    __nv_bfloat162 pl1 = __halves2bfloat162(__float2bfloat16(v.z - __bfloat162float(h2)),
                                            __float2bfloat16(v.w - __bfloat162float(h3)));
    *(__nv_bfloat162*)(hi + i)     = ph0;
    *(__nv_bfloat162*)(hi + i + 2) = ph1;
    *(__nv_bfloat162*)(lo + i)     = pl0;
    *(__nv_bfloat162*)(lo + i + 2) = pl1;
}

// W[K,N] -> WT_hi/lo[N,K] (transpose + split)
__global__ void cvt_wT(const float* __restrict__ W,
                       __nv_bfloat16* __restrict__ Th,
                       __nv_bfloat16* __restrict__ Tl, int K, int N)
{
    __shared__ float t[32][33];
    const int bx = blockIdx.x * 32, by = blockIdx.y * 32;
    const int tx = threadIdx.x & 31, ty = threadIdx.x >> 5;
#pragma unroll
    for (int r = 0; r < 4; r++)
        t[ty + 8 * r][tx] = W[(size_t)(by + ty + 8 * r) * N + bx + tx];
    __syncthreads();
#pragma unroll
    for (int r = 0; r < 4; r++) {
        float v = t[tx][ty + 8 * r];
        __nv_bfloat16 h = __float2bfloat16(v);
        Th[(size_t)(bx + ty + 8 * r) * K + by + tx] = h;
        Tl[(size_t)(bx + ty + 8 * r) * K + by + tx] = __float2bfloat16(v - __bfloat162float(h));
    }
}

// ---------------- bf16 split-precision GEMM via mma.sync ----------------
// C[M,N] = A @ W + bias, A given as hi/lo [M,K] bf16, W^T given as hi/lo [N,K] bf16.
// CTA tile 128x64, K-chunks of 64, double-buffered smem.
// stage: Ah 16K | Al 16K | Bh 8K | Bl 8K = 48K
#define STG 49152
#define GS_SMEM (2*STG)

__global__ __launch_bounds__(256, 2) void gemm_bf16(
    const __nv_bfloat16* __restrict__ Ah, const __nv_bfloat16* __restrict__ Al,
    const __nv_bfloat16* __restrict__ Bh, const __nv_bfloat16* __restrict__ Bl,
    const float* __restrict__ bias, float* __restrict__ C, int N, int K)
{
    extern __shared__ char smn[];
    const int tid = threadIdx.x, l = tid & 31, w = tid >> 5;
    const int bm = blockIdx.y * 128, bn = blockIdx.x * 64;
    const int wm = (w >> 1) * 32, wn = (w & 1) * 32;

    // staging geometry
    const int arow = tid >> 1, acol = (tid & 1) * 32;   // A: per-thread 32 bf16 (64B)
    const int brow = tid >> 2, bcol = (tid & 3) * 16;   // B: per-thread 16 bf16 (32B)

    float acc[2][4][4];
#pragma unroll
    for (int mt = 0; mt < 2; mt++)
#pragma unroll
        for (int nt = 0; nt < 4; nt++)
#pragma unroll
            for (int i = 0; i < 4; i++) acc[mt][nt][i] = 0.f;

    uint4 sah[4], sal[4], sbh[2], sbl[2];
    const int nstep = K / 64;

#define LDG_STAGE(k0) do { \
    const __nv_bfloat16* ap_h = Ah + (size_t)(bm + arow) * K + (k0) + acol; \
    const __nv_bfloat16* ap_l = Al + (size_t)(bm + arow) * K + (k0) + acol; \
    _Pragma("unroll") for (int j = 0; j < 4; j++) { \
        sah[j] = *(const uint4*)(ap_h + j * 8); \
        sal[j] = *(const uint4*)(ap_l + j * 8); } \
    const __nv_bfloat16* bp_h = Bh + (size_t)(bn + brow) * K + (k0) + bcol; \
    const __nv_bfloat16* bp_l = Bl + (size_t)(bn + brow) * K + (k0) + bcol; \
    _Pragma("unroll") for (int j = 0; j < 2; j++) { \
        sbh[j] = *(const uint4*)(bp_h + j * 8); \
        sbl[j] = *(const uint4*)(bp_l + j * 8); } \
} while (0)

#define STS_STAGE(buf) do { \
    char* pa_h = smn + (buf) * STG; \
    char* pa_l = pa_h + 16384; \
    char* pb_h = pa_h + 32768; \
    char* pb_l = pa_h + 40960; \
    _Pragma("unroll") for (int j = 0; j < 4; j++) { \
        uint32_t off = swz(arow * 128 + acol * 2 + j * 16); \
        *(uint4*)(pa_h + off) = sah[j]; \
        *(uint4*)(pa_l + off) = sal[j]; } \
    _Pragma("unroll") for (int j = 0; j < 2; j++) { \
        uint32_t off = swz(brow * 128 + bcol * 2 + j * 16); \
        *(uint4*)(pb_h + off) = sbh[j]; \
        *(uint4*)(pb_l + off) = sbl[j]; } \
} while (0)

    LDG_STAGE(0);
    STS_STAGE(0);
    __syncthreads();

    int buf = 0;
    for (int s = 0; s < nstep; s++) {
        if (s + 1 < nstep) { LDG_STAGE((s + 1) * 64); }
        {
            uint32_t base_ah = su32(smn + buf * STG);
            uint32_t base_al = base_ah + 16384;
            uint32_t base_bh = base_ah + 32768;
            uint32_t base_bl = base_ah + 40960;
#pragma unroll
            for (int kc = 0; kc < 4; kc++) {
                uint32_t fah[2][4], fal[2][4], fbh[4][2], fbl[4][2];
#pragma unroll
                for (int mt = 0; mt < 2; mt++) {
                    uint32_t off = swz((wm + mt * 16 + (l & 15)) * 128 + kc * 32 + (l >> 4) * 16);
                    LDSM4(fah[mt][0], fah[mt][1], fah[mt][2], fah[mt][3], base_ah + off);
                    LDSM4(fal[mt][0], fal[mt][1], fal[mt][2], fal[mt][3], base_al + off);
                }
#pragma unroll
                for (int nt = 0; nt < 4; nt++) {
                    uint32_t off = swz((wn + nt * 8 + (l & 7)) * 128 + kc * 32 + ((l & 15) >> 3) * 16);
                    LDSM2(fbh[nt][0], fbh[nt][1], base_bh + off);
                    LDSM2(fbl[nt][0], fbl[nt][1], base_bl + off);
                }
#pragma unroll
                for (int mt = 0; mt < 2; mt++)
#pragma unroll
                    for (int nt = 0; nt < 4; nt++) {
                        MMA16816(acc[mt][nt], fah[mt], fbh[nt]);
                        MMA16816(acc[mt][nt], fah[mt], fbl[nt]);
                        MMA16816(acc[mt][nt], fal[mt], fbh[nt]);
                    }
            }
        }
        if (s + 1 < nstep) { STS_STAGE(buf ^ 1); }
        __syncthreads();
        buf ^= 1;
    }

    // epilogue: direct global stores + bias
    const int gr = l >> 2, tc = l & 3;
#pragma unroll
    for (int mt = 0; mt < 2; mt++)
#pragma unroll
        for (int nt = 0; nt < 4; nt++) {
            int m = bm + wm + mt * 16 + gr;
            int n = bn + wn + nt * 8 + tc * 2;
            float2 bv = *(const float2*)(bias + n);
            float2 o0 = make_float2(acc[mt][nt][0] + bv.x, acc[mt][nt][1] + bv.y);
            float2 o1 = make_float2(acc[mt][nt][2] + bv.x, acc[mt][nt][3] + bv.y);
            *(float2*)(C + (size_t)m * N + n) = o0;
            *(float2*)(C + (size_t)(m + 8) * N + n) = o1;
        }
}

// ================= pass1: per-chunk S = Phi_k^T V, z = sum phi_k =================
#define P1ACC(s_) do { \
    float phi = ks[t][ii[s_]] * ks[t][jj[s_]]; \
    zacc[s_] += phi; \
    acc[s_][0].x=fmaf(phi,v0.x,acc[s_][0].x); acc[s_][0].y=fmaf(phi,v0.y,acc[s_][0].y); \
    acc[s_][0].z=fmaf(phi,v0.z,acc[s_][0].z); acc[s_][0].w=fmaf(phi,v0.w,acc[s_][0].w); \
    acc[s_][1].x=fmaf(phi,v1.x,acc[s_][1].x); acc[s_][1].y=fmaf(phi,v1.y,acc[s_][1].y); \
    acc[s_][1].z=fmaf(phi,v1.z,acc[s_][1].z); acc[s_][1].w=fmaf(phi,v1.w,acc[s_][1].w); \
    acc[s_][2].x=fmaf(phi,v2.x,acc[s_][2].x); acc[s_][2].y=fmaf(phi,v2.y,acc[s_][2].y); \
    acc[s_][2].z=fmaf(phi,v2.z,acc[s_][2].z); acc[s_][2].w=fmaf(phi,v2.w,acc[s_][2].w); \
    acc[s_][3].x=fmaf(phi,v3.x,acc[s_][3].x); acc[s_][3].y=fmaf(phi,v3.y,acc[s_][3].y); \
    acc[s_][3].z=fmaf(phi,v3.z,acc[s_][3].z); acc[s_][3].w=fmaf(phi,v3.w,acc[s_][3].w); \
} while (0)

__global__ __launch_bounds__(256) void pass1_kernel()
{
    __shared__ __align__(16) float ks[CHK][18];
    __shared__ __align__(16) float vs[CHK][64];
    const int c = blockIdx.x, h = blockIdx.y, b = blockIdx.z;
    const int tid = threadIdx.x;
    {
        int t = tid >> 1, f0 = (tid & 1) * 8;
        const float* kp = g_k + (size_t)(b*SS + c*CHK + t)*QKDIM + h*FF + f0;
        float4 k0 = *(const float4*)kp;
        float4 k1 = *(const float4*)(kp + 4);
        ks[t][f0+0]=k0.x; ks[t][f0+1]=k0.y; ks[t][f0+2]=k0.z; ks[t][f0+3]=k0.w;
        ks[t][f0+4]=k1.x; ks[t][f0+5]=k1.y; ks[t][f0+6]=k1.z; ks[t][f0+7]=k1.w;
        if (f0 == 0) ks[t][16] = 1.0f;
    }
    for (int idx = tid; idx < CHK*16; idx += 256) {
        int t = idx >> 4, d4 = (idx & 15) * 4;
        *(float4*)&vs[t][d4] = *(const float4*)(g_v + (size_t)(b*SS + c*CHK + t)*VDIM + h*HD + d4);
    }
    __syncthreads();

    const int eg = tid >> 2, dsub = tid & 3;
    int ii[5], jj[5]; float cf[5];
#pragma unroll
    for (int s = 0; s < 5; s++) {
        int e = eg + 64 * s;
        if (e >= EXPD)   { ii[s]=16; jj[s]=16; cf[s]=0.f; }
        else if (e == 0) { ii[s]=16; jj[s]=16; cf[s]=1.f; }
        else if (e < 17) { ii[s]=e-1; jj[s]=16; cf[s]=0.5f; }
        else { int p = e-17; ii[s]=p>>4; jj[s]=p&15; cf[s]=C2; }
    }
    const bool has5 = (eg < 17);

    float4 acc[5][4];
#pragma unroll
    for (int s = 0; s < 5; s++)
#pragma unroll
        for (int g = 0; g < 4; g++) acc[s][g] = make_float4(0.f,0.f,0.f,0.f);
    float zacc[5] = {0.f,0.f,0.f,0.f,0.f};

    for (int t = 0; t < CHK; t++) {
        float4 v0 = *(const float4*)&vs[t][dsub*16];
        float4 v1 = *(const float4*)&vs[t][dsub*16+4];
        float4 v2 = *(const float4*)&vs[t][dsub*16+8];
        float4 v3 = *(const float4*)&vs[t][dsub*16+12];
        P1ACC(0); P1ACC(1); P1ACC(2); P1ACC(3);
        if (has5) { P1ACC(4); }
    }

    const size_t Sbase = ((size_t)((b*HH + h)*NC + c)) * EXPD * HD;
    const size_t zbase = ((size_t)((b*HH + h)*NC + c)) * EXPD;
#pragma unroll
    for (int s = 0; s < 5; s++) {
        int e = eg + 64*s;
        if (e >= EXPD) continue;
        float cfv = cf[s];
        float* op = g_S + Sbase + (size_t)e*HD + dsub*16;
#pragma unroll
        for (int g = 0; g < 4; g++) {
            float4 o = acc[s][g];
            o.x*=cfv; o.y*=cfv; o.z*=cfv; o.w*=cfv;
            *(float4*)(op + g*4) = o;
        }
        if (dsub == 0) g_z[zbase + e] = zacc[s] * cfv;
    }
}

// ================= prefix =================
__global__ __launch_bounds__(256) void prefix_kernel(
    const float* __restrict__ kv0, const float* __restrict__ kst0,
    float* __restrict__ out_kv, float* __restrict__ out_kst)
{
    const int h = blockIdx.x, b = blockIdx.y;
    const int pair = b*HH + h;
    const int tid = threadIdx.x;
    for (int idx = tid; idx < EXPD*HD; idx += 256) {
        float run = kv0[(size_t)pair*EXPD*HD + idx];
        float* p = g_S + ((size_t)pair*NC)*EXPD*HD + idx;
#pragma unroll
        for (int cc = 0; cc < NC; cc++) {
            float sv = p[(size_t)cc*EXPD*HD];
            p[(size_t)cc*EXPD*HD] = run;
            run += sv;
        }
        if (out_kv) out_kv[(size_t)pair*EXPD*HD + idx] = run;
    }
    for (int idx = tid; idx < EXPD; idx += 256) {
        float run = kst0[(size_t)pair*EXPD + idx];
        float* p = g_z + ((size_t)pair*NC)*EXPD + idx;
#pragma unroll
        for (int cc = 0; cc < NC; cc++) {
            float sv = p[(size_t)cc*EXPD];
            p[(size_t)cc*EXPD] = run;
            run += sv;
        }
        if (out_kst) out_kst[(size_t)pair*EXPD + idx] = run;
    }
}

// ================= pass2a =================
#define P2A_SMEM ((128*18 + 128*274 + 280 + 16*64) * 4)
__global__ __launch_bounds__(256) void pass2a_kernel()
{
    extern __shared__ float sm[];
    float* qs  = sm;
    float* Phi = sm + 128*18;
    float* zs  = Phi + 128*274;
    float* kvt = zs + 280;
    const int c = blockIdx.x, h = blockIdx.y, b = blockIdx.z;
    const int tid = threadIdx.x;
    {
        int t = tid >> 1, f0 = (tid & 1) * 8;
        const float* qp = g_q + (size_t)(b*SS + c*CHK + t)*QKDIM + h*FF + f0;
        float4 a = *(const float4*)qp;
        float4 b4 = *(const float4*)(qp + 4);
        qs[t*18+f0+0]=a.x;  qs[t*18+f0+1]=a.y;  qs[t*18+f0+2]=a.z;  qs[t*18+f0+3]=a.w;
        qs[t*18+f0+4]=b4.x; qs[t*18+f0+5]=b4.y; qs[t*18+f0+6]=b4.z; qs[t*18+f0+7]=b4.w;
        if (f0 == 0) qs[t*18+16] = 1.0f;
    }
    __syncthreads();
    {
        int w = tid >> 5, lane = tid & 31;
        for (int tt = w*16; tt < w*16 + 16; tt++) {
            for (int e = lane; e < EXPD; e += 32) {
                int i, j; float cfv;
                if (e == 0)      { i=16; j=16; cfv=1.f; }
                else if (e < 17) { i=e-1; j=16; cfv=0.5f; }
                else { int p = e-17; i=p>>4; j=p&15; cfv=C2; }
                Phi[tt*274 + e] = qs[tt*18+i] * qs[tt*18+j] * cfv;
            }
        }
        for (int e = tid; e < EXPD; e += 256)
            zs[e] = g_z[((size_t)((b*HH + h)*NC + c))*EXPD + e];
    }
    __syncthreads();

    const int t = tid >> 1, d0 = (tid & 1) * 32;
    const int t274 = t * 274;
    float4 acc[8];
#pragma unroll
    for (int g = 0; g < 8; g++) acc[g] = make_float4(0.f,0.f,0.f,0.f);
    float den = 0.f;
    const size_t Sbase = ((size_t)((b*HH + h)*NC + c)) * EXPD * HD;

    for (int e0 = 0; e0 < EXPD; e0 += 16) {
        int ne = EXPD - e0; if (ne > 16) ne = 16;
        __syncthreads();
        for (int idx = tid; idx < ne*64; idx += 256)
            kvt[idx] = g_S[Sbase + (size_t)e0*64 + idx];
        __syncthreads();
        for (int ee = 0; ee < ne; ee++) {
            float ph = Phi[t274 + e0 + ee];
            den = fmaf(ph, zs[e0 + ee], den);
            const float4* kr = (const float4*)(kvt + ee*64 + d0);
#pragma unroll
            for (int g = 0; g < 8; g++) {
                float4 kv4 = kr[g];
                acc[g].x = fmaf(ph, kv4.x, acc[g].x);
                acc[g].y = fmaf(ph, kv4.y, acc[g].y);
                acc[g].z = fmaf(ph, kv4.z, acc[g].z);
                acc[g].w = fmaf(ph, kv4.w, acc[g].w);
            }
        }
    }
    float* op = g_att + (size_t)(b*SS + c*CHK + t)*VDIM + h*HD + d0;
#pragma unroll
    for (int g = 0; g < 8; g++) *(float4*)(op + g*4) = acc[g];
    if ((tid & 1) == 0)
        g_den[(size_t)(b*HH + h)*SS + c*CHK + t] = den;
}

// ================= pass2b: intra-chunk + normalize; emits att as bf16 hi/lo =================
#define P2B_SMEM ((128*17*2 + 128*64 + 128*129 + 128) * 4)
__global__ __launch_bounds__(256) void pass2b_kernel()
{
    extern __shared__ float sm[];
    float* qs  = sm;
    float* ksm = qs + 128*17;
    float* vsm = ksm + 128*17;
    float* Am  = vsm + 128*64;
    float* rs  = Am + 128*129;
    const int c = blockIdx.x, h = blockIdx.y, b = blockIdx.z;
    const int tid = threadIdx.x;
    {
        int t = tid >> 1, f0 = (tid & 1) * 8;
        const float* qp = g_q + (size_t)(b*SS + c*CHK + t)*QKDIM + h*FF + f0;
        const float* kp = g_k + (size_t)(b*SS + c*CHK + t)*QKDIM + h*FF + f0;
        float4 a = *(const float4*)qp;  float4 a2 = *(const float4*)(qp + 4);
        float4 kk = *(const float4*)kp; float4 k2 = *(const float4*)(kp + 4);
        qs[t*17+f0+0]=a.x;  qs[t*17+f0+1]=a.y;  qs[t*17+f0+2]=a.z;  qs[t*17+f0+3]=a.w;
        qs[t*17+f0+4]=a2.x; qs[t*17+f0+5]=a2.y; qs[t*17+f0+6]=a2.z; qs[t*17+f0+7]=a2.w;
        ksm[t*17+f0+0]=kk.x; ksm[t*17+f0+1]=kk.y; ksm[t*17+f0+2]=kk.z; ksm[t*17+f0+3]=kk.w;
        ksm[t*17+f0+4]=k2.x; ksm[t*17+f0+5]=k2.y; ksm[t*17+f0+6]=k2.z; ksm[t*17+f0+7]=k2.w;
    }
    for (int idx = tid; idx < CHK*16; idx += 256) {
        int t = idx >> 4, d4 = (idx & 15) * 4;
        *(float4*)&vsm[t*64 + d4] = *(const float4*)(g_v + (size_t)(b*SS + c*CHK + t)*VDIM + h*HD + d4);
    }
    __syncthreads();

    {
        const int t = tid >> 1, u0 = (tid & 1) * 64;
        float qreg[16];
#pragma unroll
        for (int f = 0; f < 16; f++) qreg[f] = qs[t*17+f];
        float rsum = 0.f;
        for (int uu = 0; uu < 64; uu++) {
            int u = u0 + uu;
            float s = 0.f;
#pragma unroll
            for (int f = 0; f < 16; f++)
                s = fmaf(qreg[f], ksm[u*17+f], s);
            float a = (u <= t) ? fmaf(s, fmaf(s, 0.03125f, 0.25f), 1.0f) : 0.f;
            Am[t*129 + u] = a;
            rsum += a;
        }
        rsum += __shfl_xor_sync(0xffffffffu, rsum, 1);
        if ((tid & 1) == 0) rs[t] = rsum;
    }
    __syncthreads();

    {
        const int t = tid >> 1, d0 = (tid & 1) * 32;
        float4 acc[8];
#pragma unroll
        for (int g = 0; g < 8; g++) acc[g] = make_float4(0.f,0.f,0.f,0.f);
        const int tmax = (tid >> 5) * 16 + 15;
        for (int u = 0; u <= tmax; u++) {
            float a = Am[t*129 + u];
            const float4* vr = (const float4*)&vsm[u*64 + d0];
#pragma unroll
            for (int g = 0; g < 8; g++) {
                float4 vv = vr[g];
                acc[g].x = fmaf(a, vv.x, acc[g].x);
                acc[g].y = fmaf(a, vv.y, acc[g].y);
                acc[g].z = fmaf(a, vv.z, acc[g].z);
                acc[g].w = fmaf(a, vv.w, acc[g].w);
            }
        }
        float den = rs[t] + g_den[(size_t)(b*HH + h)*SS + c*CHK + t] + 1e-6f;
        float inv = 1.0f / den;
        const size_t obase = (size_t)(b*SS + c*CHK + t)*VDIM + h*HD + d0;
        const float* ip = g_att + obase;
#pragma unroll
        for (int g = 0; g < 8; g++) {
            float4 cur = *(const float4*)(ip + g*4);
            float4 r;
            r.x = (cur.x + acc[g].x) * inv;
            r.y = (cur.y + acc[g].y) * inv;
            r.z = (cur.z + acc[g].z) * inv;
            r.w = (cur.w + acc[g].w) * inv;
            __nv_bfloat16 h0 = __float2bfloat16(r.x), h1 = __float2bfloat16(r.y);
            __nv_bfloat16 h2 = __float2bfloat16(r.z), h3 = __float2bfloat16(r.w);
            __nv_bfloat162 ph0 = __halves2bfloat162(h0, h1);
            __nv_bfloat162 ph1 = __halves2bfloat162(h2, h3);
            __nv_bfloat162 pl0 = __halves2bfloat162(__float2bfloat16(r.x - __bfloat162float(h0)),
                                                    __float2bfloat16(r.y - __bfloat162float(h1)));
            __nv_bfloat162 pl1 = __halves2bfloat162(__float2bfloat16(r.z - __bfloat162float(h2)),
                                                    __float2bfloat16(r.w - __bfloat162float(h3)));
            *(__nv_bfloat162*)(g_xhi + obase + g*4)     = ph0;
            *(__nv_bfloat162*)(g_xhi + obase + g*4 + 2) = ph1;
            *(__nv_bfloat162*)(g_xlo + obase + g*4)     = pl0;
            *(__nv_bfloat162*)(g_xlo + obase + g*4 + 2) = pl1;
        }
    }
}

extern "C" void kernel_launch(void* const* d_in, const int* in_sizes, int n_in,
                              void* d_out, int out_size)
{
    (void)in_sizes; (void)n_in;
    const float* x    = (const float*)d_in[0];
    const float* kv0  = (const float*)d_in[1];
    const float* kst0 = (const float*)d_in[2];
    const float* Wq   = (const float*)d_in[3];
    const float* bq   = (const float*)d_in[4];
    const float* Wk   = (const float*)d_in[5];
    const float* bk   = (const float*)d_in[6];
    const float* Wv   = (const float*)d_in[7];
    const float* bv   = (const float*)d_in[8];
    const float* Wo   = (const float*)d_in[9];
    const float* bo   = (const float*)d_in[10];

    float* y = (float*)d_out;
    float* kvf = nullptr;
    float* kstf = nullptr;
    if (out_size >= Y_ELEMS + KV_ELEMS + KST_ELEMS) {
        kvf  = y + Y_ELEMS;
        kstf = kvf + KV_ELEMS;
    }

    float *pq, *pk, *pv;
    __nv_bfloat16 *xhi, *xlo, *wth, *wtl;
    cudaGetSymbolAddress((void**)&pq,  g_q);
    cudaGetSymbolAddress((void**)&pk,  g_k);
    cudaGetSymbolAddress((void**)&pv,  g_v);
    cudaGetSymbolAddress((void**)&xhi, g_xhi);
    cudaGetSymbolAddress((void**)&xlo, g_xlo);
    cudaGetSymbolAddress((void**)&wth, g_wth);
    cudaGetSymbolAddress((void**)&wtl, g_wtl);

    cudaFuncSetAttribute(gemm_bf16, cudaFuncAttributeMaxDynamicSharedMemorySize, GS_SMEM);
    cudaFuncSetAttribute(pass2a_kernel, cudaFuncAttributeMaxDynamicSharedMemorySize, P2A_SMEM);
    cudaFuncSetAttribute(pass2b_kernel, cudaFuncAttributeMaxDynamicSharedMemorySize, P2B_SMEM);

    const int M = BB * SS;  // 8192

    // split x once
    cvt_split<<<(M * DM) / 1024, 256>>>(x, xhi, xlo, M * DM);

    // Q projection
    cvt_wT<<<dim3(QKDIM/32, DM/32), 256>>>(Wq, wth, wtl, DM, QKDIM);
    gemm_bf16<<<dim3(QKDIM/64, M/128), 256, GS_SMEM>>>(xhi, xlo, wth, wtl, bq, pq, QKDIM, DM);
    // K projection
    cvt_wT<<<dim3(QKDIM/32, DM/32), 256>>>(Wk, wth, wtl, DM, QKDIM);
    gemm_bf16<<<dim3(QKDIM/64, M/128), 256, GS_SMEM>>>(xhi, xlo, wth, wtl, bk, pk, QKDIM, DM);
    // V projection
    cvt_wT<<<dim3(VDIM/32, DM/32), 256>>>(Wv, wth, wtl, DM, VDIM);
    gemm_bf16<<<dim3(VDIM/64, M/128), 256, GS_SMEM>>>(xhi, xlo, wth, wtl, bv, pv, VDIM, DM);

    pass1_kernel<<<dim3(NC, HH, BB), 256>>>();
    prefix_kernel<<<dim3(HH, BB), 256>>>(kv0, kst0, kvf, kstf);
    pass2a_kernel<<<dim3(NC, HH, BB), 256, P2A_SMEM>>>();
    pass2b_kernel<<<dim3(NC, HH, BB), 256, P2B_SMEM>>>();   // writes att hi/lo into xhi/xlo

    // output projection: y = att @ Wo + bo
    cvt_wT<<<dim3(DM/32, VDIM/32), 256>>>(Wo, wth, wtl, VDIM, DM);
    gemm_bf16<<<dim3(DM/64, M/128), 256, GS_SMEM>>>(xhi, xlo, wth, wtl, bo, y, DM, VDIM);
}

// round 10
// speedup vs baseline: 1.4901x; 1.0489x over previous
#include <cuda_runtime.h>
#include <cuda_bf16.h>
#include <cstdint>

#define BB 4
#define SS 2048
#define DM 1024
#define HH 16
#define FF 16
#define HD 64
#define EXPD 273
#define NC 16
#define CHK 128
#define QKDIM (HH*FF)
#define VDIM  (HH*HD)
#define QKVW  1536
#define OFF_K 256
#define OFF_V 512
#define C2 0.17677669529663687f

#define Y_ELEMS   (BB*SS*DM)
#define KV_ELEMS  (BB*HH*EXPD*HD)
#define KST_ELEMS (BB*HH*EXPD)

__device__ float g_qkv[BB*SS*QKVW];
__device__ float g_S[BB*HH*NC*EXPD*HD];
__device__ float g_z[BB*HH*NC*EXPD];
__device__ float g_den[BB*HH*SS];
__device__ float g_att[BB*SS*VDIM];
__device__ float g_bqkv[QKVW];
__device__ __nv_bfloat16 g_xhi[BB*SS*DM];     // x hi/lo, later reused for att hi/lo
__device__ __nv_bfloat16 g_xlo[BB*SS*DM];
__device__ __nv_bfloat16 g_wqh[QKVW*DM];      // [Wq|Wk|Wv]^T hi/lo
__device__ __nv_bfloat16 g_wql[QKVW*DM];
__device__ __nv_bfloat16 g_woh[DM*DM];        // Wo^T hi/lo
__device__ __nv_bfloat16 g_wol[DM*DM];

// ---------------- helpers ----------------
__device__ __forceinline__ uint32_t su32(const void* p) {
    uint32_t a;
    asm("{ .reg .u64 t; cvta.to.shared.u64 t, %1; cvt.u32.u64 %0, t; }" : "=r"(a) : "l"(p));
    return a;
}
__device__ __forceinline__ uint32_t swz(uint32_t o) { return o ^ ((o >> 3) & 0x70); }
__device__ __forceinline__ void cpa16(uint32_t s, const void* g) {
    asm volatile("cp.async.cg.shared.global [%0], [%1], 16;" :: "r"(s), "l"(g));
}

#define LDSM4(r0,r1,r2,r3, addr) \
    asm volatile("ldmatrix.sync.aligned.m8n8.x4.shared.b16 {%0,%1,%2,%3}, [%4];" \
                 : "=r"(r0),"=r"(r1),"=r"(r2),"=r"(r3) : "r"(addr))
#define MMA16816(d, a, b) \
    asm volatile("mma.sync.aligned.m16n8k16.row.col.f32.bf16.bf16.f32 " \
                 "{%0,%1,%2,%3},{%4,%5,%6,%7},{%8,%9},{%0,%1,%2,%3};" \
                 : "+f"((d)[0]),"+f"((d)[1]),"+f"((d)[2]),"+f"((d)[3]) \
                 : "r"((a)[0]),"r"((a)[1]),"r"((a)[2]),"r"((a)[3]),"r"((b)[0]),"r"((b)[1]))

// ---------------- conversions ----------------
__global__ void cvt_split(const float* __restrict__ in,
                          __nv_bfloat16* __restrict__ hi,
                          __nv_bfloat16* __restrict__ lo, int n,
                          const float* __restrict__ b0, const float* __restrict__ b1,
                          const float* __restrict__ b2, float* __restrict__ bout)
{
    if (blockIdx.x == gridDim.x - 1) {
        int t = threadIdx.x;
        if (t < QKDIM) { bout[t] = b0[t]; bout[OFF_K + t] = b1[t]; }
        for (int i = t; i < VDIM; i += 256) bout[OFF_V + i] = b2[i];
        return;
    }
    int i = (blockIdx.x * blockDim.x + threadIdx.x) * 4;
    if (i >= n) return;
    float4 v = *(const float4*)(in + i);
    __nv_bfloat16 h0 = __float2bfloat16(v.x), h1 = __float2bfloat16(v.y);
    __nv_bfloat16 h2 = __float2bfloat16(v.z), h3 = __float2bfloat16(v.w);
    __nv_bfloat162 ph0 = __halves2bfloat162(h0, h1);
    __nv_bfloat162 ph1 = __halves2bfloat162(h2, h3);
    __nv_bfloat162 pl0 = __halves2bfloat162(__float2bfloat16(v.x - __bfloat162float(h0)),
                                            __float2bfloat16(v.y - __bfloat162float(h1)));
    __nv_bfloat162 pl1 = __halves2bfloat162(__float2bfloat16(v.z - __bfloat162float(h2)),
                                            __float2bfloat16(v.w - __bfloat162float(h3)));
    *(__nv_bfloat162*)(hi + i)     = ph0;
    *(__nv_bfloat162*)(hi + i + 2) = ph1;
    *(__nv_bfloat162*)(lo + i)     = pl0;
    *(__nv_bfloat162*)(lo + i + 2) = pl1;
}

// all four W matrices -> transposed hi/lo, one launch (z selects matrix)
__global__ void cvt_wT_all(const float* __restrict__ Wq, const float* __restrict__ Wk,
                           const float* __restrict__ Wv, const float* __restrict__ Wo,
                           __nv_bfloat16* __restrict__ qh, __nv_bfloat16* __restrict__ ql,
                           __nv_bfloat16* __restrict__ oh, __nv_bfloat16* __restrict__ ol)
{
    __shared__ float t[32][33];
    const int z = blockIdx.z;
    const float* W; __nv_bfloat16 *Th, *Tl; int N, rowoff;
    if (z == 0)      { W = Wq; Th = qh; Tl = ql; N = QKDIM; rowoff = 0; }
    else if (z == 1) { W = Wk; Th = qh; Tl = ql; N = QKDIM; rowoff = OFF_K; }
    else if (z == 2) { W = Wv; Th = qh; Tl = ql; N = VDIM;  rowoff = OFF_V; }
    else             { W = Wo; Th = oh; Tl = ol; N = DM;    rowoff = 0; }
    const int bx = blockIdx.x * 32, by = blockIdx.y * 32;   // bx: N dim, by: K dim (1024)
    if (bx >= N) return;
    const int tx = threadIdx.x & 31, ty = threadIdx.x >> 5;
#pragma unroll
    for (int r = 0; r < 4; r++)
        t[ty + 8 * r][tx] = W[(size_t)(by + ty + 8 * r) * N + bx + tx];
    __syncthreads();
#pragma unroll
    for (int r = 0; r < 4; r++) {
        float v = t[tx][ty + 8 * r];
        __nv_bfloat16 h = __float2bfloat16(v);
        size_t o = (size_t)(rowoff + bx + ty + 8 * r) * DM + by + tx;
        Th[o] = h;
        Tl[o] = __float2bfloat16(v - __bfloat162float(h));
    }
}

// ---------------- bf16 split GEMM, cp.async pipeline ----------------
// stage: Ah 16K | Al 16K | Bh 8K | Bl 8K = 48K, double buffered
#define STG 49152
#define GS_SMEM (2*STG)

#define ISSUE_STAGE(k0, b_) do { \
    uint32_t pa_h = sbase + (b_) * STG; \
    uint32_t pa_l = pa_h + 16384; \
    uint32_t pb_h = pa_h + 32768; \
    uint32_t pb_l = pa_h + 40960; \
    const __nv_bfloat16* aph = Ah + (size_t)(bm + arow) * K + (k0) + acol; \
    const __nv_bfloat16* apl = Al + (size_t)(bm + arow) * K + (k0) + acol; \
    _Pragma("unroll") for (int j = 0; j < 4; j++) { \
        uint32_t off = swz(arow * 128 + acol * 2 + j * 16); \
        cpa16(pa_h + off, aph + j * 8); \
        cpa16(pa_l + off, apl + j * 8); } \
    const __nv_bfloat16* bph = Bh + (size_t)(bn + brow) * K + (k0) + bcol; \
    const __nv_bfloat16* bpl = Bl + (size_t)(bn + brow) * K + (k0) + bcol; \
    _Pragma("unroll") for (int j = 0; j < 2; j++) { \
        uint32_t off = swz(brow * 128 + bcol * 2 + j * 16); \
        cpa16(pb_h + off, bph + j * 8); \
        cpa16(pb_l + off, bpl + j * 8); } \
    asm volatile("cp.async.commit_group;" ::: "memory"); \
} while (0)

__global__ __launch_bounds__(256, 2) void gemm_bf16(
    const __nv_bfloat16* __restrict__ Ah, const __nv_bfloat16* __restrict__ Al,
    const __nv_bfloat16* __restrict__ Bh, const __nv_bfloat16* __restrict__ Bl,
    const float* __restrict__ bias, float* __restrict__ C, int N, int K)
{
    extern __shared__ char smn[];
    const int tid = threadIdx.x, l = tid & 31, w = tid >> 5;
    const int bm = blockIdx.y * 128, bn = blockIdx.x * 64;
    const int wm = (w >> 1) * 32, wn = (w & 1) * 32;
    const uint32_t sbase = su32(smn);

    const int arow = tid >> 1, acol = (tid & 1) * 32;
    const int brow = tid >> 2, bcol = (tid & 3) * 16;

    float acc[2][4][4] = {};
    const int nstep = K / 64;

    ISSUE_STAGE(0, 0);
    int buf = 0;
    for (int s = 0; s < nstep; s++) {
        if (s + 1 < nstep) {
            ISSUE_STAGE((s + 1) * 64, buf ^ 1);
            asm volatile("cp.async.wait_group 1;" ::: "memory");
        } else {
            asm volatile("cp.async.wait_group 0;" ::: "memory");
        }
        __syncthreads();
        uint32_t base_ah = sbase + buf * STG;
        uint32_t base_al = base_ah + 16384;
        uint32_t base_bh = base_ah + 32768;
        uint32_t base_bl = base_ah + 40960;
#pragma unroll
        for (int kc = 0; kc < 4; kc++) {
            uint32_t fah[2][4], fal[2][4], fbh[4][2], fbl[4][2];
#pragma unroll
            for (int mt = 0; mt < 2; mt++) {
                uint32_t off = swz((wm + mt * 16 + (l & 15)) * 128 + kc * 32 + (l >> 4) * 16);
                LDSM4(fah[mt][0], fah[mt][1], fah[mt][2], fah[mt][3], base_ah + off);
                LDSM4(fal[mt][0], fal[mt][1], fal[mt][2], fal[mt][3], base_al + off);
            }
#pragma unroll
            for (int np = 0; np < 2; np++) {
                uint32_t off = swz((wn + np * 16 + (l & 7) + ((l >> 4) & 1) * 8) * 128
                                   + kc * 32 + ((l >> 3) & 1) * 16);
                LDSM4(fbh[np*2][0], fbh[np*2][1], fbh[np*2+1][0], fbh[np*2+1][1], base_bh + off);
                LDSM4(fbl[np*2][0], fbl[np*2][1], fbl[np*2+1][0], fbl[np*2+1][1], base_bl + off);
            }
#pragma unroll
            for (int mt = 0; mt < 2; mt++)
#pragma unroll
                for (int nt = 0; nt < 4; nt++) {
                    MMA16816(acc[mt][nt], fah[mt], fbh[nt]);
                    MMA16816(acc[mt][nt], fah[mt], fbl[nt]);
                    MMA16816(acc[mt][nt], fal[mt], fbh[nt]);
                }
        }
        __syncthreads();
        buf ^= 1;
    }

    const int gr = l >> 2, tc = l & 3;
#pragma unroll
    for (int mt = 0; mt < 2; mt++)
#pragma unroll
        for (int nt = 0; nt < 4; nt++) {
            int m = bm + wm + mt * 16 + gr;
            int n = bn + wn + nt * 8 + tc * 2;
            float2 bv = *(const float2*)(bias + n);
            float2 o0 = make_float2(acc[mt][nt][0] + bv.x, acc[mt][nt][1] + bv.y);
            float2 o1 = make_float2(acc[mt][nt][2] + bv.x, acc[mt][nt][3] + bv.y);
            *(float2*)(C + (size_t)m * N + n) = o0;
            *(float2*)(C + (size_t)(m + 8) * N + n) = o1;
        }
}

// ================= pass1: per-chunk S = Phi_k^T V, z = sum phi_k =================
#define P1ACC(s_) do { \
    float phi = ks[t][ii[s_]] * ks[t][jj[s_]]; \
    zacc[s_] += phi; \
    acc[s_][0].x=fmaf(phi,v0.x,acc[s_][0].x); acc[s_][0].y=fmaf(phi,v0.y,acc[s_][0].y); \
    acc[s_][0].z=fmaf(phi,v0.z,acc[s_][0].z); acc[s_][0].w=fmaf(phi,v0.w,acc[s_][0].w); \
    acc[s_][1].x=fmaf(phi,v1.x,acc[s_][1].x); acc[s_][1].y=fmaf(phi,v1.y,acc[s_][1].y); \
    acc[s_][1].z=fmaf(phi,v1.z,acc[s_][1].z); acc[s_][1].w=fmaf(phi,v1.w,acc[s_][1].w); \
    acc[s_][2].x=fmaf(phi,v2.x,acc[s_][2].x); acc[s_][2].y=fmaf(phi,v2.y,acc[s_][2].y); \
    acc[s_][2].z=fmaf(phi,v2.z,acc[s_][2].z); acc[s_][2].w=fmaf(phi,v2.w,acc[s_][2].w); \
    acc[s_][3].x=fmaf(phi,v3.x,acc[s_][3].x); acc[s_][3].y=fmaf(phi,v3.y,acc[s_][3].y); \
    acc[s_][3].z=fmaf(phi,v3.z,acc[s_][3].z); acc[s_][3].w=fmaf(phi,v3.w,acc[s_][3].w); \
} while (0)

__global__ __launch_bounds__(256) void pass1_kernel()
{
    __shared__ __align__(16) float ks[CHK][18];
    __shared__ __align__(16) float vs[CHK][64];
    const int c = blockIdx.x, h = blockIdx.y, b = blockIdx.z;
    const int tid = threadIdx.x;
    {
        int t = tid >> 1, f0 = (tid & 1) * 8;
        const float* kp = g_qkv + (size_t)(b*SS + c*CHK + t)*QKVW + OFF_K + h*FF + f0;
        float4 k0 = *(const float4*)kp;
        float4 k1 = *(const float4*)(kp + 4);
        ks[t][f0+0]=k0.x; ks[t][f0+1]=k0.y; ks[t][f0+2]=k0.z; ks[t][f0+3]=k0.w;
        ks[t][f0+4]=k1.x; ks[t][f0+5]=k1.y; ks[t][f0+6]=k1.z; ks[t][f0+7]=k1.w;
        if (f0 == 0) ks[t][16] = 1.0f;
    }
    for (int idx = tid; idx < CHK*16; idx += 256) {
        int t = idx >> 4, d4 = (idx & 15) * 4;
        *(float4*)&vs[t][d4] =
            *(const float4*)(g_qkv + (size_t)(b*SS + c*CHK + t)*QKVW + OFF_V + h*HD + d4);
    }
    __syncthreads();

    const int eg = tid >> 2, dsub = tid & 3;
    int ii[5], jj[5]; float cf[5];
#pragma unroll
    for (int s = 0; s < 5; s++) {
        int e = eg + 64 * s;
        if (e >= EXPD)   { ii[s]=16; jj[s]=16; cf[s]=0.f; }
        else if (e == 0) { ii[s]=16; jj[s]=16; cf[s]=1.f; }
        else if (e < 17) { ii[s]=e-1; jj[s]=16; cf[s]=0.5f; }
        else { int p = e-17; ii[s]=p>>4; jj[s]=p&15; cf[s]=C2; }
    }
    const bool has5 = (eg < 17);

    float4 acc[5][4];
#pragma unroll
    for (int s = 0; s < 5; s++)
#pragma unroll
        for (int g = 0; g < 4; g++) acc[s][g] = make_float4(0.f,0.f,0.f,0.f);
    float zacc[5] = {0.f,0.f,0.f,0.f,0.f};

    for (int t = 0; t < CHK; t++) {
        float4 v0 = *(const float4*)&vs[t][dsub*16];
        float4 v1 = *(const float4*)&vs[t][dsub*16+4];
        float4 v2 = *(const float4*)&vs[t][dsub*16+8];
        float4 v3 = *(const float4*)&vs[t][dsub*16+12];
        P1ACC(0); P1ACC(1); P1ACC(2); P1ACC(3);
        if (has5) { P1ACC(4); }
    }

    const size_t Sbase = ((size_t)((b*HH + h)*NC + c)) * EXPD * HD;
    const size_t zbase = ((size_t)((b*HH + h)*NC + c)) * EXPD;
#pragma unroll
    for (int s = 0; s < 5; s++) {
        int e = eg + 64*s;
        if (e >= EXPD) continue;
        float cfv = cf[s];
        float* op = g_S + Sbase + (size_t)e*HD + dsub*16;
#pragma unroll
        for (int g = 0; g < 4; g++) {
            float4 o = acc[s][g];
            o.x*=cfv; o.y*=cfv; o.z*=cfv; o.w*=cfv;
            *(float4*)(op + g*4) = o;
        }
        if (dsub == 0) g_z[zbase + e] = zacc[s] * cfv;
    }
}

// ================= prefix =================
__global__ __launch_bounds__(256) void prefix_kernel(
    const float* __restrict__ kv0, const float* __restrict__ kst0,
    float* __restrict__ out_kv, float* __restrict__ out_kst)
{
    const int h = blockIdx.x, b = blockIdx.y;
    const int pair = b*HH + h;
    const int tid = threadIdx.x;
    for (int idx = tid; idx < EXPD*HD; idx += 256) {
        float run = kv0[(size_t)pair*EXPD*HD + idx];
        float* p = g_S + ((size_t)pair*NC)*EXPD*HD + idx;
#pragma unroll
        for (int cc = 0; cc < NC; cc++) {
            float sv = p[(size_t)cc*EXPD*HD];
            p[(size_t)cc*EXPD*HD] = run;
            run += sv;
        }
        if (out_kv) out_kv[(size_t)pair*EXPD*HD + idx] = run;
    }
    for (int idx = tid; idx < EXPD; idx += 256) {
        float run = kst0[(size_t)pair*EXPD + idx];
        float* p = g_z + ((size_t)pair*NC)*EXPD + idx;
#pragma unroll
        for (int cc = 0; cc < NC; cc++) {
            float sv = p[(size_t)cc*EXPD];
            p[(size_t)cc*EXPD] = run;
            run += sv;
        }
        if (out_kst) out_kst[(size_t)pair*EXPD + idx] = run;
    }
}

// ================= pass2a =================
#define P2A_SMEM ((128*18 + 128*274 + 280 + 16*64) * 4)
__global__ __launch_bounds__(256) void pass2a_kernel()
{
    extern __shared__ float sm[];
    float* qs  = sm;
    float* Phi = sm + 128*18;
    float* zs  = Phi + 128*274;
    float* kvt = zs + 280;
    const int c = blockIdx.x, h = blockIdx.y, b = blockIdx.z;
    const int tid = threadIdx.x;
    {
        int t = tid >> 1, f0 = (tid & 1) * 8;
        const float* qp = g_qkv + (size_t)(b*SS + c*CHK + t)*QKVW + h*FF + f0;
        float4 a = *(const float4*)qp;
        float4 b4 = *(const float4*)(qp + 4);
        qs[t*18+f0+0]=a.x;  qs[t*18+f0+1]=a.y;  qs[t*18+f0+2]=a.z;  qs[t*18+f0+3]=a.w;
        qs[t*18+f0+4]=b4.x; qs[t*18+f0+5]=b4.y; qs[t*18+f0+6]=b4.z; qs[t*18+f0+7]=b4.w;
        if (f0 == 0) qs[t*18+16] = 1.0f;
    }
    __syncthreads();
    {
        int w = tid >> 5, lane = tid & 31;
        for (int tt = w*16; tt < w*16 + 16; tt++) {
            for (int e = lane; e < EXPD; e += 32) {
                int i, j; float cfv;
                if (e == 0)      { i=16; j=16; cfv=1.f; }
                else if (e < 17) { i=e-1; j=16; cfv=0.5f; }
                else { int p = e-17; i=p>>4; j=p&15; cfv=C2; }
                Phi[tt*274 + e] = qs[tt*18+i] * qs[tt*18+j] * cfv;
            }
        }
        for (int e = tid; e < EXPD; e += 256)
            zs[e] = g_z[((size_t)((b*HH + h)*NC + c))*EXPD + e];
    }
    __syncthreads();

    const int t = tid >> 1, d0 = (tid & 1) * 32;
    const int t274 = t * 274;
    float4 acc[8];
#pragma unroll
    for (int g = 0; g < 8; g++) acc[g] = make_float4(0.f,0.f,0.f,0.f);
    float den = 0.f;
    const size_t Sbase = ((size_t)((b*HH + h)*NC + c)) * EXPD * HD;

    for (int e0 = 0; e0 < EXPD; e0 += 16) {
        int ne = EXPD - e0; if (ne > 16) ne = 16;
        __syncthreads();
        for (int idx = tid; idx < ne*64; idx += 256)
            kvt[idx] = g_S[Sbase + (size_t)e0*64 + idx];
        __syncthreads();
        for (int ee = 0; ee < ne; ee++) {
            float ph = Phi[t274 + e0 + ee];
            den = fmaf(ph, zs[e0 + ee], den);
            const float4* kr = (const float4*)(kvt + ee*64 + d0);
#pragma unroll
            for (int g = 0; g < 8; g++) {
                float4 kv4 = kr[g];
                acc[g].x = fmaf(ph, kv4.x, acc[g].x);
                acc[g].y = fmaf(ph, kv4.y, acc[g].y);
                acc[g].z = fmaf(ph, kv4.z, acc[g].z);
                acc[g].w = fmaf(ph, kv4.w, acc[g].w);
            }
        }
    }
    float* op = g_att + (size_t)(b*SS + c*CHK + t)*VDIM + h*HD + d0;
#pragma unroll
    for (int g = 0; g < 8; g++) *(float4*)(op + g*4) = acc[g];
    if ((tid & 1) == 0)
        g_den[(size_t)(b*HH + h)*SS + c*CHK + t] = den;
}

// ================= pass2b: intra-chunk + normalize; emits att hi/lo =================
#define P2B_SMEM ((128*17*2 + 128*64 + 128*129 + 128) * 4)
__global__ __launch_bounds__(256) void pass2b_kernel()
{
    extern __shared__ float sm[];
    float* qs  = sm;
    float* ksm = qs + 128*17;
    float* vsm = ksm + 128*17;
    float* Am  = vsm + 128*64;
    float* rs  = Am + 128*129;
    const int c = blockIdx.x, h = blockIdx.y, b = blockIdx.z;
    const int tid = threadIdx.x;
    {
        int t = tid >> 1, f0 = (tid & 1) * 8;
        const float* qp = g_qkv + (size_t)(b*SS + c*CHK + t)*QKVW + h*FF + f0;
        const float* kp = qp + OFF_K;
        float4 a = *(const float4*)qp;  float4 a2 = *(const float4*)(qp + 4);
        float4 kk = *(const float4*)kp; float4 k2 = *(const float4*)(kp + 4);
        qs[t*17+f0+0]=a.x;  qs[t*17+f0+1]=a.y;  qs[t*17+f0+2]=a.z;  qs[t*17+f0+3]=a.w;
        qs[t*17+f0+4]=a2.x; qs[t*17+f0+5]=a2.y; qs[t*17+f0+6]=a2.z; qs[t*17+f0+7]=a2.w;
        ksm[t*17+f0+0]=kk.x; ksm[t*17+f0+1]=kk.y; ksm[t*17+f0+2]=kk.z; ksm[t*17+f0+3]=kk.w;
        ksm[t*17+f0+4]=k2.x; ksm[t*17+f0+5]=k2.y; ksm[t*17+f0+6]=k2.z; ksm[t*17+f0+7]=k2.w;
    }
    for (int idx = tid; idx < CHK*16; idx += 256) {
        int t = idx >> 4, d4 = (idx & 15) * 4;
        *(float4*)&vsm[t*64 + d4] =
            *(const float4*)(g_qkv + (size_t)(b*SS + c*CHK + t)*QKVW + OFF_V + h*HD + d4);
    }
    __syncthreads();

    {
        const int t = tid >> 1, u0 = (tid & 1) * 64;
        float qreg[16];
#pragma unroll
        for (int f = 0; f < 16; f++) qreg[f] = qs[t*17+f];
        float rsum = 0.f;
        for (int uu = 0; uu < 64; uu++) {
            int u = u0 + uu;
            float s = 0.f;
#pragma unroll
            for (int f = 0; f < 16; f++)
                s = fmaf(qreg[f], ksm[u*17+f], s);
            float a = (u <= t) ? fmaf(s, fmaf(s, 0.03125f, 0.25f), 1.0f) : 0.f;
            Am[t*129 + u] = a;
            rsum += a;
        }
        rsum += __shfl_xor_sync(0xffffffffu, rsum, 1);
        if ((tid & 1) == 0) rs[t] = rsum;
    }
    __syncthreads();

    {
        const int t = tid >> 1, d0 = (tid & 1) * 32;
        float4 acc[8];
#pragma unroll
        for (int g = 0; g < 8; g++) acc[g] = make_float4(0.f,0.f,0.f,0.f);
        const int tmax = (tid >> 5) * 16 + 15;
        for (int u = 0; u <= tmax; u++) {
            float a = Am[t*129 + u];
            const float4* vr = (const float4*)&vsm[u*64 + d0];
#pragma unroll
            for (int g = 0; g < 8; g++) {
                float4 vv = vr[g];
                acc[g].x = fmaf(a, vv.x, acc[g].x);
                acc[g].y = fmaf(a, vv.y, acc[g].y);
                acc[g].z = fmaf(a, vv.z, acc[g].z);
                acc[g].w = fmaf(a, vv.w, acc[g].w);
            }
        }
        float den = rs[t] + g_den[(size_t)(b*HH + h)*SS + c*CHK + t] + 1e-6f;
        float inv = 1.0f / den;
        const size_t obase = (size_t)(b*SS + c*CHK + t)*VDIM + h*HD + d0;
        const float* ip = g_att + obase;
#pragma unroll
        for (int g = 0; g < 8; g++) {
            float4 cur = *(const float4*)(ip + g*4);
            float4 r;
            r.x = (cur.x + acc[g].x) * inv;
            r.y = (cur.y + acc[g].y) * inv;
            r.z = (cur.z + acc[g].z) * inv;
            r.w = (cur.w + acc[g].w) * inv;
            __nv_bfloat16 h0 = __float2bfloat16(r.x), h1 = __float2bfloat16(r.y);
            __nv_bfloat16 h2 = __float2bfloat16(r.z), h3 = __float2bfloat16(r.w);
            __nv_bfloat162 ph0 = __halves2bfloat162(h0, h1);
            __nv_bfloat162 ph1 = __halves2bfloat162(h2, h3);
            __nv_bfloat162 pl0 = __halves2bfloat162(__float2bfloat16(r.x - __bfloat162float(h0)),
                                                    __float2bfloat16(r.y - __bfloat162float(h1)));
            __nv_bfloat162 pl1 = __halves2bfloat162(__float2bfloat16(r.z - __bfloat162float(h2)),
                                                    __float2bfloat16(r.w - __bfloat162float(h3)));
            *(__nv_bfloat162*)(g_xhi + obase + g*4)     = ph0;
            *(__nv_bfloat162*)(g_xhi + obase + g*4 + 2) = ph1;
            *(__nv_bfloat162*)(g_xlo + obase + g*4)     = pl0;
            *(__nv_bfloat162*)(g_xlo + obase + g*4 + 2) = pl1;
        }
    }
}

extern "C" void kernel_launch(void* const* d_in, const int* in_sizes, int n_in,
                              void* d_out, int out_size)
{
    (void)in_sizes; (void)n_in;
    const float* x    = (const float*)d_in[0];
    const float* kv0  = (const float*)d_in[1];
    const float* kst0 = (const float*)d_in[2];
    const float* Wq   = (const float*)d_in[3];
    const float* bq   = (const float*)d_in[4];
    const float* Wk   = (const float*)d_in[5];
    const float* bk   = (const float*)d_in[6];
    const float* Wv   = (const float*)d_in[7];
    const float* bv   = (const float*)d_in[8];
    const float* Wo   = (const float*)d_in[9];
    const float* bo   = (const float*)d_in[10];

    float* y = (float*)d_out;
    float* kvf = nullptr;
    float* kstf = nullptr;
    if (out_size >= Y_ELEMS + KV_ELEMS + KST_ELEMS) {
        kvf  = y + Y_ELEMS;
        kstf = kvf + KV_ELEMS;
    }

    float *pqkv, *pbqkv;
    __nv_bfloat16 *xhi, *xlo, *wqh, *wql, *woh, *wol;
    cudaGetSymbolAddress((void**)&pqkv,  g_qkv);
    cudaGetSymbolAddress((void**)&pbqkv, g_bqkv);
    cudaGetSymbolAddress((void**)&xhi, g_xhi);
    cudaGetSymbolAddress((void**)&xlo, g_xlo);
    cudaGetSymbolAddress((void**)&wqh, g_wqh);
    cudaGetSymbolAddress((void**)&wql, g_wql);
    cudaGetSymbolAddress((void**)&woh, g_woh);
    cudaGetSymbolAddress((void**)&wol, g_wol);

    cudaFuncSetAttribute(gemm_bf16, cudaFuncAttributeMaxDynamicSharedMemorySize, GS_SMEM);
    cudaFuncSetAttribute(pass2a_kernel, cudaFuncAttributeMaxDynamicSharedMemorySize, P2A_SMEM);
    cudaFuncSetAttribute(pass2b_kernel, cudaFuncAttributeMaxDynamicSharedMemorySize, P2B_SMEM);

    const int M = BB * SS;  // 8192

    // 0: split x (+ bias concat in tail block)
    cvt_split<<<(M * DM) / 1024 + 1, 256>>>(x, xhi, xlo, M * DM, bq, bk, bv, pbqkv);
    // 1: all weight transposes+splits
    cvt_wT_all<<<dim3(32, 32, 4), 256>>>(Wq, Wk, Wv, Wo, wqh, wql, woh, wol);
    // 2: fused QKV projection
    gemm_bf16<<<dim3(QKVW/64, M/128), 256, GS_SMEM>>>(xhi, xlo, wqh, wql, pbqkv, pqkv, QKVW, DM);
    // 3-6: epilogue passes
    pass1_kernel<<<dim3(NC, HH, BB), 256>>>();
    prefix_kernel<<<dim3(HH, BB), 256>>>(kv0, kst0, kvf, kstf);
    pass2a_kernel<<<dim3(NC, HH, BB), 256, P2A_SMEM>>>();
    pass2b_kernel<<<dim3(NC, HH, BB), 256, P2B_SMEM>>>();   // att -> xhi/xlo
    // 7: output projection
    gemm_bf16<<<dim3(DM/64, M/128), 256, GS_SMEM>>>(xhi, xlo, woh, wol, bo, y, DM, VDIM);
}

// round 11
// speedup vs baseline: 1.6128x; 1.0823x over previous
#include <cuda_runtime.h>
#include <cuda_bf16.h>
#include <cstdint>

#define BB 4
#define SS 2048
#define DM 1024
#define HH 16
#define FF 16
#define HD 64
#define EXPD 273
#define NC 16
#define CHK 128
#define QKDIM (HH*FF)
#define VDIM  (HH*HD)
#define QKVW  1536
#define OFF_K 256
#define OFF_V 512
#define C2 0.17677669529663687f

#define Y_ELEMS   (BB*SS*DM)
#define KV_ELEMS  (BB*HH*EXPD*HD)
#define KST_ELEMS (BB*HH*EXPD)

__device__ float g_qkv[BB*SS*QKVW];
__device__ float g_S[BB*HH*NC*EXPD*HD];
__device__ float g_z[BB*HH*NC*EXPD];
__device__ float g_den[BB*HH*SS];
__device__ float g_att[BB*SS*VDIM];
__device__ float g_bqkv[QKVW];
__device__ __nv_bfloat16 g_xhi[BB*SS*DM];
__device__ __nv_bfloat16 g_xlo[BB*SS*DM];
__device__ __nv_bfloat16 g_wqh[QKVW*DM];
__device__ __nv_bfloat16 g_wql[QKVW*DM];
__device__ __nv_bfloat16 g_woh[DM*DM];
__device__ __nv_bfloat16 g_wol[DM*DM];

// ---------------- helpers ----------------
__device__ __forceinline__ uint32_t su32(const void* p) {
    uint32_t a;
    asm("{ .reg .u64 t; cvta.to.shared.u64 t, %1; cvt.u32.u64 %0, t; }" : "=r"(a) : "l"(p));
    return a;
}
__device__ __forceinline__ uint32_t swz(uint32_t o) { return o ^ ((o >> 3) & 0x70); }
__device__ __forceinline__ void cpa16(uint32_t s, const void* g) {
    asm volatile("cp.async.cg.shared.global [%0], [%1], 16;" :: "r"(s), "l"(g));
}

#define LDSM4(r0,r1,r2,r3, addr) \
    asm volatile("ldmatrix.sync.aligned.m8n8.x4.shared.b16 {%0,%1,%2,%3}, [%4];" \
                 : "=r"(r0),"=r"(r1),"=r"(r2),"=r"(r3) : "r"(addr))
#define MMA16816(d, a, b) \
    asm volatile("mma.sync.aligned.m16n8k16.row.col.f32.bf16.bf16.f32 " \
                 "{%0,%1,%2,%3},{%4,%5,%6,%7},{%8,%9},{%0,%1,%2,%3};" \
                 : "+f"((d)[0]),"+f"((d)[1]),"+f"((d)[2]),"+f"((d)[3]) \
                 : "r"((a)[0]),"r"((a)[1]),"r"((a)[2]),"r"((a)[3]),"r"((b)[0]),"r"((b)[1]))

// ---------------- conversions ----------------
__global__ void cvt_split(const float* __restrict__ in,
                          __nv_bfloat16* __restrict__ hi,
                          __nv_bfloat16* __restrict__ lo, int n,
                          const float* __restrict__ b0, const float* __restrict__ b1,
                          const float* __restrict__ b2, float* __restrict__ bout)
{
    if (blockIdx.x == gridDim.x - 1) {
        int t = threadIdx.x;
        if (t < QKDIM) { bout[t] = b0[t]; bout[OFF_K + t] = b1[t]; }
        for (int i = t; i < VDIM; i += 256) bout[OFF_V + i] = b2[i];
        return;
    }
    int i = (blockIdx.x * blockDim.x + threadIdx.x) * 4;
    if (i >= n) return;
    float4 v = *(const float4*)(in + i);
    __nv_bfloat16 h0 = __float2bfloat16(v.x), h1 = __float2bfloat16(v.y);
    __nv_bfloat16 h2 = __float2bfloat16(v.z), h3 = __float2bfloat16(v.w);
    __nv_bfloat162 ph0 = __halves2bfloat162(h0, h1);
    __nv_bfloat162 ph1 = __halves2bfloat162(h2, h3);
    __nv_bfloat162 pl0 = __halves2bfloat162(__float2bfloat16(v.x - __bfloat162float(h0)),
                                            __float2bfloat16(v.y - __bfloat162float(h1)));
    __nv_bfloat162 pl1 = __halves2bfloat162(__float2bfloat16(v.z - __bfloat162float(h2)),
                                            __float2bfloat16(v.w - __bfloat162float(h3)));
    *(__nv_bfloat162*)(hi + i)     = ph0;
    *(__nv_bfloat162*)(hi + i + 2) = ph1;
    *(__nv_bfloat162*)(lo + i)     = pl0;
    *(__nv_bfloat162*)(lo + i + 2) = pl1;
}

__global__ void cvt_wT_all(const float* __restrict__ Wq, const float* __restrict__ Wk,
                           const float* __restrict__ Wv, const float* __restrict__ Wo,
                           __nv_bfloat16* __restrict__ qh, __nv_bfloat16* __restrict__ ql,
                           __nv_bfloat16* __restrict__ oh, __nv_bfloat16* __restrict__ ol)
{
    __shared__ float t[32][33];
    const int z = blockIdx.z;
    const float* W; __nv_bfloat16 *Th, *Tl; int N, rowoff;
    if (z == 0)      { W = Wq; Th = qh; Tl = ql; N = QKDIM; rowoff = 0; }
    else if (z == 1) { W = Wk; Th = qh; Tl = ql; N = QKDIM; rowoff = OFF_K; }
    else if (z == 2) { W = Wv; Th = qh; Tl = ql; N = VDIM;  rowoff = OFF_V; }
    else             { W = Wo; Th = oh; Tl = ol; N = DM;    rowoff = 0; }
    const int bx = blockIdx.x * 32, by = blockIdx.y * 32;
    if (bx >= N) return;
    const int tx = threadIdx.x & 31, ty = threadIdx.x >> 5;
#pragma unroll
    for (int r = 0; r < 4; r++)
        t[ty + 8 * r][tx] = W[(size_t)(by + ty + 8 * r) * N + bx + tx];
    __syncthreads();
#pragma unroll
    for (int r = 0; r < 4; r++) {
        float v = t[tx][ty + 8 * r];
        __nv_bfloat16 h = __float2bfloat16(v);
        size_t o = (size_t)(rowoff + bx + ty + 8 * r) * DM + by + tx;
        Th[o] = h;
        Tl[o] = __float2bfloat16(v - __bfloat162float(h));
    }
}

// ---------------- bf16 split GEMM, cp.async pipeline (unchanged from R10) ----------------
#define STG 49152
#define GS_SMEM (2*STG)

#define ISSUE_STAGE(k0, b_) do { \
    uint32_t pa_h = sbase + (b_) * STG; \
    uint32_t pa_l = pa_h + 16384; \
    uint32_t pb_h = pa_h + 32768; \
    uint32_t pb_l = pa_h + 40960; \
    const __nv_bfloat16* aph = Ah + (size_t)(bm + arow) * K + (k0) + acol; \
    const __nv_bfloat16* apl = Al + (size_t)(bm + arow) * K + (k0) + acol; \
    _Pragma("unroll") for (int j = 0; j < 4; j++) { \
        uint32_t off = swz(arow * 128 + acol * 2 + j * 16); \
        cpa16(pa_h + off, aph + j * 8); \
        cpa16(pa_l + off, apl + j * 8); } \
    const __nv_bfloat16* bph = Bh + (size_t)(bn + brow) * K + (k0) + bcol; \
    const __nv_bfloat16* bpl = Bl + (size_t)(bn + brow) * K + (k0) + bcol; \
    _Pragma("unroll") for (int j = 0; j < 2; j++) { \
        uint32_t off = swz(brow * 128 + bcol * 2 + j * 16); \
        cpa16(pb_h + off, bph + j * 8); \
        cpa16(pb_l + off, bpl + j * 8); } \
    asm volatile("cp.async.commit_group;" ::: "memory"); \
} while (0)

__global__ __launch_bounds__(256, 2) void gemm_bf16(
    const __nv_bfloat16* __restrict__ Ah, const __nv_bfloat16* __restrict__ Al,
    const __nv_bfloat16* __restrict__ Bh, const __nv_bfloat16* __restrict__ Bl,
    const float* __restrict__ bias, float* __restrict__ C, int N, int K)
{
    extern __shared__ char smn[];
    const int tid = threadIdx.x, l = tid & 31, w = tid >> 5;
    const int bm = blockIdx.y * 128, bn = blockIdx.x * 64;
    const int wm = (w >> 1) * 32, wn = (w & 1) * 32;
    const uint32_t sbase = su32(smn);

    const int arow = tid >> 1, acol = (tid & 1) * 32;
    const int brow = tid >> 2, bcol = (tid & 3) * 16;

    float acc[2][4][4] = {};
    const int nstep = K / 64;

    ISSUE_STAGE(0, 0);
    int buf = 0;
    for (int s = 0; s < nstep; s++) {
        if (s + 1 < nstep) {
            ISSUE_STAGE((s + 1) * 64, buf ^ 1);
            asm volatile("cp.async.wait_group 1;" ::: "memory");
        } else {
            asm volatile("cp.async.wait_group 0;" ::: "memory");
        }
        __syncthreads();
        uint32_t base_ah = sbase + buf * STG;
        uint32_t base_al = base_ah + 16384;
        uint32_t base_bh = base_ah + 32768;
        uint32_t base_bl = base_ah + 40960;
#pragma unroll
        for (int kc = 0; kc < 4; kc++) {
            uint32_t fah[2][4], fal[2][4], fbh[4][2], fbl[4][2];
#pragma unroll
            for (int mt = 0; mt < 2; mt++) {
                uint32_t off = swz((wm + mt * 16 + (l & 15)) * 128 + kc * 32 + (l >> 4) * 16);
                LDSM4(fah[mt][0], fah[mt][1], fah[mt][2], fah[mt][3], base_ah + off);
                LDSM4(fal[mt][0], fal[mt][1], fal[mt][2], fal[mt][3], base_al + off);
            }
#pragma unroll
            for (int np = 0; np < 2; np++) {
                uint32_t off = swz((wn + np * 16 + (l & 7) + ((l >> 4) & 1) * 8) * 128
                                   + kc * 32 + ((l >> 3) & 1) * 16);
                LDSM4(fbh[np*2][0], fbh[np*2][1], fbh[np*2+1][0], fbh[np*2+1][1], base_bh + off);
                LDSM4(fbl[np*2][0], fbl[np*2][1], fbl[np*2+1][0], fbl[np*2+1][1], base_bl + off);
            }
#pragma unroll
            for (int mt = 0; mt < 2; mt++)
#pragma unroll
                for (int nt = 0; nt < 4; nt++) {
                    MMA16816(acc[mt][nt], fah[mt], fbh[nt]);
                    MMA16816(acc[mt][nt], fah[mt], fbl[nt]);
                    MMA16816(acc[mt][nt], fal[mt], fbh[nt]);
                }
        }
        __syncthreads();
        buf ^= 1;
    }

    const int gr = l >> 2, tc = l & 3;
#pragma unroll
    for (int mt = 0; mt < 2; mt++)
#pragma unroll
        for (int nt = 0; nt < 4; nt++) {
            int m = bm + wm + mt * 16 + gr;
            int n = bn + wn + nt * 8 + tc * 2;
            float2 bv = *(const float2*)(bias + n);
            float2 o0 = make_float2(acc[mt][nt][0] + bv.x, acc[mt][nt][1] + bv.y);
            float2 o1 = make_float2(acc[mt][nt][2] + bv.x, acc[mt][nt][3] + bv.y);
            *(float2*)(C + (size_t)m * N + n) = o0;
            *(float2*)(C + (size_t)(m + 8) * N + n) = o1;
        }
}

// ================= pass1 via mma.sync =================
// smem: kraw[128][18] f32 | A_hi[384][72] bf16 | A_lo | B_hi[64][72] bf16 | B_lo
#define P1_SMEM 138240
__global__ __launch_bounds__(512, 1) void pass1_kernel()
{
    extern __shared__ char sm1[];
    float* kraw = (float*)sm1;
    __nv_bfloat16* Ah = (__nv_bfloat16*)(sm1 + 9216);
    __nv_bfloat16* Al = (__nv_bfloat16*)(sm1 + 64512);
    __nv_bfloat16* Bh = (__nv_bfloat16*)(sm1 + 119808);
    __nv_bfloat16* Bl = (__nv_bfloat16*)(sm1 + 129024);
    const int c = blockIdx.x, h = blockIdx.y, b = blockIdx.z;
    const int tid = threadIdx.x, l = tid & 31, w = tid >> 5;
    const int wm_g = w & 3, wn_g = w >> 2;

    if (tid < 256) {
        int t = tid >> 1, f0 = (tid & 1) * 8;
        const float* kp = g_qkv + (size_t)(b*SS + c*CHK + t)*QKVW + OFF_K + h*FF + f0;
        float4 k0 = *(const float4*)kp, k1 = *(const float4*)(kp + 4);
        kraw[t*18+f0+0]=k0.x; kraw[t*18+f0+1]=k0.y; kraw[t*18+f0+2]=k0.z; kraw[t*18+f0+3]=k0.w;
        kraw[t*18+f0+4]=k1.x; kraw[t*18+f0+5]=k1.y; kraw[t*18+f0+6]=k1.z; kraw[t*18+f0+7]=k1.w;
    }
    {
        uint4 z4 = make_uint4(0,0,0,0);
        uint4* az = (uint4*)(sm1 + 9216);     // zero A_hi + A_lo (110592 B)
        for (int i = tid; i < 6912; i += 512) az[i] = z4;
    }
    __syncthreads();

    // z = column sums of Phi (from raw k)
    const size_t zbase = ((size_t)((b*HH + h)*NC + c)) * EXPD;
    if (tid < EXPD) {
        int e = tid;
        float s = 0.f;
        if (e == 0) s = (float)CHK;
        else if (e < 17) {
            for (int t = 0; t < CHK; t++) s += kraw[t*18 + e - 1];
            s *= 0.5f;
        } else {
            int p = e - 17, i = p >> 4, j = p & 15;
            for (int t = 0; t < CHK; t++) s += kraw[t*18 + i] * kraw[t*18 + j];
            s *= C2;
        }
        g_z[zbase + e] = s;
    }

    float acc[6][2][4] = {};

    for (int kc = 0; kc < 2; kc++) {
        const int T0 = kc * 64;
        if (kc) __syncthreads();
        // build Phi chunk [e][tt]
        for (int idx = tid; idx < 288*64; idx += 512) {
            int e = idx >> 6, tt = idx & 63;
            if (e < EXPD) {
                float phi;
                if (e == 0) phi = 1.0f;
                else if (e < 17) phi = 0.5f * kraw[(T0+tt)*18 + e - 1];
                else {
                    int p = e - 17;
                    phi = C2 * kraw[(T0+tt)*18 + (p >> 4)] * kraw[(T0+tt)*18 + (p & 15)];
                }
                __nv_bfloat16 hh = __float2bfloat16(phi);
                Ah[e*72 + tt] = hh;
                Al[e*72 + tt] = __float2bfloat16(phi - __bfloat162float(hh));
            }
        }
        // build B = V^T chunk [d][tt]
        for (int idx = tid; idx < 64*16; idx += 512) {
            int tt = idx >> 4, d4 = (idx & 15) * 4;
            float4 v = *(const float4*)(g_qkv + (size_t)(b*SS + c*CHK + T0 + tt)*QKVW + OFF_V + h*HD + d4);
            float e4[4] = {v.x, v.y, v.z, v.w};
#pragma unroll
            for (int q2 = 0; q2 < 4; q2++) {
                __nv_bfloat16 hh = __float2bfloat16(e4[q2]);
                Bh[(d4+q2)*72 + tt] = hh;
                Bl[(d4+q2)*72 + tt] = __float2bfloat16(e4[q2] - __bfloat162float(hh));
            }
        }
        __syncthreads();
        // mma over this chunk (K = 64 tokens, 4 k-tiles)
        uint32_t bAh = su32(Ah), bAl = su32(Al), bBh = su32(Bh), bBl = su32(Bl);
#pragma unroll
        for (int kt = 0; kt < 4; kt++) {
            uint32_t fbh[2][2], fbl[2][2];
            {
                uint32_t off = (wn_g*16 + (l & 7) + ((l >> 4) & 1) * 8) * 144
                             + kt * 32 + ((l >> 3) & 1) * 16;
                LDSM4(fbh[0][0], fbh[0][1], fbh[1][0], fbh[1][1], bBh + off);
                LDSM4(fbl[0][0], fbl[0][1], fbl[1][0], fbl[1][1], bBl + off);
            }
#pragma unroll
            for (int i = 0; i < 6; i++) {
                uint32_t fa_h[4], fa_l[4];
                uint32_t off = ((wm_g*6 + i)*16 + (l & 15)) * 144 + kt * 32 + (l >> 4) * 16;
                LDSM4(fa_h[0], fa_h[1], fa_h[2], fa_h[3], bAh + off);
                LDSM4(fa_l[0], fa_l[1], fa_l[2], fa_l[3], bAl + off);
#pragma unroll
                for (int j = 0; j < 2; j++) {
                    MMA16816(acc[i][j], fa_h, fbh[j]);
                    MMA16816(acc[i][j], fa_h, fbl[j]);
                    MMA16816(acc[i][j], fa_l, fbh[j]);
                }
            }
        }
    }

    const size_t Sbase = ((size_t)((b*HH + h)*NC + c)) * EXPD * HD;
    const int gr = l >> 2, tc = l & 3;
#pragma unroll
    for (int i = 0; i < 6; i++) {
        int e0 = (wm_g*6 + i) * 16;
#pragma unroll
        for (int j = 0; j < 2; j++) {
            int d = (wn_g*2 + j)*8 + tc*2;
            int e1 = e0 + gr, e2 = e0 + 8 + gr;
            if (e1 < EXPD)
                *(float2*)(g_S + Sbase + (size_t)e1*HD + d) = make_float2(acc[i][j][0], acc[i][j][1]);
            if (e2 < EXPD)
                *(float2*)(g_S + Sbase + (size_t)e2*HD + d) = make_float2(acc[i][j][2], acc[i][j][3]);
        }
    }
}

// ================= prefix (8-way segment split) =================
__global__ __launch_bounds__(256) void prefix_kernel(
    const float* __restrict__ kv0, const float* __restrict__ kst0,
    float* __restrict__ out_kv, float* __restrict__ out_kst)
{
    const int h = blockIdx.x, b = blockIdx.y, seg = blockIdx.z;
    const int pair = b*HH + h;
    const int tid = threadIdx.x;
    const int seglen = EXPD*HD/8;    // 2184
    for (int idx = seg*seglen + tid; idx < (seg+1)*seglen; idx += 256) {
        float run = kv0[(size_t)pair*EXPD*HD + idx];
        float* p = g_S + ((size_t)pair*NC)*EXPD*HD + idx;
#pragma unroll
        for (int cc = 0; cc < NC; cc++) {
            float sv = p[(size_t)cc*EXPD*HD];
            p[(size_t)cc*EXPD*HD] = run;
            run += sv;
        }
        if (out_kv) out_kv[(size_t)pair*EXPD*HD + idx] = run;
    }
    if (seg == 0) {
        for (int idx = tid; idx < EXPD; idx += 256) {
            float run = kst0[(size_t)pair*EXPD + idx];
            float* p = g_z + ((size_t)pair*NC)*EXPD + idx;
#pragma unroll
            for (int cc = 0; cc < NC; cc++) {
                float sv = p[(size_t)cc*EXPD];
                p[(size_t)cc*EXPD] = run;
                run += sv;
            }
            if (out_kst) out_kst[(size_t)pair*EXPD + idx] = run;
        }
    }
}

// ================= pass2a =================
#define P2A_SMEM ((128*18 + 128*274 + 280 + 16*64) * 4)
__global__ __launch_bounds__(256) void pass2a_kernel()
{
    extern __shared__ float sm[];
    float* qs  = sm;
    float* Phi = sm + 128*18;
    float* zs  = Phi + 128*274;
    float* kvt = zs + 280;
    const int c = blockIdx.x, h = blockIdx.y, b = blockIdx.z;
    const int tid = threadIdx.x;
    {
        int t = tid >> 1, f0 = (tid & 1) * 8;
        const float* qp = g_qkv + (size_t)(b*SS + c*CHK + t)*QKVW + h*FF + f0;
        float4 a = *(const float4*)qp;
        float4 b4 = *(const float4*)(qp + 4);
        qs[t*18+f0+0]=a.x;  qs[t*18+f0+1]=a.y;  qs[t*18+f0+2]=a.z;  qs[t*18+f0+3]=a.w;
        qs[t*18+f0+4]=b4.x; qs[t*18+f0+5]=b4.y; qs[t*18+f0+6]=b4.z; qs[t*18+f0+7]=b4.w;
        if (f0 == 0) qs[t*18+16] = 1.0f;
    }
    __syncthreads();
    {
        int w = tid >> 5, lane = tid & 31;
        for (int tt = w*16; tt < w*16 + 16; tt++) {
            for (int e = lane; e < EXPD; e += 32) {
                int i, j; float cfv;
                if (e == 0)      { i=16; j=16; cfv=1.f; }
                else if (e < 17) { i=e-1; j=16; cfv=0.5f; }
                else { int p = e-17; i=p>>4; j=p&15; cfv=C2; }
                Phi[tt*274 + e] = qs[tt*18+i] * qs[tt*18+j] * cfv;
            }
        }
        for (int e = tid; e < EXPD; e += 256)
            zs[e] = g_z[((size_t)((b*HH + h)*NC + c))*EXPD + e];
    }
    __syncthreads();

    const int t = tid >> 1, d0 = (tid & 1) * 32;
    const int t274 = t * 274;
    float4 acc[8];
#pragma unroll
    for (int g = 0; g < 8; g++) acc[g] = make_float4(0.f,0.f,0.f,0.f);
    float den = 0.f;
    const size_t Sbase = ((size_t)((b*HH + h)*NC + c)) * EXPD * HD;

    for (int e0 = 0; e0 < EXPD; e0 += 16) {
        int ne = EXPD - e0; if (ne > 16) ne = 16;
        __syncthreads();
        for (int idx = tid; idx < ne*64; idx += 256)
            kvt[idx] = g_S[Sbase + (size_t)e0*64 + idx];
        __syncthreads();
        for (int ee = 0; ee < ne; ee++) {
            float ph = Phi[t274 + e0 + ee];
            den = fmaf(ph, zs[e0 + ee], den);
            const float4* kr = (const float4*)(kvt + ee*64 + d0);
#pragma unroll
            for (int g = 0; g < 8; g++) {
                float4 kv4 = kr[g];
                acc[g].x = fmaf(ph, kv4.x, acc[g].x);
                acc[g].y = fmaf(ph, kv4.y, acc[g].y);
                acc[g].z = fmaf(ph, kv4.z, acc[g].z);
                acc[g].w = fmaf(ph, kv4.w, acc[g].w);
            }
        }
    }
    float* op = g_att + (size_t)(b*SS + c*CHK + t)*VDIM + h*HD + d0;
#pragma unroll
    for (int g = 0; g < 8; g++) *(float4*)(op + g*4) = acc[g];
    if ((tid & 1) == 0)
        g_den[(size_t)(b*HH + h)*SS + c*CHK + t] = den;
}

// ================= pass2b =================
#define P2B_SMEM ((128*17*2 + 128*64 + 128*129 + 128) * 4)
__global__ __launch_bounds__(256) void pass2b_kernel()
{
    extern __shared__ float sm[];
    float* qs  = sm;
    float* ksm = qs + 128*17;
    float* vsm = ksm + 128*17;
    float* Am  = vsm + 128*64;
    float* rs  = Am + 128*129;
    const int c = blockIdx.x, h = blockIdx.y, b = blockIdx.z;
    const int tid = threadIdx.x;
    {
        int t = tid >> 1, f0 = (tid & 1) * 8;
        const float* qp = g_qkv + (size_t)(b*SS + c*CHK + t)*QKVW + h*FF + f0;
        const float* kp = qp + OFF_K;
        float4 a = *(const float4*)qp;  float4 a2 = *(const float4*)(qp + 4);
        float4 kk = *(const float4*)kp; float4 k2 = *(const float4*)(kp + 4);
        qs[t*17+f0+0]=a.x;  qs[t*17+f0+1]=a.y;  qs[t*17+f0+2]=a.z;  qs[t*17+f0+3]=a.w;
        qs[t*17+f0+4]=a2.x; qs[t*17+f0+5]=a2.y; qs[t*17+f0+6]=a2.z; qs[t*17+f0+7]=a2.w;
        ksm[t*17+f0+0]=kk.x; ksm[t*17+f0+1]=kk.y; ksm[t*17+f0+2]=kk.z; ksm[t*17+f0+3]=kk.w;
        ksm[t*17+f0+4]=k2.x; ksm[t*17+f0+5]=k2.y; ksm[t*17+f0+6]=k2.z; ksm[t*17+f0+7]=k2.w;
    }
    for (int idx = tid; idx < CHK*16; idx += 256) {
        int t = idx >> 4, d4 = (idx & 15) * 4;
        *(float4*)&vsm[t*64 + d4] =
            *(const float4*)(g_qkv + (size_t)(b*SS + c*CHK + t)*QKVW + OFF_V + h*HD + d4);
    }
    __syncthreads();

    {
        const int t = tid >> 1, u0 = (tid & 1) * 64;
        float qreg[16];
#pragma unroll
        for (int f = 0; f < 16; f++) qreg[f] = qs[t*17+f];
        float rsum = 0.f;
        for (int uu = 0; uu < 64; uu++) {
            int u = u0 + uu;
            float s = 0.f;
#pragma unroll
            for (int f = 0; f < 16; f++)
                s = fmaf(qreg[f], ksm[u*17+f], s);
            float a = (u <= t) ? fmaf(s, fmaf(s, 0.03125f, 0.25f), 1.0f) : 0.f;
            Am[t*129 + u] = a;
            rsum += a;
        }
        rsum += __shfl_xor_sync(0xffffffffu, rsum, 1);
        if ((tid & 1) == 0) rs[t] = rsum;
    }
    __syncthreads();

    {
        const int t = tid >> 1, d0 = (tid & 1) * 32;
        float4 acc[8];
#pragma unroll
        for (int g = 0; g < 8; g++) acc[g] = make_float4(0.f,0.f,0.f,0.f);
        const int tmax = (tid >> 5) * 16 + 15;
        for (int u = 0; u <= tmax; u++) {
            float a = Am[t*129 + u];
            const float4* vr = (const float4*)&vsm[u*64 + d0];
#pragma unroll
            for (int g = 0; g < 8; g++) {
                float4 vv = vr[g];
                acc[g].x = fmaf(a, vv.x, acc[g].x);
                acc[g].y = fmaf(a, vv.y, acc[g].y);
                acc[g].z = fmaf(a, vv.z, acc[g].z);
                acc[g].w = fmaf(a, vv.w, acc[g].w);
            }
        }
        float den = rs[t] + g_den[(size_t)(b*HH + h)*SS + c*CHK + t] + 1e-6f;
        float inv = 1.0f / den;
        const size_t obase = (size_t)(b*SS + c*CHK + t)*VDIM + h*HD + d0;
        const float* ip = g_att + obase;
#pragma unroll
        for (int g = 0; g < 8; g++) {
            float4 cur = *(const float4*)(ip + g*4);
            float4 r;
            r.x = (cur.x + acc[g].x) * inv;
            r.y = (cur.y + acc[g].y) * inv;
            r.z = (cur.z + acc[g].z) * inv;
            r.w = (cur.w + acc[g].w) * inv;
            __nv_bfloat16 h0 = __float2bfloat16(r.x), h1 = __float2bfloat16(r.y);
            __nv_bfloat16 h2 = __float2bfloat16(r.z), h3 = __float2bfloat16(r.w);
            __nv_bfloat162 ph0 = __halves2bfloat162(h0, h1);
            __nv_bfloat162 ph1 = __halves2bfloat162(h2, h3);
            __nv_bfloat162 pl0 = __halves2bfloat162(__float2bfloat16(r.x - __bfloat162float(h0)),
                                                    __float2bfloat16(r.y - __bfloat162float(h1)));
            __nv_bfloat162 pl1 = __halves2bfloat162(__float2bfloat16(r.z - __bfloat162float(h2)),
                                                    __float2bfloat16(r.w - __bfloat162float(h3)));
            *(__nv_bfloat162*)(g_xhi + obase + g*4)     = ph0;
            *(__nv_bfloat162*)(g_xhi + obase + g*4 + 2) = ph1;
            *(__nv_bfloat162*)(g_xlo + obase + g*4)     = pl0;
            *(__nv_bfloat162*)(g_xlo + obase + g*4 + 2) = pl1;
        }
    }
}

extern "C" void kernel_launch(void* const* d_in, const int* in_sizes, int n_in,
                              void* d_out, int out_size)
{
    (void)in_sizes; (void)n_in;
    const float* x    = (const float*)d_in[0];
    const float* kv0  = (const float*)d_in[1];
    const float* kst0 = (const float*)d_in[2];
    const float* Wq   = (const float*)d_in[3];
    const float* bq   = (const float*)d_in[4];
    const float* Wk   = (const float*)d_in[5];
    const float* bk   = (const float*)d_in[6];
    const float* Wv   = (const float*)d_in[7];
    const float* bv   = (const float*)d_in[8];
    const float* Wo   = (const float*)d_in[9];
    const float* bo   = (const float*)d_in[10];

    float* y = (float*)d_out;
    float* kvf = nullptr;
    float* kstf = nullptr;
    if (out_size >= Y_ELEMS + KV_ELEMS + KST_ELEMS) {
        kvf  = y + Y_ELEMS;
        kstf = kvf + KV_ELEMS;
    }

    float *pqkv, *pbqkv;
    __nv_bfloat16 *xhi, *xlo, *wqh, *wql, *woh, *wol;
    cudaGetSymbolAddress((void**)&pqkv,  g_qkv);
    cudaGetSymbolAddress((void**)&pbqkv, g_bqkv);
    cudaGetSymbolAddress((void**)&xhi, g_xhi);
    cudaGetSymbolAddress((void**)&xlo, g_xlo);
    cudaGetSymbolAddress((void**)&wqh, g_wqh);
    cudaGetSymbolAddress((void**)&wql, g_wql);
    cudaGetSymbolAddress((void**)&woh, g_woh);
    cudaGetSymbolAddress((void**)&wol, g_wol);

    cudaFuncSetAttribute(gemm_bf16, cudaFuncAttributeMaxDynamicSharedMemorySize, GS_SMEM);
    cudaFuncSetAttribute(pass1_kernel, cudaFuncAttributeMaxDynamicSharedMemorySize, P1_SMEM);
    cudaFuncSetAttribute(pass2a_kernel, cudaFuncAttributeMaxDynamicSharedMemorySize, P2A_SMEM);
    cudaFuncSetAttribute(pass2b_kernel, cudaFuncAttributeMaxDynamicSharedMemorySize, P2B_SMEM);

    const int M = BB * SS;  // 8192

    cvt_split<<<(M * DM) / 1024 + 1, 256>>>(x, xhi, xlo, M * DM, bq, bk, bv, pbqkv);
    cvt_wT_all<<<dim3(32, 32, 4), 256>>>(Wq, Wk, Wv, Wo, wqh, wql, woh, wol);
    gemm_bf16<<<dim3(QKVW/64, M/128), 256, GS_SMEM>>>(xhi, xlo, wqh, wql, pbqkv, pqkv, QKVW, DM);

    pass1_kernel<<<dim3(NC, HH, BB), 512, P1_SMEM>>>();
    prefix_kernel<<<dim3(HH, BB, 8), 256>>>(kv0, kst0, kvf, kstf);
    pass2a_kernel<<<dim3(NC, HH, BB), 256, P2A_SMEM>>>();
    pass2b_kernel<<<dim3(NC, HH, BB), 256, P2B_SMEM>>>();

    gemm_bf16<<<dim3(DM/64, M/128), 256, GS_SMEM>>>(xhi, xlo, woh, wol, bo, y, DM, VDIM);
}

// round 15
// speedup vs baseline: 2.0861x; 1.2935x over previous
#include <cuda_runtime.h>
#include <cuda_bf16.h>
#include <cstdint>

#define BB 4
#define SS 2048
#define DM 1024
#define HH 16
#define FF 16
#define HD 64
#define EXPD 273
#define NC 16
#define CHK 128
#define QKDIM (HH*FF)
#define VDIM  (HH*HD)
#define QKVW  1536
#define OFF_K 256
#define OFF_V 512
#define C2 0.17677669529663687f

#define Y_ELEMS   (BB*SS*DM)
#define KV_ELEMS  (BB*HH*EXPD*HD)
#define KST_ELEMS (BB*HH*EXPD)

__device__ float g_qkv[BB*SS*QKVW];
__device__ float g_S[BB*HH*NC*EXPD*HD];
__device__ float g_z[BB*HH*NC*EXPD];
__device__ float g_den[BB*HH*SS];
__device__ float g_att[BB*SS*VDIM];
__device__ float g_bqkv[QKVW];
__device__ __nv_bfloat16 g_xhi[BB*SS*DM];
__device__ __nv_bfloat16 g_xlo[BB*SS*DM];
__device__ __nv_bfloat16 g_wqh[QKVW*DM];
__device__ __nv_bfloat16 g_wql[QKVW*DM];
__device__ __nv_bfloat16 g_woh[DM*DM];
__device__ __nv_bfloat16 g_wol[DM*DM];

// ---------------- helpers ----------------
__device__ __forceinline__ uint32_t su32(const void* p) {
    uint32_t a;
    asm("{ .reg .u64 t; cvta.to.shared.u64 t, %1; cvt.u32.u64 %0, t; }" : "=r"(a) : "l"(p));
    return a;
}
__device__ __forceinline__ uint32_t swz(uint32_t o) { return o ^ ((o >> 3) & 0x70); }
__device__ __forceinline__ void cpa16(uint32_t s, const void* g) {
    asm volatile("cp.async.cg.shared.global [%0], [%1], 16;" :: "r"(s), "l"(g));
}

#define LDSM4(r0,r1,r2,r3, addr) \
    asm volatile("ldmatrix.sync.aligned.m8n8.x4.shared.b16 {%0,%1,%2,%3}, [%4];" \
                 : "=r"(r0),"=r"(r1),"=r"(r2),"=r"(r3) : "r"(addr))
#define MMA16816(d, a, b) \
    asm volatile("mma.sync.aligned.m16n8k16.row.col.f32.bf16.bf16.f32 " \
                 "{%0,%1,%2,%3},{%4,%5,%6,%7},{%8,%9},{%0,%1,%2,%3};" \
                 : "+f"((d)[0]),"+f"((d)[1]),"+f"((d)[2]),"+f"((d)[3]) \
                 : "r"((a)[0]),"r"((a)[1]),"r"((a)[2]),"r"((a)[3]),"r"((b)[0]),"r"((b)[1]))

// ---------------- conversions ----------------
__global__ void cvt_split(const float* __restrict__ in,
                          __nv_bfloat16* __restrict__ hi,
                          __nv_bfloat16* __restrict__ lo, int n,
                          const float* __restrict__ b0, const float* __restrict__ b1,
                          const float* __restrict__ b2, float* __restrict__ bout)
{
    if (blockIdx.x == gridDim.x - 1) {
        int t = threadIdx.x;
        if (t < QKDIM) { bout[t] = b0[t]; bout[OFF_K + t] = b1[t]; }
        for (int i = t; i < VDIM; i += 256) bout[OFF_V + i] = b2[i];
        return;
    }
    int i = (blockIdx.x * blockDim.x + threadIdx.x) * 4;
    if (i >= n) return;
    float4 v = *(const float4*)(in + i);
    __nv_bfloat16 h0 = __float2bfloat16(v.x), h1 = __float2bfloat16(v.y);
    __nv_bfloat16 h2 = __float2bfloat16(v.z), h3 = __float2bfloat16(v.w);
    __nv_bfloat162 ph0 = __halves2bfloat162(h0, h1);
    __nv_bfloat162 ph1 = __halves2bfloat162(h2, h3);
    __nv_bfloat162 pl0 = __halves2bfloat162(__float2bfloat16(v.x - __bfloat162float(h0)),
                                            __float2bfloat16(v.y - __bfloat162float(h1)));
    __nv_bfloat162 pl1 = __halves2bfloat162(__float2bfloat16(v.z - __bfloat162float(h2)),
                                            __float2bfloat16(v.w - __bfloat162float(h3)));
    *(__nv_bfloat162*)(hi + i)     = ph0;
    *(__nv_bfloat162*)(hi + i + 2) = ph1;
    *(__nv_bfloat162*)(lo + i)     = pl0;
    *(__nv_bfloat162*)(lo + i + 2) = pl1;
}

__global__ void cvt_wT_all(const float* __restrict__ Wq, const float* __restrict__ Wk,
                           const float* __restrict__ Wv, const float* __restrict__ Wo,
                           __nv_bfloat16* __restrict__ qh, __nv_bfloat16* __restrict__ ql,
                           __nv_bfloat16* __restrict__ oh, __nv_bfloat16* __restrict__ ol)
{
    __shared__ float t[32][33];
    const int z = blockIdx.z;
    const float* W; __nv_bfloat16 *Th, *Tl; int N, rowoff;
    if (z == 0)      { W = Wq; Th = qh; Tl = ql; N = QKDIM; rowoff = 0; }
    else if (z == 1) { W = Wk; Th = qh; Tl = ql; N = QKDIM; rowoff = OFF_K; }
    else if (z == 2) { W = Wv; Th = qh; Tl = ql; N = VDIM;  rowoff = OFF_V; }
    else             { W = Wo; Th = oh; Tl = ol; N = DM;    rowoff = 0; }
    const int bx = blockIdx.x * 32, by = blockIdx.y * 32;
    if (bx >= N) return;
    const int tx = threadIdx.x & 31, ty = threadIdx.x >> 5;
#pragma unroll
    for (int r = 0; r < 4; r++)
        t[ty + 8 * r][tx] = W[(size_t)(by + ty + 8 * r) * N + bx + tx];
    __syncthreads();
#pragma unroll
    for (int r = 0; r < 4; r++) {
        float v = t[tx][ty + 8 * r];
        __nv_bfloat16 h = __float2bfloat16(v);
        size_t o = (size_t)(rowoff + bx + ty + 8 * r) * DM + by + tx;
        Th[o] = h;
        Tl[o] = __float2bfloat16(v - __bfloat162float(h));
    }
}

// ---------------- bf16 split GEMM, cp.async pipeline ----------------
#define STG 49152
#define GS_SMEM (2*STG)

#define ISSUE_STAGE(k0, b_) do { \
    uint32_t pa_h = sbase + (b_) * STG; \
    uint32_t pa_l = pa_h + 16384; \
    uint32_t pb_h = pa_h + 32768; \
    uint32_t pb_l = pa_h + 40960; \
    const __nv_bfloat16* aph = Ah + (size_t)(bm + arow) * K + (k0) + acol; \
    const __nv_bfloat16* apl = Al + (size_t)(bm + arow) * K + (k0) + acol; \
    _Pragma("unroll") for (int j = 0; j < 4; j++) { \
        uint32_t off = swz(arow * 128 + acol * 2 + j * 16); \
        cpa16(pa_h + off, aph + j * 8); \
        cpa16(pa_l + off, apl + j * 8); } \
    const __nv_bfloat16* bph = Bh + (size_t)(bn + brow) * K + (k0) + bcol; \
    const __nv_bfloat16* bpl = Bl + (size_t)(bn + brow) * K + (k0) + bcol; \
    _Pragma("unroll") for (int j = 0; j < 2; j++) { \
        uint32_t off = swz(brow * 128 + bcol * 2 + j * 16); \
        cpa16(pb_h + off, bph + j * 8); \
        cpa16(pb_l + off, bpl + j * 8); } \
    asm volatile("cp.async.commit_group;" ::: "memory"); \
} while (0)

__global__ __launch_bounds__(256, 2) void gemm_bf16(
    const __nv_bfloat16* __restrict__ Ah, const __nv_bfloat16* __restrict__ Al,
    const __nv_bfloat16* __restrict__ Bh, const __nv_bfloat16* __restrict__ Bl,
    const float* __restrict__ bias, float* __restrict__ C, int N, int K)
{
    extern __shared__ char smn[];
    const int tid = threadIdx.x, l = tid & 31, w = tid >> 5;
    const int bm = blockIdx.y * 128, bn = blockIdx.x * 64;
    const int wm = (w >> 1) * 32, wn = (w & 1) * 32;
    const uint32_t sbase = su32(smn);

    const int arow = tid >> 1, acol = (tid & 1) * 32;
    const int brow = tid >> 2, bcol = (tid & 3) * 16;

    float acc[2][4][4] = {};
    const int nstep = K / 64;

    ISSUE_STAGE(0, 0);
    int buf = 0;
    for (int s = 0; s < nstep; s++) {
        if (s + 1 < nstep) {
            ISSUE_STAGE((s + 1) * 64, buf ^ 1);
            asm volatile("cp.async.wait_group 1;" ::: "memory");
        } else {
            asm volatile("cp.async.wait_group 0;" ::: "memory");
        }
        __syncthreads();
        uint32_t base_ah = sbase + buf * STG;
        uint32_t base_al = base_ah + 16384;
        uint32_t base_bh = base_ah + 32768;
        uint32_t base_bl = base_ah + 40960;
#pragma unroll
        for (int kc = 0; kc < 4; kc++) {
            uint32_t fah[2][4], fal[2][4], fbh[4][2], fbl[4][2];
#pragma unroll
            for (int mt = 0; mt < 2; mt++) {
                uint32_t off = swz((wm + mt * 16 + (l & 15)) * 128 + kc * 32 + (l >> 4) * 16);
                LDSM4(fah[mt][0], fah[mt][1], fah[mt][2], fah[mt][3], base_ah + off);
                LDSM4(fal[mt][0], fal[mt][1], fal[mt][2], fal[mt][3], base_al + off);
            }
#pragma unroll
            for (int np = 0; np < 2; np++) {
                uint32_t off = swz((wn + np * 16 + (l & 7) + ((l >> 4) & 1) * 8) * 128
                                   + kc * 32 + ((l >> 3) & 1) * 16);
                LDSM4(fbh[np*2][0], fbh[np*2][1], fbh[np*2+1][0], fbh[np*2+1][1], base_bh + off);
                LDSM4(fbl[np*2][0], fbl[np*2][1], fbl[np*2+1][0], fbl[np*2+1][1], base_bl + off);
            }
#pragma unroll
            for (int mt = 0; mt < 2; mt++)
#pragma unroll
                for (int nt = 0; nt < 4; nt++) {
                    MMA16816(acc[mt][nt], fah[mt], fbh[nt]);
                    MMA16816(acc[mt][nt], fah[mt], fbl[nt]);
                    MMA16816(acc[mt][nt], fal[mt], fbh[nt]);
                }
        }
        __syncthreads();
        buf ^= 1;
    }

    const int gr = l >> 2, tc = l & 3;
#pragma unroll
    for (int mt = 0; mt < 2; mt++)
#pragma unroll
        for (int nt = 0; nt < 4; nt++) {
            int m = bm + wm + mt * 16 + gr;
            int n = bn + wn + nt * 8 + tc * 2;
            float2 bv = *(const float2*)(bias + n);
            float2 o0 = make_float2(acc[mt][nt][0] + bv.x, acc[mt][nt][1] + bv.y);
            float2 o1 = make_float2(acc[mt][nt][2] + bv.x, acc[mt][nt][3] + bv.y);
            *(float2*)(C + (size_t)m * N + n) = o0;
            *(float2*)(C + (size_t)(m + 8) * N + n) = o1;
        }
}

// ================= pass1 via mma.sync =================
#define P1_SMEM 138240
__global__ __launch_bounds__(512, 1) void pass1_kernel()
{
    extern __shared__ char sm1[];
    float* kraw = (float*)sm1;
    __nv_bfloat16* Ah = (__nv_bfloat16*)(sm1 + 9216);
    __nv_bfloat16* Al = (__nv_bfloat16*)(sm1 + 64512);
    __nv_bfloat16* Bh = (__nv_bfloat16*)(sm1 + 119808);
    __nv_bfloat16* Bl = (__nv_bfloat16*)(sm1 + 129024);
    const int c = blockIdx.x, h = blockIdx.y, b = blockIdx.z;
    const int tid = threadIdx.x, l = tid & 31, w = tid >> 5;
    const int wm_g = w & 3, wn_g = w >> 2;

    if (tid < 256) {
        int t = tid >> 1, f0 = (tid & 1) * 8;
        const float* kp = g_qkv + (size_t)(b*SS + c*CHK + t)*QKVW + OFF_K + h*FF + f0;
        float4 k0 = *(const float4*)kp, k1 = *(const float4*)(kp + 4);
        kraw[t*18+f0+0]=k0.x; kraw[t*18+f0+1]=k0.y; kraw[t*18+f0+2]=k0.z; kraw[t*18+f0+3]=k0.w;
        kraw[t*18+f0+4]=k1.x; kraw[t*18+f0+5]=k1.y; kraw[t*18+f0+6]=k1.z; kraw[t*18+f0+7]=k1.w;
    }
    {
        uint4 z4 = make_uint4(0,0,0,0);
        uint4* az = (uint4*)(sm1 + 9216);
        for (int i = tid; i < 6912; i += 512) az[i] = z4;
    }
    __syncthreads();

    const size_t zbase = ((size_t)((b*HH + h)*NC + c)) * EXPD;
    if (tid < EXPD) {
        int e = tid;
        float s = 0.f;
        if (e == 0) s = (float)CHK;
        else if (e < 17) {
            for (int t = 0; t < CHK; t++) s += kraw[t*18 + e - 1];
            s *= 0.5f;
        } else {
            int p = e - 17, i = p >> 4, j = p & 15;
            for (int t = 0; t < CHK; t++) s += kraw[t*18 + i] * kraw[t*18 + j];
            s *= C2;
        }
        g_z[zbase + e] = s;
    }

    float acc[6][2][4] = {};

    for (int kc = 0; kc < 2; kc++) {
        const int T0 = kc * 64;
        if (kc) __syncthreads();
        for (int idx = tid; idx < 288*64; idx += 512) {
            int e = idx >> 6, tt = idx & 63;
            if (e < EXPD) {
                float phi;
                if (e == 0) phi = 1.0f;
                else if (e < 17) phi = 0.5f * kraw[(T0+tt)*18 + e - 1];
                else {
                    int p = e - 17;
                    phi = C2 * kraw[(T0+tt)*18 + (p >> 4)] * kraw[(T0+tt)*18 + (p & 15)];
                }
                __nv_bfloat16 hh = __float2bfloat16(phi);
                Ah[e*72 + tt] = hh;
                Al[e*72 + tt] = __float2bfloat16(phi - __bfloat162float(hh));
            }
        }
        for (int idx = tid; idx < 64*16; idx += 512) {
            int tt = idx >> 4, d4 = (idx & 15) * 4;
            float4 v = *(const float4*)(g_qkv + (size_t)(b*SS + c*CHK + T0 + tt)*QKVW + OFF_V + h*HD + d4);
            float e4[4] = {v.x, v.y, v.z, v.w};
#pragma unroll
            for (int q2 = 0; q2 < 4; q2++) {
                __nv_bfloat16 hh = __float2bfloat16(e4[q2]);
                Bh[(d4+q2)*72 + tt] = hh;
                Bl[(d4+q2)*72 + tt] = __float2bfloat16(e4[q2] - __bfloat162float(hh));
            }
        }
        __syncthreads();
        uint32_t bAh = su32(Ah), bAl = su32(Al), bBh = su32(Bh), bBl = su32(Bl);
#pragma unroll
        for (int kt = 0; kt < 4; kt++) {
            uint32_t fbh[2][2], fbl[2][2];
            {
                uint32_t off = (wn_g*16 + (l & 7) + ((l >> 4) & 1) * 8) * 144
                             + kt * 32 + ((l >> 3) & 1) * 16;
                LDSM4(fbh[0][0], fbh[0][1], fbh[1][0], fbh[1][1], bBh + off);
                LDSM4(fbl[0][0], fbl[0][1], fbl[1][0], fbl[1][1], bBl + off);
            }
#pragma unroll
            for (int i = 0; i < 6; i++) {
                uint32_t fa_h[4], fa_l[4];
                uint32_t off = ((wm_g*6 + i)*16 + (l & 15)) * 144 + kt * 32 + (l >> 4) * 16;
                LDSM4(fa_h[0], fa_h[1], fa_h[2], fa_h[3], bAh + off);
                LDSM4(fa_l[0], fa_l[1], fa_l[2], fa_l[3], bAl + off);
#pragma unroll
                for (int j = 0; j < 2; j++) {
                    MMA16816(acc[i][j], fa_h, fbh[j]);
                    MMA16816(acc[i][j], fa_h, fbl[j]);
                    MMA16816(acc[i][j], fa_l, fbh[j]);
                }
            }
        }
    }

    const size_t Sbase = ((size_t)((b*HH + h)*NC + c)) * EXPD * HD;
    const int gr = l >> 2, tc = l & 3;
#pragma unroll
    for (int i = 0; i < 6; i++) {
        int e0 = (wm_g*6 + i) * 16;
#pragma unroll
        for (int j = 0; j < 2; j++) {
            int d = (wn_g*2 + j)*8 + tc*2;
            int e1 = e0 + gr, e2 = e0 + 8 + gr;
            if (e1 < EXPD)
                *(float2*)(g_S + Sbase + (size_t)e1*HD + d) = make_float2(acc[i][j][0], acc[i][j][1]);
            if (e2 < EXPD)
                *(float2*)(g_S + Sbase + (size_t)e2*HD + d) = make_float2(acc[i][j][2], acc[i][j][3]);
        }
    }
}

// ================= prefix (8-way segment split) =================
__global__ __launch_bounds__(256) void prefix_kernel(
    const float* __restrict__ kv0, const float* __restrict__ kst0,
    float* __restrict__ out_kv, float* __restrict__ out_kst)
{
    const int h = blockIdx.x, b = blockIdx.y, seg = blockIdx.z;
    const int pair = b*HH + h;
    const int tid = threadIdx.x;
    const int seglen = EXPD*HD/8;
    for (int idx = seg*seglen + tid; idx < (seg+1)*seglen; idx += 256) {
        float run = kv0[(size_t)pair*EXPD*HD + idx];
        float* p = g_S + ((size_t)pair*NC)*EXPD*HD + idx;
#pragma unroll
        for (int cc = 0; cc < NC; cc++) {
            float sv = p[(size_t)cc*EXPD*HD];
            p[(size_t)cc*EXPD*HD] = run;
            run += sv;
        }
        if (out_kv) out_kv[(size_t)pair*EXPD*HD + idx] = run;
    }
    if (seg == 0) {
        for (int idx = tid; idx < EXPD; idx += 256) {
            float run = kst0[(size_t)pair*EXPD + idx];
            float* p = g_z + ((size_t)pair*NC)*EXPD + idx;
#pragma unroll
            for (int cc = 0; cc < NC; cc++) {
                float sv = p[(size_t)cc*EXPD];
                p[(size_t)cc*EXPD] = run;
                run += sv;
            }
            if (out_kst) out_kst[(size_t)pair*EXPD + idx] = run;
        }
    }
}

// ================= pass2a via mma.sync =================
// smem: qraw[128][18] f32 | PhiH[128][296] bf16 | PhiL | zs[288] f32 | BsH[64][40] bf16 | BsL
#define P2A_SMEM 172160
__global__ __launch_bounds__(256, 1) void pass2a_kernel()
{
    extern __shared__ char smp[];
    float* qraw = (float*)smp;                               // 9216
    __nv_bfloat16* PhiH = (__nv_bfloat16*)(smp + 9216);      // 75776
    __nv_bfloat16* PhiL = (__nv_bfloat16*)(smp + 84992);     // 75776
    float* zs = (float*)(smp + 160768);                      // 1152
    __nv_bfloat16* BsH = (__nv_bfloat16*)(smp + 161920);     // 5120
    __nv_bfloat16* BsL = (__nv_bfloat16*)(smp + 167040);     // 5120
    const int c = blockIdx.x, h = blockIdx.y, b = blockIdx.z;
    const int tid = threadIdx.x, l = tid & 31, w = tid >> 5;
    const int wm = (w >> 1) * 32, wn = (w & 1) * 32;

    {
        int t = tid >> 1, f0 = (tid & 1) * 8;
        const float* qp = g_qkv + (size_t)(b*SS + c*CHK + t)*QKVW + h*FF + f0;
        float4 a = *(const float4*)qp, a2 = *(const float4*)(qp + 4);
        qraw[t*18+f0+0]=a.x;  qraw[t*18+f0+1]=a.y;  qraw[t*18+f0+2]=a.z;  qraw[t*18+f0+3]=a.w;
        qraw[t*18+f0+4]=a2.x; qraw[t*18+f0+5]=a2.y; qraw[t*18+f0+6]=a2.z; qraw[t*18+f0+7]=a2.w;
    }
    {
        const size_t zb = ((size_t)((b*HH + h)*NC + c)) * EXPD;
        for (int e = tid; e < 288; e += 256)
            zs[e] = (e < EXPD) ? g_z[zb + e] : 0.f;
    }
    __syncthreads();

    // Phi build (registers) + den accumulation in fp32
    {
        const int t = tid >> 1, half = tid & 1;
        float qr[16];
#pragma unroll
        for (int f = 0; f < 16; f++) qr[f] = qraw[t*18 + f];
        float den = 0.f;
        __nv_bfloat16* ph = PhiH + t*296;
        __nv_bfloat16* pl = PhiL + t*296;
        if (half == 0) {
#pragma unroll
            for (int ep = 0; ep < 144; ep += 2) {
                float p0, p1;
                { int e = ep;
                  p0 = (e == 0) ? 1.0f : (e < 17 ? 0.5f*qr[e-1]
                        : C2*qr[(e-17)>>4]*qr[(e-17)&15]); }
                { int e = ep + 1;
                  p1 = (e < 17) ? 0.5f*qr[e-1]
                        : C2*qr[(e-17)>>4]*qr[(e-17)&15]; }
                den += p0*zs[ep] + p1*zs[ep+1];
                __nv_bfloat16 h0 = __float2bfloat16(p0), h1 = __float2bfloat16(p1);
                *(__nv_bfloat162*)(ph + ep) = __halves2bfloat162(h0, h1);
                *(__nv_bfloat162*)(pl + ep) = __halves2bfloat162(
                    __float2bfloat16(p0 - __bfloat162float(h0)),
                    __float2bfloat16(p1 - __bfloat162float(h1)));
            }
        } else {
#pragma unroll
            for (int ep = 144; ep < 288; ep += 2) {
                float p0, p1;
                { int e = ep;
                  p0 = (e < EXPD) ? C2*qr[(e-17)>>4]*qr[(e-17)&15] : 0.f; }
                { int e = ep + 1;
                  p1 = (e < EXPD) ? C2*qr[(e-17)>>4]*qr[(e-17)&15] : 0.f; }
                den += p0*zs[ep] + p1*zs[ep+1];
                __nv_bfloat16 h0 = __float2bfloat16(p0), h1 = __float2bfloat16(p1);
                *(__nv_bfloat162*)(ph + ep) = __halves2bfloat162(h0, h1);
                *(__nv_bfloat162*)(pl + ep) = __halves2bfloat162(
                    __float2bfloat16(p0 - __bfloat162float(h0)),
                    __float2bfloat16(p1 - __bfloat162float(h1)));
            }
        }
        den += __shfl_xor_sync(0xffffffffu, den, 1);
        if (half == 0)
            g_den[(size_t)(b*HH + h)*SS + c*CHK + t] = den;
    }

    float acc[2][4][4] = {};
    const size_t Sbase = ((size_t)((b*HH + h)*NC + c)) * EXPD * HD;

    for (int e0 = 0; e0 < 288; e0 += 32) {
        __syncthreads();
        // stage S[e0..e0+32) -> BsT[d][40] hi/lo (transposed, f32->bf16 split)
        {
            int kk = tid >> 3, d8 = (tid & 7) * 8;
            int e = e0 + kk;
            float4 v0, v1;
            if (e < EXPD) {
                v0 = *(const float4*)(g_S + Sbase + (size_t)e*HD + d8);
                v1 = *(const float4*)(g_S + Sbase + (size_t)e*HD + d8 + 4);
            } else {
                v0 = make_float4(0.f,0.f,0.f,0.f);
                v1 = v0;
            }
            float ev[8] = {v0.x, v0.y, v0.z, v0.w, v1.x, v1.y, v1.z, v1.w};
#pragma unroll
            for (int q2 = 0; q2 < 8; q2++) {
                __nv_bfloat16 hh = __float2bfloat16(ev[q2]);
                BsH[(d8+q2)*40 + kk] = hh;
                BsL[(d8+q2)*40 + kk] = __float2bfloat16(ev[q2] - __bfloat162float(hh));
            }
        }
        __syncthreads();
        uint32_t bPH = su32(PhiH), bPL = su32(PhiL), bBH = su32(BsH), bBL = su32(BsL);
#pragma unroll
        for (int kt = 0; kt < 2; kt++) {
            uint32_t fah[2][4], fal[2][4], fbh[4][2], fbl[4][2];
#pragma unroll
            for (int mt = 0; mt < 2; mt++) {
                uint32_t off = (wm + mt*16 + (l & 15)) * 592 + (e0 + kt*16) * 2 + (l >> 4) * 16;
                LDSM4(fah[mt][0], fah[mt][1], fah[mt][2], fah[mt][3], bPH + off);
                LDSM4(fal[mt][0], fal[mt][1], fal[mt][2], fal[mt][3], bPL + off);
            }
#pragma unroll
            for (int np = 0; np < 2; np++) {
                uint32_t off = (wn + np*16 + (l & 7) + ((l >> 4) & 1) * 8) * 80
                             + kt*32 + ((l >> 3) & 1) * 16;
                LDSM4(fbh[np*2][0], fbh[np*2][1], fbh[np*2+1][0], fbh[np*2+1][1], bBH + off);
                LDSM4(fbl[np*2][0], fbl[np*2][1], fbl[np*2+1][0], fbl[np*2+1][1], bBL + off);
            }
#pragma unroll
            for (int mt = 0; mt < 2; mt++)
#pragma unroll
                for (int nt = 0; nt < 4; nt++) {
                    MMA16816(acc[mt][nt], fah[mt], fbh[nt]);
                    MMA16816(acc[mt][nt], fah[mt], fbl[nt]);
                    MMA16816(acc[mt][nt], fal[mt], fbh[nt]);
                }
        }
    }

    const int gr = l >> 2, tc = l & 3;
#pragma unroll
    for (int mt = 0; mt < 2; mt++)
#pragma unroll
        for (int nt = 0; nt < 4; nt++) {
            int m = wm + mt*16 + gr;
            int n = wn + nt*8 + tc*2;
            float* op = g_att + (size_t)(b*SS + c*CHK + m)*VDIM + h*HD + n;
            *(float2*)op = make_float2(acc[mt][nt][0], acc[mt][nt][1]);
            *(float2*)(op + (size_t)8*VDIM) = make_float2(acc[mt][nt][2], acc[mt][nt][3]);
        }
}

// ================= pass2b =================
#define P2B_SMEM ((128*17*2 + 128*64 + 128*129 + 128) * 4)
__global__ __launch_bounds__(256) void pass2b_kernel()
{
    extern __shared__ float sm[];
    float* qs  = sm;
    float* ksm = qs + 128*17;
    float* vsm = ksm + 128*17;
    float* Am  = vsm + 128*64;
    float* rs  = Am + 128*129;
    const int c = blockIdx.x, h = blockIdx.y, b = blockIdx.z;
    const int tid = threadIdx.x;
    {
        int t = tid >> 1, f0 = (tid & 1) * 8;
        const float* qp = g_qkv + (size_t)(b*SS + c*CHK + t)*QKVW + h*FF + f0;
        const float* kp = qp + OFF_K;
        float4 a = *(const float4*)qp;  float4 a2 = *(const float4*)(qp + 4);
        float4 kk = *(const float4*)kp; float4 k2 = *(const float4*)(kp + 4);
        qs[t*17+f0+0]=a.x;  qs[t*17+f0+1]=a.y;  qs[t*17+f0+2]=a.z;  qs[t*17+f0+3]=a.w;
        qs[t*17+f0+4]=a2.x; qs[t*17+f0+5]=a2.y; qs[t*17+f0+6]=a2.z; qs[t*17+f0+7]=a2.w;
        ksm[t*17+f0+0]=kk.x; ksm[t*17+f0+1]=kk.y; ksm[t*17+f0+2]=kk.z; ksm[t*17+f0+3]=kk.w;
        ksm[t*17+f0+4]=k2.x; ksm[t*17+f0+5]=k2.y; ksm[t*17+f0+6]=k2.z; ksm[t*17+f0+7]=k2.w;
    }
    for (int idx = tid; idx < CHK*16; idx += 256) {
        int t = idx >> 4, d4 = (idx & 15) * 4;
        *(float4*)&vsm[t*64 + d4] =
            *(const float4*)(g_qkv + (size_t)(b*SS + c*CHK + t)*QKVW + OFF_V + h*HD + d4);
    }
    __syncthreads();

    {
        const int t = tid >> 1, u0 = (tid & 1) * 64;
        float qreg[16];
#pragma unroll
        for (int f = 0; f < 16; f++) qreg[f] = qs[t*17+f];
        float rsum = 0.f;
        for (int uu = 0; uu < 64; uu++) {
            int u = u0 + uu;
            float s = 0.f;
#pragma unroll
            for (int f = 0; f < 16; f++)
                s = fmaf(qreg[f], ksm[u*17+f], s);
            float a = (u <= t) ? fmaf(s, fmaf(s, 0.03125f, 0.25f), 1.0f) : 0.f;
            Am[t*129 + u] = a;
            rsum += a;
        }
        rsum += __shfl_xor_sync(0xffffffffu, rsum, 1);
        if ((tid & 1) == 0) rs[t] = rsum;
    }
    __syncthreads();

    {
        const int t = tid >> 1, d0 = (tid & 1) * 32;
        float4 acc[8];
#pragma unroll
        for (int g = 0; g < 8; g++) acc[g] = make_float4(0.f,0.f,0.f,0.f);
        const int tmax = (tid >> 5) * 16 + 15;
        for (int u = 0; u <= tmax; u++) {
            float a = Am[t*129 + u];
            const float4* vr = (const float4*)&vsm[u*64 + d0];
#pragma unroll
            for (int g = 0; g < 8; g++) {
                float4 vv = vr[g];
                acc[g].x = fmaf(a, vv.x, acc[g].x);
                acc[g].y = fmaf(a, vv.y, acc[g].y);
                acc[g].z = fmaf(a, vv.z, acc[g].z);
                acc[g].w = fmaf(a, vv.w, acc[g].w);
            }
        }
        float den = rs[t] + g_den[(size_t)(b*HH + h)*SS + c*CHK + t] + 1e-6f;
        float inv = 1.0f / den;
        const size_t obase = (size_t)(b*SS + c*CHK + t)*VDIM + h*HD + d0;
        const float* ip = g_att + obase;
#pragma unroll
        for (int g = 0; g < 8; g++) {
            float4 cur = *(const float4*)(ip + g*4);
            float4 r;
            r.x = (cur.x + acc[g].x) * inv;
            r.y = (cur.y + acc[g].y) * inv;
            r.z = (cur.z + acc[g].z) * inv;
            r.w = (cur.w + acc[g].w) * inv;
            __nv_bfloat16 h0 = __float2bfloat16(r.x), h1 = __float2bfloat16(r.y);
            __nv_bfloat16 h2 = __float2bfloat16(r.z), h3 = __float2bfloat16(r.w);
            __nv_bfloat162 ph0 = __halves2bfloat162(h0, h1);
            __nv_bfloat162 ph1 = __halves2bfloat162(h2, h3);
            __nv_bfloat162 pl0 = __halves2bfloat162(__float2bfloat16(r.x - __bfloat162float(h0)),
                                                    __float2bfloat16(r.y - __bfloat162float(h1)));
            __nv_bfloat162 pl1 = __halves2bfloat162(__float2bfloat16(r.z - __bfloat162float(h2)),
                                                    __float2bfloat16(r.w - __bfloat162float(h3)));
            *(__nv_bfloat162*)(g_xhi + obase + g*4)     = ph0;
            *(__nv_bfloat162*)(g_xhi + obase + g*4 + 2) = ph1;
            *(__nv_bfloat162*)(g_xlo + obase + g*4)     = pl0;
            *(__nv_bfloat162*)(g_xlo + obase + g*4 + 2) = pl1;
        }
    }
}

extern "C" void kernel_launch(void* const* d_in, const int* in_sizes, int n_in,
                              void* d_out, int out_size)
{
    (void)in_sizes; (void)n_in;
    const float* x    = (const float*)d_in[0];
    const float* kv0  = (const float*)d_in[1];
    const float* kst0 = (const float*)d_in[2];
    const float* Wq   = (const float*)d_in[3];
    const float* bq   = (const float*)d_in[4];
    const float* Wk   = (const float*)d_in[5];
    const float* bk   = (const float*)d_in[6];
    const float* Wv   = (const float*)d_in[7];
    const float* bv   = (const float*)d_in[8];
    const float* Wo   = (const float*)d_in[9];
    const float* bo   = (const float*)d_in[10];

    float* y = (float*)d_out;
    float* kvf = nullptr;
    float* kstf = nullptr;
    if (out_size >= Y_ELEMS + KV_ELEMS + KST_ELEMS) {
        kvf  = y + Y_ELEMS;
        kstf = kvf + KV_ELEMS;
    }

    float *pqkv, *pbqkv;
    __nv_bfloat16 *xhi, *xlo, *wqh, *wql, *woh, *wol;
    cudaGetSymbolAddress((void**)&pqkv,  g_qkv);
    cudaGetSymbolAddress((void**)&pbqkv, g_bqkv);
    cudaGetSymbolAddress((void**)&xhi, g_xhi);
    cudaGetSymbolAddress((void**)&xlo, g_xlo);
    cudaGetSymbolAddress((void**)&wqh, g_wqh);
    cudaGetSymbolAddress((void**)&wql, g_wql);
    cudaGetSymbolAddress((void**)&woh, g_woh);
    cudaGetSymbolAddress((void**)&wol, g_wol);

    cudaFuncSetAttribute(gemm_bf16, cudaFuncAttributeMaxDynamicSharedMemorySize, GS_SMEM);
    cudaFuncSetAttribute(pass1_kernel, cudaFuncAttributeMaxDynamicSharedMemorySize, P1_SMEM);
    cudaFuncSetAttribute(pass2a_kernel, cudaFuncAttributeMaxDynamicSharedMemorySize, P2A_SMEM);
    cudaFuncSetAttribute(pass2b_kernel, cudaFuncAttributeMaxDynamicSharedMemorySize, P2B_SMEM);

    const int M = BB * SS;  // 8192

    cvt_split<<<(M * DM) / 1024 + 1, 256>>>(x, xhi, xlo, M * DM, bq, bk, bv, pbqkv);
    cvt_wT_all<<<dim3(32, 32, 4), 256>>>(Wq, Wk, Wv, Wo, wqh, wql, woh, wol);
    gemm_bf16<<<dim3(QKVW/64, M/128), 256, GS_SMEM>>>(xhi, xlo, wqh, wql, pbqkv, pqkv, QKVW, DM);

    pass1_kernel<<<dim3(NC, HH, BB), 512, P1_SMEM>>>();
    prefix_kernel<<<dim3(HH, BB, 8), 256>>>(kv0, kst0, kvf, kstf);
    pass2a_kernel<<<dim3(NC, HH, BB), 256, P2A_SMEM>>>();
    pass2b_kernel<<<dim3(NC, HH, BB), 256, P2B_SMEM>>>();

    gemm_bf16<<<dim3(DM/64, M/128), 256, GS_SMEM>>>(xhi, xlo, woh, wol, bo, y, DM, VDIM);
}

// round 16
// speedup vs baseline: 2.1817x; 1.0458x over previous
#include <cuda_runtime.h>
#include <cuda_bf16.h>
#include <cstdint>

#define BB 4
#define SS 2048
#define DM 1024
#define HH 16
#define FF 16
#define HD 64
#define EXPD 273
#define NC 16
#define CHK 128
#define QKDIM (HH*FF)
#define VDIM  (HH*HD)
#define QKVW  1536
#define OFF_K 256
#define OFF_V 512
#define C2 0.17677669529663687f

#define Y_ELEMS   (BB*SS*DM)
#define KV_ELEMS  (BB*HH*EXPD*HD)
#define KST_ELEMS (BB*HH*EXPD)

__device__ float g_qkv[BB*SS*QKVW];
__device__ float g_S[BB*HH*NC*EXPD*HD];
__device__ float g_z[BB*HH*NC*EXPD];
__device__ float g_den[BB*HH*SS];
__device__ float g_att[BB*SS*VDIM];
__device__ float g_bqkv[QKVW];
__device__ __nv_bfloat16 g_xhi[BB*SS*DM];
__device__ __nv_bfloat16 g_xlo[BB*SS*DM];
__device__ __nv_bfloat16 g_wqh[QKVW*DM];
__device__ __nv_bfloat16 g_wql[QKVW*DM];
__device__ __nv_bfloat16 g_woh[DM*DM];
__device__ __nv_bfloat16 g_wol[DM*DM];

// ---------------- helpers ----------------
__device__ __forceinline__ uint32_t su32(const void* p) {
    uint32_t a;
    asm("{ .reg .u64 t; cvta.to.shared.u64 t, %1; cvt.u32.u64 %0, t; }" : "=r"(a) : "l"(p));
    return a;
}
__device__ __forceinline__ uint32_t swz(uint32_t o) { return o ^ ((o >> 3) & 0x70); }
__device__ __forceinline__ void cpa16(uint32_t s, const void* g) {
    asm volatile("cp.async.cg.shared.global [%0], [%1], 16;" :: "r"(s), "l"(g));
}

#define LDSM4(r0,r1,r2,r3, addr) \
    asm volatile("ldmatrix.sync.aligned.m8n8.x4.shared.b16 {%0,%1,%2,%3}, [%4];" \
                 : "=r"(r0),"=r"(r1),"=r"(r2),"=r"(r3) : "r"(addr))
#define LDSM4T(r0,r1,r2,r3, addr) \
    asm volatile("ldmatrix.sync.aligned.m8n8.x4.trans.shared.b16 {%0,%1,%2,%3}, [%4];" \
                 : "=r"(r0),"=r"(r1),"=r"(r2),"=r"(r3) : "r"(addr))
#define LDSM2(r0,r1, addr) \
    asm volatile("ldmatrix.sync.aligned.m8n8.x2.shared.b16 {%0,%1}, [%2];" \
                 : "=r"(r0),"=r"(r1) : "r"(addr))
#define MMA16816(d, a, b) \
    asm volatile("mma.sync.aligned.m16n8k16.row.col.f32.bf16.bf16.f32 " \
                 "{%0,%1,%2,%3},{%4,%5,%6,%7},{%8,%9},{%0,%1,%2,%3};" \
                 : "+f"((d)[0]),"+f"((d)[1]),"+f"((d)[2]),"+f"((d)[3]) \
                 : "r"((a)[0]),"r"((a)[1]),"r"((a)[2]),"r"((a)[3]),"r"((b)[0]),"r"((b)[1]))

// ---------------- conversions ----------------
__global__ void cvt_split(const float* __restrict__ in,
                          __nv_bfloat16* __restrict__ hi,
                          __nv_bfloat16* __restrict__ lo, int n,
                          const float* __restrict__ b0, const float* __restrict__ b1,
                          const float* __restrict__ b2, float* __restrict__ bout)
{
    if (blockIdx.x == gridDim.x - 1) {
        int t = threadIdx.x;
        if (t < QKDIM) { bout[t] = b0[t]; bout[OFF_K + t] = b1[t]; }
        for (int i = t; i < VDIM; i += 256) bout[OFF_V + i] = b2[i];
        return;
    }
    int i = (blockIdx.x * blockDim.x + threadIdx.x) * 4;
    if (i >= n) return;
    float4 v = *(const float4*)(in + i);
    __nv_bfloat16 h0 = __float2bfloat16(v.x), h1 = __float2bfloat16(v.y);
    __nv_bfloat16 h2 = __float2bfloat16(v.z), h3 = __float2bfloat16(v.w);
    __nv_bfloat162 ph0 = __halves2bfloat162(h0, h1);
    __nv_bfloat162 ph1 = __halves2bfloat162(h2, h3);
    __nv_bfloat162 pl0 = __halves2bfloat162(__float2bfloat16(v.x - __bfloat162float(h0)),
                                            __float2bfloat16(v.y - __bfloat162float(h1)));
    __nv_bfloat162 pl1 = __halves2bfloat162(__float2bfloat16(v.z - __bfloat162float(h2)),
                                            __float2bfloat16(v.w - __bfloat162float(h3)));
    *(__nv_bfloat162*)(hi + i)     = ph0;
    *(__nv_bfloat162*)(hi + i + 2) = ph1;
    *(__nv_bfloat162*)(lo + i)     = pl0;
    *(__nv_bfloat162*)(lo + i + 2) = pl1;
}

__global__ void cvt_wT_all(const float* __restrict__ Wq, const float* __restrict__ Wk,
                           const float* __restrict__ Wv, const float* __restrict__ Wo,
                           __nv_bfloat16* __restrict__ qh, __nv_bfloat16* __restrict__ ql,
                           __nv_bfloat16* __restrict__ oh, __nv_bfloat16* __restrict__ ol)
{
    __shared__ float t[32][33];
    const int z = blockIdx.z;
    const float* W; __nv_bfloat16 *Th, *Tl; int N, rowoff;
    if (z == 0)      { W = Wq; Th = qh; Tl = ql; N = QKDIM; rowoff = 0; }
    else if (z == 1) { W = Wk; Th = qh; Tl = ql; N = QKDIM; rowoff = OFF_K; }
    else if (z == 2) { W = Wv; Th = qh; Tl = ql; N = VDIM;  rowoff = OFF_V; }
    else             { W = Wo; Th = oh; Tl = ol; N = DM;    rowoff = 0; }
    const int bx = blockIdx.x * 32, by = blockIdx.y * 32;
    if (bx >= N) return;
    const int tx = threadIdx.x & 31, ty = threadIdx.x >> 5;
#pragma unroll
    for (int r = 0; r < 4; r++)
        t[ty + 8 * r][tx] = W[(size_t)(by + ty + 8 * r) * N + bx + tx];
    __syncthreads();
#pragma unroll
    for (int r = 0; r < 4; r++) {
        float v = t[tx][ty + 8 * r];
        __nv_bfloat16 h = __float2bfloat16(v);
        size_t o = (size_t)(rowoff + bx + ty + 8 * r) * DM + by + tx;
        Th[o] = h;
        Tl[o] = __float2bfloat16(v - __bfloat162float(h));
    }
}

// ---------------- bf16 split GEMM, cp.async pipeline ----------------
#define STG 49152
#define GS_SMEM (2*STG)

#define ISSUE_STAGE(k0, b_) do { \
    uint32_t pa_h = sbase + (b_) * STG; \
    uint32_t pa_l = pa_h + 16384; \
    uint32_t pb_h = pa_h + 32768; \
    uint32_t pb_l = pa_h + 40960; \
    const __nv_bfloat16* aph = Ah + (size_t)(bm + arow) * K + (k0) + acol; \
    const __nv_bfloat16* apl = Al + (size_t)(bm + arow) * K + (k0) + acol; \
    _Pragma("unroll") for (int j = 0; j < 4; j++) { \
        uint32_t off = swz(arow * 128 + acol * 2 + j * 16); \
        cpa16(pa_h + off, aph + j * 8); \
        cpa16(pa_l + off, apl + j * 8); } \
    const __nv_bfloat16* bph = Bh + (size_t)(bn + brow) * K + (k0) + bcol; \
    const __nv_bfloat16* bpl = Bl + (size_t)(bn + brow) * K + (k0) + bcol; \
    _Pragma("unroll") for (int j = 0; j < 2; j++) { \
        uint32_t off = swz(brow * 128 + bcol * 2 + j * 16); \
        cpa16(pb_h + off, bph + j * 8); \
        cpa16(pb_l + off, bpl + j * 8); } \
    asm volatile("cp.async.commit_group;" ::: "memory"); \
} while (0)

__global__ __launch_bounds__(256, 2) void gemm_bf16(
    const __nv_bfloat16* __restrict__ Ah, const __nv_bfloat16* __restrict__ Al,
    const __nv_bfloat16* __restrict__ Bh, const __nv_bfloat16* __restrict__ Bl,
    const float* __restrict__ bias, float* __restrict__ C, int N, int K)
{
    extern __shared__ char smn[];
    const int tid = threadIdx.x, l = tid & 31, w = tid >> 5;
    const int bm = blockIdx.y * 128, bn = blockIdx.x * 64;
    const int wm = (w >> 1) * 32, wn = (w & 1) * 32;
    const uint32_t sbase = su32(smn);

    const int arow = tid >> 1, acol = (tid & 1) * 32;
    const int brow = tid >> 2, bcol = (tid & 3) * 16;

    float acc[2][4][4] = {};
    const int nstep = K / 64;

    ISSUE_STAGE(0, 0);
    int buf = 0;
    for (int s = 0; s < nstep; s++) {
        if (s + 1 < nstep) {
            ISSUE_STAGE((s + 1) * 64, buf ^ 1);
            asm volatile("cp.async.wait_group 1;" ::: "memory");
        } else {
            asm volatile("cp.async.wait_group 0;" ::: "memory");
        }
        __syncthreads();
        uint32_t base_ah = sbase + buf * STG;
        uint32_t base_al = base_ah + 16384;
        uint32_t base_bh = base_ah + 32768;
        uint32_t base_bl = base_ah + 40960;
#pragma unroll
        for (int kc = 0; kc < 4; kc++) {
            uint32_t fah[2][4], fal[2][4], fbh[4][2], fbl[4][2];
#pragma unroll
            for (int mt = 0; mt < 2; mt++) {
                uint32_t off = swz((wm + mt * 16 + (l & 15)) * 128 + kc * 32 + (l >> 4) * 16);
                LDSM4(fah[mt][0], fah[mt][1], fah[mt][2], fah[mt][3], base_ah + off);
                LDSM4(fal[mt][0], fal[mt][1], fal[mt][2], fal[mt][3], base_al + off);
            }
#pragma unroll
            for (int np = 0; np < 2; np++) {
                uint32_t off = swz((wn + np * 16 + (l & 7) + ((l >> 4) & 1) * 8) * 128
                                   + kc * 32 + ((l >> 3) & 1) * 16);
                LDSM4(fbh[np*2][0], fbh[np*2][1], fbh[np*2+1][0], fbh[np*2+1][1], base_bh + off);
                LDSM4(fbl[np*2][0], fbl[np*2][1], fbl[np*2+1][0], fbl[np*2+1][1], base_bl + off);
            }
#pragma unroll
            for (int mt = 0; mt < 2; mt++)
#pragma unroll
                for (int nt = 0; nt < 4; nt++) {
                    MMA16816(acc[mt][nt], fah[mt], fbh[nt]);
                    MMA16816(acc[mt][nt], fah[mt], fbl[nt]);
                    MMA16816(acc[mt][nt], fal[mt], fbh[nt]);
                }
        }
        __syncthreads();
        buf ^= 1;
    }

    const int gr = l >> 2, tc = l & 3;
#pragma unroll
    for (int mt = 0; mt < 2; mt++)
#pragma unroll
        for (int nt = 0; nt < 4; nt++) {
            int m = bm + wm + mt * 16 + gr;
            int n = bn + wn + nt * 8 + tc * 2;
            float2 bv = *(const float2*)(bias + n);
            float2 o0 = make_float2(acc[mt][nt][0] + bv.x, acc[mt][nt][1] + bv.y);
            float2 o1 = make_float2(acc[mt][nt][2] + bv.x, acc[mt][nt][3] + bv.y);
            *(float2*)(C + (size_t)m * N + n) = o0;
            *(float2*)(C + (size_t)(m + 8) * N + n) = o1;
        }
}

// ================= pass1 via mma.sync + trans-A, register Phi build =================
// smem: kraw[128][18] f32 (9216) | PhH[128][296] bf16 (75776) | PhL (75776)
//       | BtH[64][152] bf16 (19456) | BtL (19456)  = 199680
#define P1_SMEM 199680

#define P1_QBLOCK(E0, E1) \
    _Pragma("unroll") \
    for (int ep = (E0); ep < (E1); ep += 2) { \
        float p0, p1; \
        { constexpr_int_e0: ; int e = ep; \
          p0 = (e == 0) ? 1.0f : (e < 17 ? 0.5f*kr[e-1] \
                : (e < EXPD ? C2*kr[(e-17)>>4]*kr[(e-17)&15] : 0.f)); } \
        { int e = ep + 1; \
          p1 = (e < 17) ? 0.5f*kr[e-1] \
                : (e < EXPD ? C2*kr[(e-17)>>4]*kr[(e-17)&15] : 0.f); } \
        __nv_bfloat16 h0 = __float2bfloat16(p0), h1 = __float2bfloat16(p1); \
        *(__nv_bfloat162*)(ph + ep) = __halves2bfloat162(h0, h1); \
        *(__nv_bfloat162*)(pl + ep) = __halves2bfloat162( \
            __float2bfloat16(p0 - __bfloat162float(h0)), \
            __float2bfloat16(p1 - __bfloat162float(h1))); \
    }

__global__ __launch_bounds__(512, 1) void pass1_kernel()
{
    extern __shared__ char sm1[];
    float* kraw = (float*)sm1;
    __nv_bfloat16* PhH = (__nv_bfloat16*)(sm1 + 9216);
    __nv_bfloat16* PhL = (__nv_bfloat16*)(sm1 + 84992);
    __nv_bfloat16* BtH = (__nv_bfloat16*)(sm1 + 160768);
    __nv_bfloat16* BtL = (__nv_bfloat16*)(sm1 + 180224);
    const int c = blockIdx.x, h = blockIdx.y, b = blockIdx.z;
    const int tid = threadIdx.x, l = tid & 31, w = tid >> 5;
    const int wm_g = w & 1, wn_g = w >> 1;   // 2 m-groups x 8 n-groups

    if (tid < 256) {
        int t = tid >> 1, f0 = (tid & 1) * 8;
        const float* kp = g_qkv + (size_t)(b*SS + c*CHK + t)*QKVW + OFF_K + h*FF + f0;
        float4 k0 = *(const float4*)kp, k1 = *(const float4*)(kp + 4);
        kraw[t*18+f0+0]=k0.x; kraw[t*18+f0+1]=k0.y; kraw[t*18+f0+2]=k0.z; kraw[t*18+f0+3]=k0.w;
        kraw[t*18+f0+4]=k1.x; kraw[t*18+f0+5]=k1.y; kraw[t*18+f0+6]=k1.z; kraw[t*18+f0+7]=k1.w;
    }
    // V^T build: [d][152] hi/lo, both 64-token halves = 128 tokens
    for (int idx = tid; idx < 128*16; idx += 512) {
        int tt = idx >> 4, d4 = (idx & 15) * 4;
        float4 v = *(const float4*)(g_qkv + (size_t)(b*SS + c*CHK + tt)*QKVW + OFF_V + h*HD + d4);
        float e4[4] = {v.x, v.y, v.z, v.w};
#pragma unroll
        for (int q2 = 0; q2 < 4; q2++) {
            __nv_bfloat16 hh = __float2bfloat16(e4[q2]);
            BtH[(d4+q2)*152 + tt] = hh;
            BtL[(d4+q2)*152 + tt] = __float2bfloat16(e4[q2] - __bfloat162float(hh));
        }
    }
    __syncthreads();

    // z = column sums of Phi (from raw k)
    const size_t zbase = ((size_t)((b*HH + h)*NC + c)) * EXPD;
    if (tid < EXPD) {
        int e = tid;
        float s = 0.f;
        if (e == 0) s = (float)CHK;
        else if (e < 17) {
            for (int t = 0; t < CHK; t++) s += kraw[t*18 + e - 1];
            s *= 0.5f;
        } else {
            int p = e - 17, i = p >> 4, j = p & 15;
            for (int t = 0; t < CHK; t++) s += kraw[t*18 + i] * kraw[t*18 + j];
            s *= C2;
        }
        g_z[zbase + e] = s;
    }

    // Phi build: [t][296] hi/lo; q = tid>>7 keeps warps convergent
    {
        const int t = tid & 127, q = tid >> 7;
        float kr[16];
#pragma unroll
        for (int f = 0; f < 16; f++) kr[f] = kraw[t*18 + f];
        __nv_bfloat16* ph = PhH + t*296;
        __nv_bfloat16* pl = PhL + t*296;
        if (q == 0) {
#pragma unroll
            for (int ep = 0; ep < 72; ep += 2) {
                float p0, p1;
                { int e = ep;
                  p0 = (e == 0) ? 1.0f : (e < 17 ? 0.5f*kr[e-1]
                        : C2*kr[(e-17)>>4]*kr[(e-17)&15]); }
                { int e = ep + 1;
                  p1 = (e < 17) ? 0.5f*kr[e-1] : C2*kr[(e-17)>>4]*kr[(e-17)&15]; }
                __nv_bfloat16 h0 = __float2bfloat16(p0), h1 = __float2bfloat16(p1);
                *(__nv_bfloat162*)(ph + ep) = __halves2bfloat162(h0, h1);
                *(__nv_bfloat162*)(pl + ep) = __halves2bfloat162(
                    __float2bfloat16(p0 - __bfloat162float(h0)),
                    __float2bfloat16(p1 - __bfloat162float(h1)));
            }
        } else if (q == 1) {
#pragma unroll
            for (int ep = 72; ep < 144; ep += 2) {
                float p0 = C2*kr[(ep-17)>>4]*kr[(ep-17)&15];
                float p1 = C2*kr[(ep-16)>>4]*kr[(ep-16)&15];
                __nv_bfloat16 h0 = __float2bfloat16(p0), h1 = __float2bfloat16(p1);
                *(__nv_bfloat162*)(ph + ep) = __halves2bfloat162(h0, h1);
                *(__nv_bfloat162*)(pl + ep) = __halves2bfloat162(
                    __float2bfloat16(p0 - __bfloat162float(h0)),
                    __float2bfloat16(p1 - __bfloat162float(h1)));
            }
        } else if (q == 2) {
#pragma unroll
            for (int ep = 144; ep < 216; ep += 2) {
                float p0 = C2*kr[(ep-17)>>4]*kr[(ep-17)&15];
                float p1 = C2*kr[(ep-16)>>4]*kr[(ep-16)&15];
                __nv_bfloat16 h0 = __float2bfloat16(p0), h1 = __float2bfloat16(p1);
                *(__nv_bfloat162*)(ph + ep) = __halves2bfloat162(h0, h1);
                *(__nv_bfloat162*)(pl + ep) = __halves2bfloat162(
                    __float2bfloat16(p0 - __bfloat162float(h0)),
                    __float2bfloat16(p1 - __bfloat162float(h1)));
            }
        } else {
#pragma unroll
            for (int ep = 216; ep < 288; ep += 2) {
                float p0 = (ep     < EXPD) ? C2*kr[(ep-17)>>4]*kr[(ep-17)&15] : 0.f;
                float p1 = (ep + 1 < EXPD) ? C2*kr[(ep-16)>>4]*kr[(ep-16)&15] : 0.f;
                __nv_bfloat16 h0 = __float2bfloat16(p0), h1 = __float2bfloat16(p1);
                *(__nv_bfloat162*)(ph + ep) = __halves2bfloat162(h0, h1);
                *(__nv_bfloat162*)(pl + ep) = __halves2bfloat162(
                    __float2bfloat16(p0 - __bfloat162float(h0)),
                    __float2bfloat16(p1 - __bfloat162float(h1)));
            }
        }
    }
    __syncthreads();

    // mma: S[e 288][d 64] = Phi^T @ V ; A = Phi^T via trans-ldmatrix, K=128 tokens
    float acc[9][4] = {};
    const uint32_t bPH = su32(PhH), bPL = su32(PhL);
    const uint32_t bBH = su32(BtH), bBL = su32(BtL);
    const uint32_t boff0 = (wn_g*8 + (l & 7)) * 304 + ((l >> 3) & 1) * 16;
    const uint32_t aoff0 = ((l & 7) + ((l >> 4) & 1) * 8) * 592 + ((l >> 3) & 1) * 16;
#pragma unroll
    for (int kt = 0; kt < 8; kt++) {
        uint32_t fbh[2], fbl[2];
        LDSM2(fbh[0], fbh[1], bBH + boff0 + kt*32);
        LDSM2(fbl[0], fbl[1], bBL + boff0 + kt*32);
#pragma unroll
        for (int i = 0; i < 9; i++) {
            int m_base = (wm_g*9 + i) * 16;
            uint32_t aoff = aoff0 + kt*16*592 + m_base*2;
            uint32_t fah[4], fal[4];
            LDSM4T(fah[0], fah[1], fah[2], fah[3], bPH + aoff);
            LDSM4T(fal[0], fal[1], fal[2], fal[3], bPL + aoff);
            MMA16816(acc[i], fah, fbh);
            MMA16816(acc[i], fah, fbl);
            MMA16816(acc[i], fal, fbh);
        }
    }

    const size_t Sbase = ((size_t)((b*HH + h)*NC + c)) * EXPD * HD;
    const int gr = l >> 2, tc = l & 3;
    const int d = wn_g*8 + tc*2;
#pragma unroll
    for (int i = 0; i < 9; i++) {
        int e1 = (wm_g*9 + i)*16 + gr, e2 = e1 + 8;
        if (e1 < EXPD)
            *(float2*)(g_S + Sbase + (size_t)e1*HD + d) = make_float2(acc[i][0], acc[i][1]);
        if (e2 < EXPD)
            *(float2*)(g_S + Sbase + (size_t)e2*HD + d) = make_float2(acc[i][2], acc[i][3]);
    }
}

// ================= prefix (8-way segment split) =================
__global__ __launch_bounds__(256) void prefix_kernel(
    const float* __restrict__ kv0, const float* __restrict__ kst0,
    float* __restrict__ out_kv, float* __restrict__ out_kst)
{
    const int h = blockIdx.x, b = blockIdx.y, seg = blockIdx.z;
    const int pair = b*HH + h;
    const int tid = threadIdx.x;
    const int seglen = EXPD*HD/8;
    for (int idx = seg*seglen + tid; idx < (seg+1)*seglen; idx += 256) {
        float run = kv0[(size_t)pair*EXPD*HD + idx];
        float* p = g_S + ((size_t)pair*NC)*EXPD*HD + idx;
#pragma unroll
        for (int cc = 0; cc < NC; cc++) {
            float sv = p[(size_t)cc*EXPD*HD];
            p[(size_t)cc*EXPD*HD] = run;
            run += sv;
        }
        if (out_kv) out_kv[(size_t)pair*EXPD*HD + idx] = run;
    }
    if (seg == 0) {
        for (int idx = tid; idx < EXPD; idx += 256) {
            float run = kst0[(size_t)pair*EXPD + idx];
            float* p = g_z + ((size_t)pair*NC)*EXPD + idx;
#pragma unroll
            for (int cc = 0; cc < NC; cc++) {
                float sv = p[(size_t)cc*EXPD];
                p[(size_t)cc*EXPD] = run;
                run += sv;
            }
            if (out_kst) out_kst[(size_t)pair*EXPD + idx] = run;
        }
    }
}

// ================= pass2a via mma.sync =================
#define P2A_SMEM 172160
__global__ __launch_bounds__(256, 1) void pass2a_kernel()
{
    extern __shared__ char smp[];
    float* qraw = (float*)smp;
    __nv_bfloat16* PhiH = (__nv_bfloat16*)(smp + 9216);
    __nv_bfloat16* PhiL = (__nv_bfloat16*)(smp + 84992);
    float* zs = (float*)(smp + 160768);
    __nv_bfloat16* BsH = (__nv_bfloat16*)(smp + 161920);
    __nv_bfloat16* BsL = (__nv_bfloat16*)(smp + 167040);
    const int c = blockIdx.x, h = blockIdx.y, b = blockIdx.z;
    const int tid = threadIdx.x, l = tid & 31, w = tid >> 5;
    const int wm = (w >> 1) * 32, wn = (w & 1) * 32;

    {
        int t = tid >> 1, f0 = (tid & 1) * 8;
        const float* qp = g_qkv + (size_t)(b*SS + c*CHK + t)*QKVW + h*FF + f0;
        float4 a = *(const float4*)qp, a2 = *(const float4*)(qp + 4);
        qraw[t*18+f0+0]=a.x;  qraw[t*18+f0+1]=a.y;  qraw[t*18+f0+2]=a.z;  qraw[t*18+f0+3]=a.w;
        qraw[t*18+f0+4]=a2.x; qraw[t*18+f0+5]=a2.y; qraw[t*18+f0+6]=a2.z; qraw[t*18+f0+7]=a2.w;
    }
    {
        const size_t zb = ((size_t)((b*HH + h)*NC + c)) * EXPD;
        for (int e = tid; e < 288; e += 256)
            zs[e] = (e < EXPD) ? g_z[zb + e] : 0.f;
    }
    __syncthreads();

    {
        const int t = tid >> 1, half = tid & 1;
        float qr[16];
#pragma unroll
        for (int f = 0; f < 16; f++) qr[f] = qraw[t*18 + f];
        float den = 0.f;
        __nv_bfloat16* ph = PhiH + t*296;
        __nv_bfloat16* pl = PhiL + t*296;
        if (half == 0) {
#pragma unroll
            for (int ep = 0; ep < 144; ep += 2) {
                float p0, p1;
                { int e = ep;
                  p0 = (e == 0) ? 1.0f : (e < 17 ? 0.5f*qr[e-1]
                        : C2*qr[(e-17)>>4]*qr[(e-17)&15]); }
                { int e = ep + 1;
                  p1 = (e < 17) ? 0.5f*qr[e-1]
                        : C2*qr[(e-17)>>4]*qr[(e-17)&15]; }
                den += p0*zs[ep] + p1*zs[ep+1];
                __nv_bfloat16 h0 = __float2bfloat16(p0), h1 = __float2bfloat16(p1);
                *(__nv_bfloat162*)(ph + ep) = __halves2bfloat162(h0, h1);
                *(__nv_bfloat162*)(pl + ep) = __halves2bfloat162(
                    __float2bfloat16(p0 - __bfloat162float(h0)),
                    __float2bfloat16(p1 - __bfloat162float(h1)));
            }
        } else {
#pragma unroll
            for (int ep = 144; ep < 288; ep += 2) {
                float p0, p1;
                { int e = ep;
                  p0 = (e < EXPD) ? C2*qr[(e-17)>>4]*qr[(e-17)&15] : 0.f; }
                { int e = ep + 1;
                  p1 = (e < EXPD) ? C2*qr[(e-17)>>4]*qr[(e-17)&15] : 0.f; }
                den += p0*zs[ep] + p1*zs[ep+1];
                __nv_bfloat16 h0 = __float2bfloat16(p0), h1 = __float2bfloat16(p1);
                *(__nv_bfloat162*)(ph + ep) = __halves2bfloat162(h0, h1);
                *(__nv_bfloat162*)(pl + ep) = __halves2bfloat162(
                    __float2bfloat16(p0 - __bfloat162float(h0)),
                    __float2bfloat16(p1 - __bfloat162float(h1)));
            }
        }
        den += __shfl_xor_sync(0xffffffffu, den, 1);
        if (half == 0)
            g_den[(size_t)(b*HH + h)*SS + c*CHK + t] = den;
    }

    float acc[2][4][4] = {};
    const size_t Sbase = ((size_t)((b*HH + h)*NC + c)) * EXPD * HD;

    for (int e0 = 0; e0 < 288; e0 += 32) {
        __syncthreads();
        {
            int kk = tid >> 3, d8 = (tid & 7) * 8;
            int e = e0 + kk;
            float4 v0, v1;
            if (e < EXPD) {
                v0 = *(const float4*)(g_S + Sbase + (size_t)e*HD + d8);
                v1 = *(const float4*)(g_S + Sbase + (size_t)e*HD + d8 + 4);
            } else {
                v0 = make_float4(0.f,0.f,0.f,0.f);
                v1 = v0;
            }
            float ev[8] = {v0.x, v0.y, v0.z, v0.w, v1.x, v1.y, v1.z, v1.w};
#pragma unroll
            for (int q2 = 0; q2 < 8; q2++) {
                __nv_bfloat16 hh = __float2bfloat16(ev[q2]);
                BsH[(d8+q2)*40 + kk] = hh;
                BsL[(d8+q2)*40 + kk] = __float2bfloat16(ev[q2] - __bfloat162float(hh));
            }
        }
        __syncthreads();
        uint32_t bPH = su32(PhiH), bPL = su32(PhiL), bBH = su32(BsH), bBL = su32(BsL);
#pragma unroll
        for (int kt = 0; kt < 2; kt++) {
            uint32_t fah[2][4], fal[2][4], fbh[4][2], fbl[4][2];
#pragma unroll
            for (int mt = 0; mt < 2; mt++) {
                uint32_t off = (wm + mt*16 + (l & 15)) * 592 + (e0 + kt*16) * 2 + (l >> 4) * 16;
                LDSM4(fah[mt][0], fah[mt][1], fah[mt][2], fah[mt][3], bPH + off);
                LDSM4(fal[mt][0], fal[mt][1], fal[mt][2], fal[mt][3], bPL + off);
            }
#pragma unroll
            for (int np = 0; np < 2; np++) {
                uint32_t off = (wn + np*16 + (l & 7) + ((l >> 4) & 1) * 8) * 80
                             + kt*32 + ((l >> 3) & 1) * 16;
                LDSM4(fbh[np*2][0], fbh[np*2][1], fbh[np*2+1][0], fbh[np*2+1][1], bBH + off);
                LDSM4(fbl[np*2][0], fbl[np*2][1], fbl[np*2+1][0], fbl[np*2+1][1], bBL + off);
            }
#pragma unroll
            for (int mt = 0; mt < 2; mt++)
#pragma unroll
                for (int nt = 0; nt < 4; nt++) {
                    MMA16816(acc[mt][nt], fah[mt], fbh[nt]);
                    MMA16816(acc[mt][nt], fah[mt], fbl[nt]);
                    MMA16816(acc[mt][nt], fal[mt], fbh[nt]);
                }
        }
    }

    const int gr = l >> 2, tc = l & 3;
#pragma unroll
    for (int mt = 0; mt < 2; mt++)
#pragma unroll
        for (int nt = 0; nt < 4; nt++) {
            int m = wm + mt*16 + gr;
            int n = wn + nt*8 + tc*2;
            float* op = g_att + (size_t)(b*SS + c*CHK + m)*VDIM + h*HD + n;
            *(float2*)op = make_float2(acc[mt][nt][0], acc[mt][nt][1]);
            *(float2*)(op + (size_t)8*VDIM) = make_float2(acc[mt][nt][2], acc[mt][nt][3]);
        }
}

// ================= pass2b =================
#define P2B_SMEM ((128*17*2 + 128*64 + 128*129 + 128) * 4)
__global__ __launch_bounds__(256) void pass2b_kernel()
{
    extern __shared__ float sm[];
    float* qs  = sm;
    float* ksm = qs + 128*17;
    float* vsm = ksm + 128*17;
    float* Am  = vsm + 128*64;
    float* rs  = Am + 128*129;
    const int c = blockIdx.x, h = blockIdx.y, b = blockIdx.z;
    const int tid = threadIdx.x;
    {
        int t = tid >> 1, f0 = (tid & 1) * 8;
        const float* qp = g_qkv + (size_t)(b*SS + c*CHK + t)*QKVW + h*FF + f0;
        const float* kp = qp + OFF_K;
        float4 a = *(const float4*)qp;  float4 a2 = *(const float4*)(qp + 4);
        float4 kk = *(const float4*)kp; float4 k2 = *(const float4*)(kp + 4);
        qs[t*17+f0+0]=a.x;  qs[t*17+f0+1]=a.y;  qs[t*17+f0+2]=a.z;  qs[t*17+f0+3]=a.w;
        qs[t*17+f0+4]=a2.x; qs[t*17+f0+5]=a2.y; qs[t*17+f0+6]=a2.z; qs[t*17+f0+7]=a2.w;
        ksm[t*17+f0+0]=kk.x; ksm[t*17+f0+1]=kk.y; ksm[t*17+f0+2]=kk.z; ksm[t*17+f0+3]=kk.w;
        ksm[t*17+f0+4]=k2.x; ksm[t*17+f0+5]=k2.y; ksm[t*17+f0+6]=k2.z; ksm[t*17+f0+7]=k2.w;
    }
    for (int idx = tid; idx < CHK*16; idx += 256) {
        int t = idx >> 4, d4 = (idx & 15) * 4;
        *(float4*)&vsm[t*64 + d4] =
            *(const float4*)(g_qkv + (size_t)(b*SS + c*CHK + t)*QKVW + OFF_V + h*HD + d4);
    }
    __syncthreads();

    {
        const int t = tid >> 1, u0 = (tid & 1) * 64;
        float qreg[16];
#pragma unroll
        for (int f = 0; f < 16; f++) qreg[f] = qs[t*17+f];
        float rsum = 0.f;
        for (int uu = 0; uu < 64; uu++) {
            int u = u0 + uu;
            float s = 0.f;
#pragma unroll
            for (int f = 0; f < 16; f++)
                s = fmaf(qreg[f], ksm[u*17+f], s);
            float a = (u <= t) ? fmaf(s, fmaf(s, 0.03125f, 0.25f), 1.0f) : 0.f;
            Am[t*129 + u] = a;
            rsum += a;
        }
        rsum += __shfl_xor_sync(0xffffffffu, rsum, 1);
        if ((tid & 1) == 0) rs[t] = rsum;
    }
    __syncthreads();

    {
        const int t = tid >> 1, d0 = (tid & 1) * 32;
        float4 acc[8];
#pragma unroll
        for (int g = 0; g < 8; g++) acc[g] = make_float4(0.f,0.f,0.f,0.f);
        const int tmax = (tid >> 5) * 16 + 15;
        for (int u = 0; u <= tmax; u++) {
            float a = Am[t*129 + u];
            const float4* vr = (const float4*)&vsm[u*64 + d0];
#pragma unroll
            for (int g = 0; g < 8; g++) {
                float4 vv = vr[g];
                acc[g].x = fmaf(a, vv.x, acc[g].x);
                acc[g].y = fmaf(a, vv.y, acc[g].y);
                acc[g].z = fmaf(a, vv.z, acc[g].z);
                acc[g].w = fmaf(a, vv.w, acc[g].w);
            }
        }
        float den = rs[t] + g_den[(size_t)(b*HH + h)*SS + c*CHK + t] + 1e-6f;
        float inv = 1.0f / den;
        const size_t obase = (size_t)(b*SS + c*CHK + t)*VDIM + h*HD + d0;
        const float* ip = g_att + obase;
#pragma unroll
        for (int g = 0; g < 8; g++) {
            float4 cur = *(const float4*)(ip + g*4);
            float4 r;
            r.x = (cur.x + acc[g].x) * inv;
            r.y = (cur.y + acc[g].y) * inv;
            r.z = (cur.z + acc[g].z) * inv;
            r.w = (cur.w + acc[g].w) * inv;
            __nv_bfloat16 h0 = __float2bfloat16(r.x), h1 = __float2bfloat16(r.y);
            __nv_bfloat16 h2 = __float2bfloat16(r.z), h3 = __float2bfloat16(r.w);
            __nv_bfloat162 ph0 = __halves2bfloat162(h0, h1);
            __nv_bfloat162 ph1 = __halves2bfloat162(h2, h3);
            __nv_bfloat162 pl0 = __halves2bfloat162(__float2bfloat16(r.x - __bfloat162float(h0)),
                                                    __float2bfloat16(r.y - __bfloat162float(h1)));
            __nv_bfloat162 pl1 = __halves2bfloat162(__float2bfloat16(r.z - __bfloat162float(h2)),
                                                    __float2bfloat16(r.w - __bfloat162float(h3)));
            *(__nv_bfloat162*)(g_xhi + obase + g*4)     = ph0;
            *(__nv_bfloat162*)(g_xhi + obase + g*4 + 2) = ph1;
            *(__nv_bfloat162*)(g_xlo + obase + g*4)     = pl0;
            *(__nv_bfloat162*)(g_xlo + obase + g*4 + 2) = pl1;
        }
    }
}

extern "C" void kernel_launch(void* const* d_in, const int* in_sizes, int n_in,
                              void* d_out, int out_size)
{
    (void)in_sizes; (void)n_in;
    const float* x    = (const float*)d_in[0];
    const float* kv0  = (const float*)d_in[1];
    const float* kst0 = (const float*)d_in[2];
    const float* Wq   = (const float*)d_in[3];
    const float* bq   = (const float*)d_in[4];
    const float* Wk   = (const float*)d_in[5];
    const float* bk   = (const float*)d_in[6];
    const float* Wv   = (const float*)d_in[7];
    const float* bv   = (const float*)d_in[8];
    const float* Wo   = (const float*)d_in[9];
    const float* bo   = (const float*)d_in[10];

    float* y = (float*)d_out;
    float* kvf = nullptr;
    float* kstf = nullptr;
    if (out_size >= Y_ELEMS + KV_ELEMS + KST_ELEMS) {
        kvf  = y + Y_ELEMS;
        kstf = kvf + KV_ELEMS;
    }

    float *pqkv, *pbqkv;
    __nv_bfloat16 *xhi, *xlo, *wqh, *wql, *woh, *wol;
    cudaGetSymbolAddress((void**)&pqkv,  g_qkv);
    cudaGetSymbolAddress((void**)&pbqkv, g_bqkv);
    cudaGetSymbolAddress((void**)&xhi, g_xhi);
    cudaGetSymbolAddress((void**)&xlo, g_xlo);
    cudaGetSymbolAddress((void**)&wqh, g_wqh);
    cudaGetSymbolAddress((void**)&wql, g_wql);
    cudaGetSymbolAddress((void**)&woh, g_woh);
    cudaGetSymbolAddress((void**)&wol, g_wol);

    cudaFuncSetAttribute(gemm_bf16, cudaFuncAttributeMaxDynamicSharedMemorySize, GS_SMEM);
    cudaFuncSetAttribute(pass1_kernel, cudaFuncAttributeMaxDynamicSharedMemorySize, P1_SMEM);
    cudaFuncSetAttribute(pass2a_kernel, cudaFuncAttributeMaxDynamicSharedMemorySize, P2A_SMEM);
    cudaFuncSetAttribute(pass2b_kernel, cudaFuncAttributeMaxDynamicSharedMemorySize, P2B_SMEM);

    const int M = BB * SS;  // 8192

    cvt_split<<<(M * DM) / 1024 + 1, 256>>>(x, xhi, xlo, M * DM, bq, bk, bv, pbqkv);
    cvt_wT_all<<<dim3(32, 32, 4), 256>>>(Wq, Wk, Wv, Wo, wqh, wql, woh, wol);
    gemm_bf16<<<dim3(QKVW/64, M/128), 256, GS_SMEM>>>(xhi, xlo, wqh, wql, pbqkv, pqkv, QKVW, DM);

    pass1_kernel<<<dim3(NC, HH, BB), 512, P1_SMEM>>>();
    prefix_kernel<<<dim3(HH, BB, 8), 256>>>(kv0, kst0, kvf, kstf);
    pass2a_kernel<<<dim3(NC, HH, BB), 256, P2A_SMEM>>>();
    pass2b_kernel<<<dim3(NC, HH, BB), 256, P2B_SMEM>>>();

    gemm_bf16<<<dim3(DM/64, M/128), 256, GS_SMEM>>>(xhi, xlo, woh, wol, bo, y, DM, VDIM);
}

// round 17
// speedup vs baseline: 2.2794x; 1.0448x over previous
#include <cuda_runtime.h>
#include <cuda_bf16.h>
#include <cstdint>

#define BB 4
#define SS 2048
#define DM 1024
#define HH 16
#define FF 16
#define HD 64
#define EXPD 273
#define NC 16
#define CHK 128
#define QKDIM (HH*FF)
#define VDIM  (HH*HD)
#define QKVW  1536
#define OFF_K 256
#define OFF_V 512
#define C2 0.17677669529663687f

#define Y_ELEMS   (BB*SS*DM)
#define KV_ELEMS  (BB*HH*EXPD*HD)
#define KST_ELEMS (BB*HH*EXPD)

__device__ float g_qkv[BB*SS*QKVW];
__device__ float g_S[BB*HH*NC*EXPD*HD];
__device__ float g_z[BB*HH*NC*EXPD];
__device__ float g_den[BB*HH*SS];
__device__ float g_att[BB*SS*VDIM];
__device__ float g_bqkv[QKVW];
__device__ __nv_bfloat16 g_xhi[BB*SS*DM];
__device__ __nv_bfloat16 g_xlo[BB*SS*DM];
__device__ __nv_bfloat16 g_wqh[QKVW*DM];
__device__ __nv_bfloat16 g_wql[QKVW*DM];
__device__ __nv_bfloat16 g_woh[DM*DM];
__device__ __nv_bfloat16 g_wol[DM*DM];

// ---------------- helpers ----------------
__device__ __forceinline__ uint32_t su32(const void* p) {
    uint32_t a;
    asm("{ .reg .u64 t; cvta.to.shared.u64 t, %1; cvt.u32.u64 %0, t; }" : "=r"(a) : "l"(p));
    return a;
}
__device__ __forceinline__ uint32_t swz(uint32_t o) { return o ^ ((o >> 3) & 0x70); }
__device__ __forceinline__ void cpa16(uint32_t s, const void* g) {
    asm volatile("cp.async.cg.shared.global [%0], [%1], 16;" :: "r"(s), "l"(g));
}

#define LDSM4(r0,r1,r2,r3, addr) \
    asm volatile("ldmatrix.sync.aligned.m8n8.x4.shared.b16 {%0,%1,%2,%3}, [%4];" \
                 : "=r"(r0),"=r"(r1),"=r"(r2),"=r"(r3) : "r"(addr))
#define LDSM4T(r0,r1,r2,r3, addr) \
    asm volatile("ldmatrix.sync.aligned.m8n8.x4.trans.shared.b16 {%0,%1,%2,%3}, [%4];" \
                 : "=r"(r0),"=r"(r1),"=r"(r2),"=r"(r3) : "r"(addr))
#define LDSM2(r0,r1, addr) \
    asm volatile("ldmatrix.sync.aligned.m8n8.x2.shared.b16 {%0,%1}, [%2];" \
                 : "=r"(r0),"=r"(r1) : "r"(addr))
#define MMA16816(d, a, b) \
    asm volatile("mma.sync.aligned.m16n8k16.row.col.f32.bf16.bf16.f32 " \
                 "{%0,%1,%2,%3},{%4,%5,%6,%7},{%8,%9},{%0,%1,%2,%3};" \
                 : "+f"((d)[0]),"+f"((d)[1]),"+f"((d)[2]),"+f"((d)[3]) \
                 : "r"((a)[0]),"r"((a)[1]),"r"((a)[2]),"r"((a)[3]),"r"((b)[0]),"r"((b)[1]))

__device__ __forceinline__ void split_store(__nv_bfloat16* hp, __nv_bfloat16* lp,
                                            float p0, float p1)
{
    __nv_bfloat16 h0 = __float2bfloat16(p0), h1 = __float2bfloat16(p1);
    *(__nv_bfloat162*)hp = __halves2bfloat162(h0, h1);
    *(__nv_bfloat162*)lp = __halves2bfloat162(__float2bfloat16(p0 - __bfloat162float(h0)),
                                              __float2bfloat16(p1 - __bfloat162float(h1)));
}

// ---------------- conversions ----------------
__global__ void cvt_split(const float* __restrict__ in,
                          __nv_bfloat16* __restrict__ hi,
                          __nv_bfloat16* __restrict__ lo, int n)
{
    int i = (blockIdx.x * blockDim.x + threadIdx.x) * 4;
    if (i >= n) return;
    float4 v = *(const float4*)(in + i);
    split_store(hi + i, lo + i, v.x, v.y);
    split_store(hi + i + 2, lo + i + 2, v.z, v.w);
}

__global__ void bias_concat(const float* __restrict__ b0, const float* __restrict__ b1,
                            const float* __restrict__ b2, float* __restrict__ bout)
{
    int t = threadIdx.x;
    if (t < QKDIM) { bout[t] = b0[t]; bout[OFF_K + t] = b1[t]; }
    for (int i = t; i < VDIM; i += 256) bout[OFF_V + i] = b2[i];
}

__global__ void cvt_wT_all(const float* __restrict__ Wq, const float* __restrict__ Wk,
                           const float* __restrict__ Wv, const float* __restrict__ Wo,
                           __nv_bfloat16* __restrict__ qh, __nv_bfloat16* __restrict__ ql,
                           __nv_bfloat16* __restrict__ oh, __nv_bfloat16* __restrict__ ol)
{
    __shared__ float t[32][33];
    const int z = blockIdx.z;
    const float* W; __nv_bfloat16 *Th, *Tl; int N, rowoff;
    if (z == 0)      { W = Wq; Th = qh; Tl = ql; N = QKDIM; rowoff = 0; }
    else if (z == 1) { W = Wk; Th = qh; Tl = ql; N = QKDIM; rowoff = OFF_K; }
    else if (z == 2) { W = Wv; Th = qh; Tl = ql; N = VDIM;  rowoff = OFF_V; }
    else             { W = Wo; Th = oh; Tl = ol; N = DM;    rowoff = 0; }
    const int bx = blockIdx.x * 32, by = blockIdx.y * 32;
    if (bx >= N) return;
    const int tx = threadIdx.x & 31, ty = threadIdx.x >> 5;
#pragma unroll
    for (int r = 0; r < 4; r++)
        t[ty + 8 * r][tx] = W[(size_t)(by + ty + 8 * r) * N + bx + tx];
    __syncthreads();
#pragma unroll
    for (int r = 0; r < 4; r++) {
        float v = t[tx][ty + 8 * r];
        __nv_bfloat16 h = __float2bfloat16(v);
        size_t o = (size_t)(rowoff + bx + ty + 8 * r) * DM + by + tx;
        Th[o] = h;
        Tl[o] = __float2bfloat16(v - __bfloat162float(h));
    }
}

// ---------------- bf16 split GEMM, cp.async pipeline ----------------
#define STG 49152
#define GS_SMEM (2*STG)

#define ISSUE_STAGE(k0, b_) do { \
    uint32_t pa_h = sbase + (b_) * STG; \
    uint32_t pa_l = pa_h + 16384; \
    uint32_t pb_h = pa_h + 32768; \
    uint32_t pb_l = pa_h + 40960; \
    const __nv_bfloat16* aph = Ah + (size_t)(bm + arow) * K + (k0) + acol; \
    const __nv_bfloat16* apl = Al + (size_t)(bm + arow) * K + (k0) + acol; \
    _Pragma("unroll") for (int j = 0; j < 4; j++) { \
        uint32_t off = swz(arow * 128 + acol * 2 + j * 16); \
        cpa16(pa_h + off, aph + j * 8); \
        cpa16(pa_l + off, apl + j * 8); } \
    const __nv_bfloat16* bph = Bh + (size_t)(bn + brow) * K + (k0) + bcol; \
    const __nv_bfloat16* bpl = Bl + (size_t)(bn + brow) * K + (k0) + bcol; \
    _Pragma("unroll") for (int j = 0; j < 2; j++) { \
        uint32_t off = swz(brow * 128 + bcol * 2 + j * 16); \
        cpa16(pb_h + off, bph + j * 8); \
        cpa16(pb_l + off, bpl + j * 8); } \
    asm volatile("cp.async.commit_group;" ::: "memory"); \
} while (0)

__global__ __launch_bounds__(256, 2) void gemm_bf16(
    const __nv_bfloat16* __restrict__ Ah, const __nv_bfloat16* __restrict__ Al,
    const __nv_bfloat16* __restrict__ Bh, const __nv_bfloat16* __restrict__ Bl,
    const float* __restrict__ bias, float* __restrict__ C, int N, int K)
{
    extern __shared__ char smn[];
    const int tid = threadIdx.x, l = tid & 31, w = tid >> 5;
    const int bm = blockIdx.y * 128, bn = blockIdx.x * 64;
    const int wm = (w >> 1) * 32, wn = (w & 1) * 32;
    const uint32_t sbase = su32(smn);

    const int arow = tid >> 1, acol = (tid & 1) * 32;
    const int brow = tid >> 2, bcol = (tid & 3) * 16;

    float acc[2][4][4] = {};
    const int nstep = K / 64;

    ISSUE_STAGE(0, 0);
    int buf = 0;
    for (int s = 0; s < nstep; s++) {
        if (s + 1 < nstep) {
            ISSUE_STAGE((s + 1) * 64, buf ^ 1);
            asm volatile("cp.async.wait_group 1;" ::: "memory");
        } else {
            asm volatile("cp.async.wait_group 0;" ::: "memory");
        }
        __syncthreads();
        uint32_t base_ah = sbase + buf * STG;
        uint32_t base_al = base_ah + 16384;
        uint32_t base_bh = base_ah + 32768;
        uint32_t base_bl = base_ah + 40960;
#pragma unroll
        for (int kc = 0; kc < 4; kc++) {
            uint32_t fah[2][4], fal[2][4], fbh[4][2], fbl[4][2];
#pragma unroll
            for (int mt = 0; mt < 2; mt++) {
                uint32_t off = swz((wm + mt * 16 + (l & 15)) * 128 + kc * 32 + (l >> 4) * 16);
                LDSM4(fah[mt][0], fah[mt][1], fah[mt][2], fah[mt][3], base_ah + off);
                LDSM4(fal[mt][0], fal[mt][1], fal[mt][2], fal[mt][3], base_al + off);
            }
#pragma unroll
            for (int np = 0; np < 2; np++) {
                uint32_t off = swz((wn + np * 16 + (l & 7) + ((l >> 4) & 1) * 8) * 128
                                   + kc * 32 + ((l >> 3) & 1) * 16);
                LDSM4(fbh[np*2][0], fbh[np*2][1], fbh[np*2+1][0], fbh[np*2+1][1], base_bh + off);
                LDSM4(fbl[np*2][0], fbl[np*2][1], fbl[np*2+1][0], fbl[np*2+1][1], base_bl + off);
            }
#pragma unroll
            for (int mt = 0; mt < 2; mt++)
#pragma unroll
                for (int nt = 0; nt < 4; nt++) {
                    MMA16816(acc[mt][nt], fah[mt], fbh[nt]);
                    MMA16816(acc[mt][nt], fah[mt], fbl[nt]);
                    MMA16816(acc[mt][nt], fal[mt], fbh[nt]);
                }
        }
        __syncthreads();
        buf ^= 1;
    }

    const int gr = l >> 2, tc = l & 3;
#pragma unroll
    for (int mt = 0; mt < 2; mt++)
#pragma unroll
        for (int nt = 0; nt < 4; nt++) {
            int m = bm + wm + mt * 16 + gr;
            int n = bn + wn + nt * 8 + tc * 2;
            float2 bv = *(const float2*)(bias + n);
            float2 o0 = make_float2(acc[mt][nt][0] + bv.x, acc[mt][nt][1] + bv.y);
            float2 o1 = make_float2(acc[mt][nt][2] + bv.x, acc[mt][nt][3] + bv.y);
            *(float2*)(C + (size_t)m * N + n) = o0;
            *(float2*)(C + (size_t)(m + 8) * N + n) = o1;
        }
}

// ================= pass1 via mma.sync + trans-A (unchanged) =================
#define P1_SMEM 199680
__global__ __launch_bounds__(512, 1) void pass1_kernel()
{
    extern __shared__ char sm1[];
    float* kraw = (float*)sm1;
    __nv_bfloat16* PhH = (__nv_bfloat16*)(sm1 + 9216);
    __nv_bfloat16* PhL = (__nv_bfloat16*)(sm1 + 84992);
    __nv_bfloat16* BtH = (__nv_bfloat16*)(sm1 + 160768);
    __nv_bfloat16* BtL = (__nv_bfloat16*)(sm1 + 180224);
    const int c = blockIdx.x, h = blockIdx.y, b = blockIdx.z;
    const int tid = threadIdx.x, l = tid & 31, w = tid >> 5;
    const int wm_g = w & 1, wn_g = w >> 1;

    if (tid < 256) {
        int t = tid >> 1, f0 = (tid & 1) * 8;
        const float* kp = g_qkv + (size_t)(b*SS + c*CHK + t)*QKVW + OFF_K + h*FF + f0;
        float4 k0 = *(const float4*)kp, k1 = *(const float4*)(kp + 4);
        kraw[t*18+f0+0]=k0.x; kraw[t*18+f0+1]=k0.y; kraw[t*18+f0+2]=k0.z; kraw[t*18+f0+3]=k0.w;
        kraw[t*18+f0+4]=k1.x; kraw[t*18+f0+5]=k1.y; kraw[t*18+f0+6]=k1.z; kraw[t*18+f0+7]=k1.w;
    }
    for (int idx = tid; idx < 128*16; idx += 512) {
        int tt = idx >> 4, d4 = (idx & 15) * 4;
        float4 v = *(const float4*)(g_qkv + (size_t)(b*SS + c*CHK + tt)*QKVW + OFF_V + h*HD + d4);
        float e4[4] = {v.x, v.y, v.z, v.w};
#pragma unroll
        for (int q2 = 0; q2 < 4; q2++) {
            __nv_bfloat16 hh = __float2bfloat16(e4[q2]);
            BtH[(d4+q2)*152 + tt] = hh;
            BtL[(d4+q2)*152 + tt] = __float2bfloat16(e4[q2] - __bfloat162float(hh));
        }
    }
    __syncthreads();

    const size_t zbase = ((size_t)((b*HH + h)*NC + c)) * EXPD;
    if (tid < EXPD) {
        int e = tid;
        float s = 0.f;
        if (e == 0) s = (float)CHK;
        else if (e < 17) {
            for (int t = 0; t < CHK; t++) s += kraw[t*18 + e - 1];
            s *= 0.5f;
        } else {
            int p = e - 17, i = p >> 4, j = p & 15;
            for (int t = 0; t < CHK; t++) s += kraw[t*18 + i] * kraw[t*18 + j];
            s *= C2;
        }
        g_z[zbase + e] = s;
    }

    {
        const int t = tid & 127, q = tid >> 7;
        float kr[16];
#pragma unroll
        for (int f = 0; f < 16; f++) kr[f] = kraw[t*18 + f];
        __nv_bfloat16* ph = PhH + t*296;
        __nv_bfloat16* pl = PhL + t*296;
        if (q == 0) {
#pragma unroll
            for (int ep = 0; ep < 72; ep += 2) {
                float p0, p1;
                { int e = ep;
                  p0 = (e == 0) ? 1.0f : (e < 17 ? 0.5f*kr[e-1]
                        : C2*kr[(e-17)>>4]*kr[(e-17)&15]); }
                { int e = ep + 1;
                  p1 = (e < 17) ? 0.5f*kr[e-1] : C2*kr[(e-17)>>4]*kr[(e-17)&15]; }
                split_store(ph + ep, pl + ep, p0, p1);
            }
        } else if (q == 1) {
#pragma unroll
            for (int ep = 72; ep < 144; ep += 2)
                split_store(ph + ep, pl + ep,
                            C2*kr[(ep-17)>>4]*kr[(ep-17)&15],
                            C2*kr[(ep-16)>>4]*kr[(ep-16)&15]);
        } else if (q == 2) {
#pragma unroll
            for (int ep = 144; ep < 216; ep += 2)
                split_store(ph + ep, pl + ep,
                            C2*kr[(ep-17)>>4]*kr[(ep-17)&15],
                            C2*kr[(ep-16)>>4]*kr[(ep-16)&15]);
        } else {
#pragma unroll
            for (int ep = 216; ep < 288; ep += 2)
                split_store(ph + ep, pl + ep,
                            (ep     < EXPD) ? C2*kr[(ep-17)>>4]*kr[(ep-17)&15] : 0.f,
                            (ep + 1 < EXPD) ? C2*kr[(ep-16)>>4]*kr[(ep-16)&15] : 0.f);
        }
    }
    __syncthreads();

    float acc[9][4] = {};
    const uint32_t bPH = su32(PhH), bPL = su32(PhL);
    const uint32_t bBH = su32(BtH), bBL = su32(BtL);
    const uint32_t boff0 = (wn_g*8 + (l & 7)) * 304 + ((l >> 3) & 1) * 16;
    const uint32_t aoff0 = ((l & 7) + ((l >> 4) & 1) * 8) * 592 + ((l >> 3) & 1) * 16;
#pragma unroll
    for (int kt = 0; kt < 8; kt++) {
        uint32_t fbh[2], fbl[2];
        LDSM2(fbh[0], fbh[1], bBH + boff0 + kt*32);
        LDSM2(fbl[0], fbl[1], bBL + boff0 + kt*32);
#pragma unroll
        for (int i = 0; i < 9; i++) {
            int m_base = (wm_g*9 + i) * 16;
            uint32_t aoff = aoff0 + kt*16*592 + m_base*2;
            uint32_t fah[4], fal[4];
            LDSM4T(fah[0], fah[1], fah[2], fah[3], bPH + aoff);
            LDSM4T(fal[0], fal[1], fal[2], fal[3], bPL + aoff);
            MMA16816(acc[i], fah, fbh);
            MMA16816(acc[i], fah, fbl);
            MMA16816(acc[i], fal, fbh);
        }
    }

    const size_t Sbase = ((size_t)((b*HH + h)*NC + c)) * EXPD * HD;
    const int gr = l >> 2, tc = l & 3;
    const int d = wn_g*8 + tc*2;
#pragma unroll
    for (int i = 0; i < 9; i++) {
        int e1 = (wm_g*9 + i)*16 + gr, e2 = e1 + 8;
        if (e1 < EXPD)
            *(float2*)(g_S + Sbase + (size_t)e1*HD + d) = make_float2(acc[i][0], acc[i][1]);
        if (e2 < EXPD)
            *(float2*)(g_S + Sbase + (size_t)e2*HD + d) = make_float2(acc[i][2], acc[i][3]);
    }
}

// ================= prefix (8-way segment split) =================
__global__ __launch_bounds__(256) void prefix_kernel(
    const float* __restrict__ kv0, const float* __restrict__ kst0,
    float* __restrict__ out_kv, float* __restrict__ out_kst)
{
    const int h = blockIdx.x, b = blockIdx.y, seg = blockIdx.z;
    const int pair = b*HH + h;
    const int tid = threadIdx.x;
    const int seglen = EXPD*HD/8;
    for (int idx = seg*seglen + tid; idx < (seg+1)*seglen; idx += 256) {
        float run = kv0[(size_t)pair*EXPD*HD + idx];
        float* p = g_S + ((size_t)pair*NC)*EXPD*HD + idx;
#pragma unroll
        for (int cc = 0; cc < NC; cc++) {
            float sv = p[(size_t)cc*EXPD*HD];
            p[(size_t)cc*EXPD*HD] = run;
            run += sv;
        }
        if (out_kv) out_kv[(size_t)pair*EXPD*HD + idx] = run;
    }
    if (seg == 0) {
        for (int idx = tid; idx < EXPD; idx += 256) {
            float run = kst0[(size_t)pair*EXPD + idx];
            float* p = g_z + ((size_t)pair*NC)*EXPD + idx;
#pragma unroll
            for (int cc = 0; cc < NC; cc++) {
                float sv = p[(size_t)cc*EXPD];
                p[(size_t)cc*EXPD] = run;
                run += sv;
            }
            if (out_kst) out_kst[(size_t)pair*EXPD + idx] = run;
        }
    }
}

// ================= pass2a via mma.sync (unchanged) =================
#define P2A_SMEM 172160
__global__ __launch_bounds__(256, 1) void pass2a_kernel()
{
    extern __shared__ char smp[];
    float* qraw = (float*)smp;
    __nv_bfloat16* PhiH = (__nv_bfloat16*)(smp + 9216);
    __nv_bfloat16* PhiL = (__nv_bfloat16*)(smp + 84992);
    float* zs = (float*)(smp + 160768);
    __nv_bfloat16* BsH = (__nv_bfloat16*)(smp + 161920);
    __nv_bfloat16* BsL = (__nv_bfloat16*)(smp + 167040);
    const int c = blockIdx.x, h = blockIdx.y, b = blockIdx.z;
    const int tid = threadIdx.x, l = tid & 31, w = tid >> 5;
    const int wm = (w >> 1) * 32, wn = (w & 1) * 32;

    {
        int t = tid >> 1, f0 = (tid & 1) * 8;
        const float* qp = g_qkv + (size_t)(b*SS + c*CHK + t)*QKVW + h*FF + f0;
        float4 a = *(const float4*)qp, a2 = *(const float4*)(qp + 4);
        qraw[t*18+f0+0]=a.x;  qraw[t*18+f0+1]=a.y;  qraw[t*18+f0+2]=a.z;  qraw[t*18+f0+3]=a.w;
        qraw[t*18+f0+4]=a2.x; qraw[t*18+f0+5]=a2.y; qraw[t*18+f0+6]=a2.z; qraw[t*18+f0+7]=a2.w;
    }
    {
        const size_t zb = ((size_t)((b*HH + h)*NC + c)) * EXPD;
        for (int e = tid; e < 288; e += 256)
            zs[e] = (e < EXPD) ? g_z[zb + e] : 0.f;
    }
    __syncthreads();

    {
        const int t = tid >> 1, half = tid & 1;
        float qr[16];
#pragma unroll
        for (int f = 0; f < 16; f++) qr[f] = qraw[t*18 + f];
        float den = 0.f;
        __nv_bfloat16* ph = PhiH + t*296;
        __nv_bfloat16* pl = PhiL + t*296;
        if (half == 0) {
#pragma unroll
            for (int ep = 0; ep < 144; ep += 2) {
                float p0, p1;
                { int e = ep;
                  p0 = (e == 0) ? 1.0f : (e < 17 ? 0.5f*qr[e-1]
                        : C2*qr[(e-17)>>4]*qr[(e-17)&15]); }
                { int e = ep + 1;
                  p1 = (e < 17) ? 0.5f*qr[e-1]
                        : C2*qr[(e-17)>>4]*qr[(e-17)&15]; }
                den += p0*zs[ep] + p1*zs[ep+1];
                split_store(ph + ep, pl + ep, p0, p1);
            }
        } else {
#pragma unroll
            for (int ep = 144; ep < 288; ep += 2) {
                float p0 = (ep     < EXPD) ? C2*qr[(ep-17)>>4]*qr[(ep-17)&15] : 0.f;
                float p1 = (ep + 1 < EXPD) ? C2*qr[(ep-16)>>4]*qr[(ep-16)&15] : 0.f;
                den += p0*zs[ep] + p1*zs[ep+1];
                split_store(ph + ep, pl + ep, p0, p1);
            }
        }
        den += __shfl_xor_sync(0xffffffffu, den, 1);
        if (half == 0)
            g_den[(size_t)(b*HH + h)*SS + c*CHK + t] = den;
    }

    float acc[2][4][4] = {};
    const size_t Sbase = ((size_t)((b*HH + h)*NC + c)) * EXPD * HD;

    for (int e0 = 0; e0 < 288; e0 += 32) {
        __syncthreads();
        {
            int kk = tid >> 3, d8 = (tid & 7) * 8;
            int e = e0 + kk;
            float4 v0, v1;
            if (e < EXPD) {
                v0 = *(const float4*)(g_S + Sbase + (size_t)e*HD + d8);
                v1 = *(const float4*)(g_S + Sbase + (size_t)e*HD + d8 + 4);
            } else {
                v0 = make_float4(0.f,0.f,0.f,0.f);
                v1 = v0;
            }
            float ev[8] = {v0.x, v0.y, v0.z, v0.w, v1.x, v1.y, v1.z, v1.w};
#pragma unroll
            for (int q2 = 0; q2 < 8; q2++) {
                __nv_bfloat16 hh = __float2bfloat16(ev[q2]);
                BsH[(d8+q2)*40 + kk] = hh;
                BsL[(d8+q2)*40 + kk] = __float2bfloat16(ev[q2] - __bfloat162float(hh));
            }
        }
        __syncthreads();
        uint32_t bPH = su32(PhiH), bPL = su32(PhiL), bBH = su32(BsH), bBL = su32(BsL);
#pragma unroll
        for (int kt = 0; kt < 2; kt++) {
            uint32_t fah[2][4], fal[2][4], fbh[4][2], fbl[4][2];
#pragma unroll
            for (int mt = 0; mt < 2; mt++) {
                uint32_t off = (wm + mt*16 + (l & 15)) * 592 + (e0 + kt*16) * 2 + (l >> 4) * 16;
                LDSM4(fah[mt][0], fah[mt][1], fah[mt][2], fah[mt][3], bPH + off);
                LDSM4(fal[mt][0], fal[mt][1], fal[mt][2], fal[mt][3], bPL + off);
            }
#pragma unroll
            for (int np = 0; np < 2; np++) {
                uint32_t off = (wn + np*16 + (l & 7) + ((l >> 4) & 1) * 8) * 80
                             + kt*32 + ((l >> 3) & 1) * 16;
                LDSM4(fbh[np*2][0], fbh[np*2][1], fbh[np*2+1][0], fbh[np*2+1][1], bBH + off);
                LDSM4(fbl[np*2][0], fbl[np*2][1], fbl[np*2+1][0], fbl[np*2+1][1], bBL + off);
            }
#pragma unroll
            for (int mt = 0; mt < 2; mt++)
#pragma unroll
                for (int nt = 0; nt < 4; nt++) {
                    MMA16816(acc[mt][nt], fah[mt], fbh[nt]);
                    MMA16816(acc[mt][nt], fah[mt], fbl[nt]);
                    MMA16816(acc[mt][nt], fal[mt], fbh[nt]);
                }
        }
    }

    const int gr = l >> 2, tc = l & 3;
#pragma unroll
    for (int mt = 0; mt < 2; mt++)
#pragma unroll
        for (int nt = 0; nt < 4; nt++) {
            int m = wm + mt*16 + gr;
            int n = wn + nt*8 + tc*2;
            float* op = g_att + (size_t)(b*SS + c*CHK + m)*VDIM + h*HD + n;
            *(float2*)op = make_float2(acc[mt][nt][0], acc[mt][nt][1]);
            *(float2*)(op + (size_t)8*VDIM) = make_float2(acc[mt][nt][2], acc[mt][nt][3]);
        }
}

// ================= pass2b via mma.sync =================
// smem: qh 6144 | ql 6144 | kh 6144 | kl 6144 | VtH 17408 | VtL 17408
//       | AsH 34816 | AsL 34816 | rs4 2048  = 131072
#define P2B_SMEM 131072
__global__ __launch_bounds__(256, 1) void pass2b_kernel()
{
    extern __shared__ char smb[];
    __nv_bfloat16* qh = (__nv_bfloat16*)smb;
    __nv_bfloat16* ql = (__nv_bfloat16*)(smb + 6144);
    __nv_bfloat16* kh = (__nv_bfloat16*)(smb + 12288);
    __nv_bfloat16* kl = (__nv_bfloat16*)(smb + 18432);
    __nv_bfloat16* VtH = (__nv_bfloat16*)(smb + 24576);
    __nv_bfloat16* VtL = (__nv_bfloat16*)(smb + 41984);
    __nv_bfloat16* AsH = (__nv_bfloat16*)(smb + 59392);
    __nv_bfloat16* AsL = (__nv_bfloat16*)(smb + 94208);
    float* rs4 = (float*)(smb + 129024);
    const int c = blockIdx.x, h = blockIdx.y, b = blockIdx.z;
    const int tid = threadIdx.x, l = tid & 31, w = tid >> 5;
    const int gr = l >> 2, tc = l & 3;

    // load q,k hi/lo [t][24]
    {
        int t = tid >> 1, f0 = (tid & 1) * 8;
        const float* qp = g_qkv + (size_t)(b*SS + c*CHK + t)*QKVW + h*FF + f0;
        const float* kp = qp + OFF_K;
        float4 a = *(const float4*)qp, a2 = *(const float4*)(qp + 4);
        float4 kk = *(const float4*)kp, k2 = *(const float4*)(kp + 4);
        split_store(qh + t*24+f0,   ql + t*24+f0,   a.x, a.y);
        split_store(qh + t*24+f0+2, ql + t*24+f0+2, a.z, a.w);
        split_store(qh + t*24+f0+4, ql + t*24+f0+4, a2.x, a2.y);
        split_store(qh + t*24+f0+6, ql + t*24+f0+6, a2.z, a2.w);
        split_store(kh + t*24+f0,   kl + t*24+f0,   kk.x, kk.y);
        split_store(kh + t*24+f0+2, kl + t*24+f0+2, kk.z, kk.w);
        split_store(kh + t*24+f0+4, kl + t*24+f0+4, k2.x, k2.y);
        split_store(kh + t*24+f0+6, kl + t*24+f0+6, k2.z, k2.w);
    }
    // V^T [d][136] hi/lo
    for (int idx = tid; idx < 128*16; idx += 256) {
        int tt = idx >> 4, d4 = (idx & 15) * 4;
        float4 v = *(const float4*)(g_qkv + (size_t)(b*SS + c*CHK + tt)*QKVW + OFF_V + h*HD + d4);
        float e4[4] = {v.x, v.y, v.z, v.w};
#pragma unroll
        for (int q2 = 0; q2 < 4; q2++) {
            __nv_bfloat16 hh = __float2bfloat16(e4[q2]);
            VtH[(d4+q2)*136 + tt] = hh;
            VtL[(d4+q2)*136 + tt] = __float2bfloat16(e4[q2] - __bfloat162float(hh));
        }
    }
    __syncthreads();

    // ---- scores: S = Q @ K^T, 128x128, K=16 (one k-tile) ----
    {
        const int wm = (w & 1) * 64, wn = (w >> 1) * 32;
        uint32_t bqh = su32(qh), bql = su32(ql), bkh = su32(kh), bkl = su32(kl);
        uint32_t fah[4][4], fal[4][4], fbh[4][2], fbl[4][2];
#pragma unroll
        for (int mt = 0; mt < 4; mt++) {
            uint32_t off = (wm + mt*16 + (l & 15)) * 48 + (l >> 4) * 16;
            LDSM4(fah[mt][0], fah[mt][1], fah[mt][2], fah[mt][3], bqh + off);
            LDSM4(fal[mt][0], fal[mt][1], fal[mt][2], fal[mt][3], bql + off);
        }
#pragma unroll
        for (int np = 0; np < 2; np++) {
            uint32_t off = (wn + np*16 + (l & 7) + ((l >> 4) & 1) * 8) * 48
                         + ((l >> 3) & 1) * 16;
            LDSM4(fbh[np*2][0], fbh[np*2][1], fbh[np*2+1][0], fbh[np*2+1][1], bkh + off);
            LDSM4(fbl[np*2][0], fbl[np*2][1], fbl[np*2+1][0], fbl[np*2+1][1], bkl + off);
        }
#pragma unroll
        for (int mt = 0; mt < 4; mt++) {
            float sum0 = 0.f, sum1 = 0.f;
#pragma unroll
            for (int nt = 0; nt < 4; nt++) {
                float sacc[4] = {0.f, 0.f, 0.f, 0.f};
                MMA16816(sacc, fah[mt], fbh[nt]);
                MMA16816(sacc, fah[mt], fbl[nt]);
                MMA16816(sacc, fal[mt], fbh[nt]);
                int r0 = wm + mt*16 + gr, r1 = r0 + 8;
                int c0 = wn + nt*8 + tc*2;
                float a0 = (c0   <= r0) ? fmaf(sacc[0], fmaf(sacc[0], 0.03125f, 0.25f), 1.0f) : 0.f;
                float a1 = (c0+1 <= r0) ? fmaf(sacc[1], fmaf(sacc[1], 0.03125f, 0.25f), 1.0f) : 0.f;
                float a2 = (c0   <= r1) ? fmaf(sacc[2], fmaf(sacc[2], 0.03125f, 0.25f), 1.0f) : 0.f;
                float a3 = (c0+1 <= r1) ? fmaf(sacc[3], fmaf(sacc[3], 0.03125f, 0.25f), 1.0f) : 0.f;
                sum0 += a0 + a1; sum1 += a2 + a3;
                split_store(AsH + r0*136 + c0, AsL + r0*136 + c0, a0, a1);
                split_store(AsH + r1*136 + c0, AsL + r1*136 + c0, a2, a3);
            }
            sum0 += __shfl_xor_sync(0xffffffffu, sum0, 1);
            sum0 += __shfl_xor_sync(0xffffffffu, sum0, 2);
            sum1 += __shfl_xor_sync(0xffffffffu, sum1, 1);
            sum1 += __shfl_xor_sync(0xffffffffu, sum1, 2);
            if (tc == 0) {
                rs4[(w >> 1)*128 + wm + mt*16 + gr]     = sum0;
                rs4[(w >> 1)*128 + wm + mt*16 + gr + 8] = sum1;
            }
        }
    }
    __syncthreads();

    // ---- AV: out[128][64] = A @ V^T, K=128 tokens ----
    {
        const int wm = (w & 1) * 64, wn = (w >> 1) * 16;
        float acc[4][2][4] = {};
        uint32_t bAH = su32(AsH), bAL = su32(AsL), bVH = su32(VtH), bVL = su32(VtL);
#pragma unroll
        for (int kt = 0; kt < 8; kt++) {
            uint32_t fbh[2][2], fbl[2][2];
            {
                uint32_t off = (wn + (l & 7) + ((l >> 4) & 1) * 8) * 272
                             + kt*32 + ((l >> 3) & 1) * 16;
                LDSM4(fbh[0][0], fbh[0][1], fbh[1][0], fbh[1][1], bVH + off);
                LDSM4(fbl[0][0], fbl[0][1], fbl[1][0], fbl[1][1], bVL + off);
            }
#pragma unroll
            for (int mt = 0; mt < 4; mt++) {
                uint32_t off = (wm + mt*16 + (l & 15)) * 272 + kt*32 + (l >> 4) * 16;
                uint32_t fah[4], fal[4];
                LDSM4(fah[0], fah[1], fah[2], fah[3], bAH + off);
                LDSM4(fal[0], fal[1], fal[2], fal[3], bAL + off);
#pragma unroll
                for (int nt = 0; nt < 2; nt++) {
                    MMA16816(acc[mt][nt], fah, fbh[nt]);
                    MMA16816(acc[mt][nt], fah, fbl[nt]);
                    MMA16816(acc[mt][nt], fal, fbh[nt]);
                }
            }
        }
        // epilogue
#pragma unroll
        for (int mt = 0; mt < 4; mt++) {
#pragma unroll
            for (int half = 0; half < 2; half++) {
                int m = wm + mt*16 + gr + half*8;
                float rsum = rs4[m] + rs4[128 + m] + rs4[256 + m] + rs4[384 + m];
                float den = rsum + g_den[(size_t)(b*HH + h)*SS + c*CHK + m] + 1e-6f;
                float inv = 1.0f / den;
#pragma unroll
                for (int nt = 0; nt < 2; nt++) {
                    int n = wn + nt*8 + tc*2;
                    const size_t obase = (size_t)(b*SS + c*CHK + m)*VDIM + h*HD + n;
                    float2 cur = *(const float2*)(g_att + obase);
                    float r0 = (cur.x + acc[mt][nt][half*2])   * inv;
                    float r1 = (cur.y + acc[mt][nt][half*2+1]) * inv;
                    split_store(g_xhi + obase, g_xlo + obase, r0, r1);
                }
            }
        }
    }
}

extern "C" void kernel_launch(void* const* d_in, const int* in_sizes, int n_in,
                              void* d_out, int out_size)
{
    (void)in_sizes; (void)n_in;
    const float* x    = (const float*)d_in[0];
    const float* kv0  = (const float*)d_in[1];
    const float* kst0 = (const float*)d_in[2];
    const float* Wq   = (const float*)d_in[3];
    const float* bq   = (const float*)d_in[4];
    const float* Wk   = (const float*)d_in[5];
    const float* bk   = (const float*)d_in[6];
    const float* Wv   = (const float*)d_in[7];
    const float* bv   = (const float*)d_in[8];
    const float* Wo   = (const float*)d_in[9];
    const float* bo   = (const float*)d_in[10];

    float* y = (float*)d_out;
    float* kvf = nullptr;
    float* kstf = nullptr;
    if (out_size >= Y_ELEMS + KV_ELEMS + KST_ELEMS) {
        kvf  = y + Y_ELEMS;
        kstf = kvf + KV_ELEMS;
    }

    float *pqkv, *pbqkv;
    __nv_bfloat16 *xhi, *xlo, *wqh, *wql, *woh, *wol;
    cudaGetSymbolAddress((void**)&pqkv,  g_qkv);
    cudaGetSymbolAddress((void**)&pbqkv, g_bqkv);
    cudaGetSymbolAddress((void**)&xhi, g_xhi);
    cudaGetSymbolAddress((void**)&xlo, g_xlo);
    cudaGetSymbolAddress((void**)&wqh, g_wqh);
    cudaGetSymbolAddress((void**)&wql, g_wql);
    cudaGetSymbolAddress((void**)&woh, g_woh);
    cudaGetSymbolAddress((void**)&wol, g_wol);

    cudaFuncSetAttribute(gemm_bf16, cudaFuncAttributeMaxDynamicSharedMemorySize, GS_SMEM);
    cudaFuncSetAttribute(pass1_kernel, cudaFuncAttributeMaxDynamicSharedMemorySize, P1_SMEM);
    cudaFuncSetAttribute(pass2a_kernel, cudaFuncAttributeMaxDynamicSharedMemorySize, P2A_SMEM);
    cudaFuncSetAttribute(pass2b_kernel, cudaFuncAttributeMaxDynamicSharedMemorySize, P2B_SMEM);

    const int M = BB * SS;  // 8192

    cvt_split<<<(M * DM) / 1024, 256>>>(x, xhi, xlo, M * DM);
    cvt_wT_all<<<dim3(32, 32, 4), 256>>>(Wq, Wk, Wv, Wo, wqh, wql, woh, wol);
    bias_concat<<<1, 256>>>(bq, bk, bv, pbqkv);
    gemm_bf16<<<dim3(QKVW/64, M/128), 256, GS_SMEM>>>(xhi, xlo, wqh, wql, pbqkv, pqkv, QKVW, DM);

    pass1_kernel<<<dim3(NC, HH, BB), 512, P1_SMEM>>>();
    prefix_kernel<<<dim3(HH, BB, 8), 256>>>(kv0, kst0, kvf, kstf);
    pass2a_kernel<<<dim3(NC, HH, BB), 256, P2A_SMEM>>>();
    pass2b_kernel<<<dim3(NC, HH, BB), 256, P2B_SMEM>>>();

    gemm_bf16<<<dim3(DM/64, M/128), 256, GS_SMEM>>>(xhi, xlo, woh, wol, bo, y, DM, VDIM);
}